// round 3
// baseline (speedup 1.0000x reference)
#include <cuda_runtime.h>
#include <cstdint>

// Problem constants
#define BB 4
#define SS 2048
#define DD 1024
#define HH 16
#define DKK 64
#define MM (BB*SS)            // 8192
#define OUT_PLANE (BB*SS*DD)  // 8388608

// Scratch (allocation-free rule: __device__ globals)
__device__ float g_Qh[BB*HH*SS*DKK];   // Q projected, head layout
__device__ float g_ctx[BB*SS*DD];      // attention context, [B,S,D]

// ---------------------------------------------------------------------------
// helpers
// ---------------------------------------------------------------------------
__device__ __forceinline__ float to_tf32(float x) {
    uint32_t u;
    asm("cvt.rna.tf32.f32 %0, %1;" : "=r"(u) : "f"(x));
    return __uint_as_float(u);
}

// D += A(16x8) * B(8x8), tf32 inputs, fp32 accum
__device__ __forceinline__ void mma8(float* c, float a0, float a1, float a2, float a3,
                                     float b0, float b1) {
    asm volatile(
        "mma.sync.aligned.m16n8k8.row.col.f32.tf32.tf32.f32 "
        "{%0,%1,%2,%3}, {%4,%5,%6,%7}, {%8,%9}, {%0,%1,%2,%3};\n"
        : "+f"(c[0]), "+f"(c[1]), "+f"(c[2]), "+f"(c[3])
        : "r"(__float_as_uint(a0)), "r"(__float_as_uint(a1)),
          "r"(__float_as_uint(a2)), "r"(__float_as_uint(a3)),
          "r"(__float_as_uint(b0)), "r"(__float_as_uint(b1)));
}

// ---------------------------------------------------------------------------
// TF32 GEMM v2: C[m,e] = sum_d A[m,d] * W[e,d]
// Block tile 128x128, BK=16, 128 threads = 4 warps (2M x 2N), warp = 64x64.
// Double-buffered smem, register prefetch. smem layout [k][m], stride 136:
//   frag reads: bank = (tig*8 + g + const) % 32  -> conflict-free
//   STS: warp w owns k-cols w*4..w*4+3, lanes = rows -> conflict-free
// ---------------------------------------------------------------------------
#define GS 136
__global__ __launch_bounds__(128) void gemm_tc(const float* __restrict__ A,
                                               const float* __restrict__ W,
                                               float* __restrict__ out,
                                               int head_layout)
{
    __shared__ float As[2][16][GS];
    __shared__ float Bs[2][16][GS];

    const int tid  = threadIdx.x;
    const int lane = tid & 31;
    const int w    = tid >> 5;
    const int g    = lane >> 2;
    const int tig  = lane & 3;
    const int wm   = w & 1;
    const int wn   = w >> 1;

    const int m0 = blockIdx.y << 7;
    const int n0 = blockIdx.x << 7;

    // loader: warp w covers k-offset w*4..w*4+3 for all 128 rows (4 rounds of 32)
    const float* Ap = A + (size_t)(m0 + lane) * DD + (w << 2);
    const float* Wp = W + (size_t)(n0 + lane) * DD + (w << 2);

    float acc[4][8][4];
#pragma unroll
    for (int mf = 0; mf < 4; mf++)
#pragma unroll
        for (int nf = 0; nf < 8; nf++)
#pragma unroll
            for (int r = 0; r < 4; r++) acc[mf][nf][r] = 0.0f;

    float4 ra[4], rb[4];
#pragma unroll
    for (int r = 0; r < 4; r++) {
        ra[r] = *(const float4*)(Ap + (size_t)(r * 32) * DD);
        rb[r] = *(const float4*)(Wp + (size_t)(r * 32) * DD);
    }
    // STS tile 0 -> buf 0
#pragma unroll
    for (int r = 0; r < 4; r++) {
        int row = r * 32 + lane;
        As[0][(w << 2) + 0][row] = to_tf32(ra[r].x);
        As[0][(w << 2) + 1][row] = to_tf32(ra[r].y);
        As[0][(w << 2) + 2][row] = to_tf32(ra[r].z);
        As[0][(w << 2) + 3][row] = to_tf32(ra[r].w);
        Bs[0][(w << 2) + 0][row] = to_tf32(rb[r].x);
        Bs[0][(w << 2) + 1][row] = to_tf32(rb[r].y);
        Bs[0][(w << 2) + 2][row] = to_tf32(rb[r].z);
        Bs[0][(w << 2) + 3][row] = to_tf32(rb[r].w);
    }
    __syncthreads();

    int buf = 0;
    for (int t = 0; t < 64; t++) {
        if (t < 63) {
            const float* Ap2 = Ap + (t + 1) * 16;
            const float* Wp2 = Wp + (t + 1) * 16;
#pragma unroll
            for (int r = 0; r < 4; r++) {
                ra[r] = *(const float4*)(Ap2 + (size_t)(r * 32) * DD);
                rb[r] = *(const float4*)(Wp2 + (size_t)(r * 32) * DD);
            }
        }
        // compute on buf
#pragma unroll
        for (int ks = 0; ks < 2; ks++) {
            float a[4][4];
#pragma unroll
            for (int mf = 0; mf < 4; mf++) {
                int m = (wm << 6) + (mf << 4);
                a[mf][0] = As[buf][ks * 8 + tig    ][m + g];
                a[mf][1] = As[buf][ks * 8 + tig    ][m + g + 8];
                a[mf][2] = As[buf][ks * 8 + tig + 4][m + g];
                a[mf][3] = As[buf][ks * 8 + tig + 4][m + g + 8];
            }
#pragma unroll
            for (int nf = 0; nf < 8; nf++) {
                int n = (wn << 6) + (nf << 3) + g;
                float b0 = Bs[buf][ks * 8 + tig    ][n];
                float b1 = Bs[buf][ks * 8 + tig + 4][n];
#pragma unroll
                for (int mf = 0; mf < 4; mf++)
                    mma8(acc[mf][nf], a[mf][0], a[mf][1], a[mf][2], a[mf][3], b0, b1);
            }
        }
        if (t < 63) {
            int nb = buf ^ 1;
#pragma unroll
            for (int r = 0; r < 4; r++) {
                int row = r * 32 + lane;
                As[nb][(w << 2) + 0][row] = to_tf32(ra[r].x);
                As[nb][(w << 2) + 1][row] = to_tf32(ra[r].y);
                As[nb][(w << 2) + 2][row] = to_tf32(ra[r].z);
                As[nb][(w << 2) + 3][row] = to_tf32(ra[r].w);
                Bs[nb][(w << 2) + 0][row] = to_tf32(rb[r].x);
                Bs[nb][(w << 2) + 1][row] = to_tf32(rb[r].y);
                Bs[nb][(w << 2) + 2][row] = to_tf32(rb[r].z);
                Bs[nb][(w << 2) + 3][row] = to_tf32(rb[r].w);
            }
            __syncthreads();
            buf = nb;
        }
    }

    // epilogue
#pragma unroll
    for (int mf = 0; mf < 4; mf++) {
#pragma unroll
        for (int half = 0; half < 2; half++) {
            int m = m0 + (wm << 6) + (mf << 4) + g + half * 8;
            int bq = m >> 11;
            int s  = m & 2047;
#pragma unroll
            for (int nf = 0; nf < 8; nf++) {
                int e = n0 + (wn << 6) + (nf << 3) + (tig << 1);
                float2 val;
                val.x = acc[mf][nf][half * 2 + 0];
                val.y = acc[mf][nf][half * 2 + 1];
                if (head_layout) {
                    int h = e >> 6, dk = e & 63;
                    *(float2*)&out[((((size_t)bq * HH + h) << 11) + s) * DKK + dk] = val;
                } else {
                    *(float2*)&out[(size_t)m * DD + e] = val;
                }
            }
        }
    }
}

// ---------------------------------------------------------------------------
// TF32 causal flash attention v2. Grid: (S/128, B*H). Block: 128 thr (4 warps).
// Q,K,V in [B,H,S,DK] fp32. Writes ctx in [B,S,D].
// Block = 128 queries; warp = 32 queries x 64 keys. K tile aliased as P tile.
// Dynamic smem: Qs[128][68] + KP[128][68] + Vs[64][72] = 88064 B.
// ---------------------------------------------------------------------------
#define QST 68
#define VST 72
#define ATT_SMEM ((128*QST + 128*QST + 64*VST) * 4)

__global__ __launch_bounds__(128) void attn_tc(const float* __restrict__ Q,
                                               const float* __restrict__ K,
                                               const float* __restrict__ V,
                                               float* __restrict__ ctx)
{
    extern __shared__ float sm[];
    float* Qs = sm;                    // [128][QST]
    float* KP = sm + 128 * QST;        // [128][QST]  (K rows 0..63, then P rows 0..127)
    float* Vs = sm + 2 * 128 * QST;    // [64][VST]

    const int tid  = threadIdx.x;
    const int lane = tid & 31;
    const int w    = tid >> 5;
    const int g    = lane >> 2;
    const int tig  = lane & 3;
    const int wrow = w << 5;           // warp query-row base (0,32,64,96)
    const int bxr  = gridDim.x - 1 - blockIdx.x;   // heavy blocks first
    const int bh   = blockIdx.y;

    const size_t base = (size_t)bh * SS * DKK;
    const float* Qb = Q + base + (size_t)bxr * 128 * DKK;

    // stage Q (pre-scaled by 1/sqrt(64), tf32)
#pragma unroll
    for (int u = 0; u < 16; u++) {
        int idx = u * 128 + tid;
        int r = idx >> 4, c4 = idx & 15;
        float4 t = *(const float4*)(Qb + r * DKK + c4 * 4);
        float4 s;
        s.x = to_tf32(t.x * 0.125f);
        s.y = to_tf32(t.y * 0.125f);
        s.z = to_tf32(t.z * 0.125f);
        s.w = to_tf32(t.w * 0.125f);
        *(float4*)&Qs[r * QST + c4 * 4] = s;
    }

    float accO[2][8][4];
#pragma unroll
    for (int mf = 0; mf < 2; mf++)
#pragma unroll
        for (int nf = 0; nf < 8; nf++)
#pragma unroll
            for (int r = 0; r < 4; r++) accO[mf][nf][r] = 0.0f;
    float m_[2][2] = {{-1e30f, -1e30f}, {-1e30f, -1e30f}};
    float l_[2][2] = {{0.0f, 0.0f}, {0.0f, 0.0f}};

    const int ktmax = 2 * bxr + 1;
    for (int kt = 0; kt <= ktmax; kt++) {
        __syncthreads();   // P/V reads of previous iter done (and Q staged on kt==0)

        const float* Kt = K + base + (size_t)kt * 64 * DKK;
        const float* Vt = V + base + (size_t)kt * 64 * DKK;
#pragma unroll
        for (int u = 0; u < 8; u++) {
            int idx = u * 128 + tid;
            int r = idx >> 4, c4 = idx & 15;
            float4 kv = *(const float4*)(Kt + r * DKK + c4 * 4);
            float4 vv = *(const float4*)(Vt + r * DKK + c4 * 4);
            float4 s;
            s.x = to_tf32(kv.x); s.y = to_tf32(kv.y);
            s.z = to_tf32(kv.z); s.w = to_tf32(kv.w);
            *(float4*)&KP[r * QST + c4 * 4] = s;
            s.x = to_tf32(vv.x); s.y = to_tf32(vv.y);
            s.z = to_tf32(vv.z); s.w = to_tf32(vv.w);
            *(float4*)&Vs[r * VST + c4 * 4] = s;
        }
        __syncthreads();

        // warp fully above the causal frontier? (only possible on last tile)
        const bool skip = (kt * 64) > (bxr * 128 + wrow + 31);

        float sacc[2][8][4];
        if (!skip) {
#pragma unroll
            for (int mf = 0; mf < 2; mf++)
#pragma unroll
                for (int nf = 0; nf < 8; nf++)
#pragma unroll
                    for (int r = 0; r < 4; r++) sacc[mf][nf][r] = 0.0f;

            // GEMM1: S(32x64) = Q @ K^T
#pragma unroll
            for (int ks = 0; ks < 8; ks++) {
                float a[2][4];
#pragma unroll
                for (int mf = 0; mf < 2; mf++) {
                    int row = wrow + (mf << 4);
                    a[mf][0] = Qs[(row + g    ) * QST + ks * 8 + tig];
                    a[mf][1] = Qs[(row + g + 8) * QST + ks * 8 + tig];
                    a[mf][2] = Qs[(row + g    ) * QST + ks * 8 + tig + 4];
                    a[mf][3] = Qs[(row + g + 8) * QST + ks * 8 + tig + 4];
                }
#pragma unroll
                for (int nf = 0; nf < 8; nf++) {
                    float b0 = KP[(nf * 8 + g) * QST + ks * 8 + tig];
                    float b1 = KP[(nf * 8 + g) * QST + ks * 8 + tig + 4];
                    mma8(sacc[0][nf], a[0][0], a[0][1], a[0][2], a[0][3], b0, b1);
                    mma8(sacc[1][nf], a[1][0], a[1][1], a[1][2], a[1][3], b0, b1);
                }
            }

            // causal mask (only the last two tiles can intersect the diagonal)
            if (kt * 64 + 63 > bxr * 128 + wrow) {
                int koff = kt * 64;
                int qabs = bxr * 128 + wrow;
#pragma unroll
                for (int mf = 0; mf < 2; mf++) {
                    int r0 = qabs + (mf << 4) + g;
                    int r1 = r0 + 8;
#pragma unroll
                    for (int nf = 0; nf < 8; nf++) {
                        int c0 = koff + nf * 8 + tig * 2, c1 = c0 + 1;
                        if (c0 > r0) sacc[mf][nf][0] = -1e30f;
                        if (c1 > r0) sacc[mf][nf][1] = -1e30f;
                        if (c0 > r1) sacc[mf][nf][2] = -1e30f;
                        if (c1 > r1) sacc[mf][nf][3] = -1e30f;
                    }
                }
            }

            // online softmax per (mf, half)
#pragma unroll
            for (int mf = 0; mf < 2; mf++) {
                float rm0 = -1e30f, rm1 = -1e30f;
#pragma unroll
                for (int nf = 0; nf < 8; nf++) {
                    rm0 = fmaxf(rm0, fmaxf(sacc[mf][nf][0], sacc[mf][nf][1]));
                    rm1 = fmaxf(rm1, fmaxf(sacc[mf][nf][2], sacc[mf][nf][3]));
                }
                rm0 = fmaxf(rm0, __shfl_xor_sync(0xFFFFFFFFu, rm0, 1));
                rm0 = fmaxf(rm0, __shfl_xor_sync(0xFFFFFFFFu, rm0, 2));
                rm1 = fmaxf(rm1, __shfl_xor_sync(0xFFFFFFFFu, rm1, 1));
                rm1 = fmaxf(rm1, __shfl_xor_sync(0xFFFFFFFFu, rm1, 2));
                float mn0 = fmaxf(m_[mf][0], rm0), mn1 = fmaxf(m_[mf][1], rm1);
                float al0 = __expf(m_[mf][0] - mn0), al1 = __expf(m_[mf][1] - mn1);
                float rs0 = 0.0f, rs1 = 0.0f;
#pragma unroll
                for (int nf = 0; nf < 8; nf++) {
                    sacc[mf][nf][0] = __expf(sacc[mf][nf][0] - mn0);
                    sacc[mf][nf][1] = __expf(sacc[mf][nf][1] - mn0);
                    sacc[mf][nf][2] = __expf(sacc[mf][nf][2] - mn1);
                    sacc[mf][nf][3] = __expf(sacc[mf][nf][3] - mn1);
                    rs0 += sacc[mf][nf][0] + sacc[mf][nf][1];
                    rs1 += sacc[mf][nf][2] + sacc[mf][nf][3];
                }
                rs0 += __shfl_xor_sync(0xFFFFFFFFu, rs0, 1);
                rs0 += __shfl_xor_sync(0xFFFFFFFFu, rs0, 2);
                rs1 += __shfl_xor_sync(0xFFFFFFFFu, rs1, 1);
                rs1 += __shfl_xor_sync(0xFFFFFFFFu, rs1, 2);
                l_[mf][0] = l_[mf][0] * al0 + rs0;
                l_[mf][1] = l_[mf][1] * al1 + rs1;
                m_[mf][0] = mn0; m_[mf][1] = mn1;
#pragma unroll
                for (int nf = 0; nf < 8; nf++) {
                    accO[mf][nf][0] *= al0; accO[mf][nf][1] *= al0;
                    accO[mf][nf][2] *= al1; accO[mf][nf][3] *= al1;
                }
            }
        }

        __syncthreads();   // all warps done reading KP as K

        if (!skip) {
            // write P into KP [qrow][key] (warp-private rows)
#pragma unroll
            for (int mf = 0; mf < 2; mf++) {
                int row = wrow + (mf << 4);
#pragma unroll
                for (int nf = 0; nf < 8; nf++) {
                    int c = nf * 8 + tig * 2;
                    KP[(row + g    ) * QST + c    ] = to_tf32(sacc[mf][nf][0]);
                    KP[(row + g    ) * QST + c + 1] = to_tf32(sacc[mf][nf][1]);
                    KP[(row + g + 8) * QST + c    ] = to_tf32(sacc[mf][nf][2]);
                    KP[(row + g + 8) * QST + c + 1] = to_tf32(sacc[mf][nf][3]);
                }
            }
            __syncwarp();

            // GEMM2: O(32x64) += P(32x64) @ V(64x64)
#pragma unroll
            for (int ks = 0; ks < 8; ks++) {
                float a[2][4];
#pragma unroll
                for (int mf = 0; mf < 2; mf++) {
                    int row = wrow + (mf << 4);
                    a[mf][0] = KP[(row + g    ) * QST + ks * 8 + tig];
                    a[mf][1] = KP[(row + g + 8) * QST + ks * 8 + tig];
                    a[mf][2] = KP[(row + g    ) * QST + ks * 8 + tig + 4];
                    a[mf][3] = KP[(row + g + 8) * QST + ks * 8 + tig + 4];
                }
#pragma unroll
                for (int nf = 0; nf < 8; nf++) {
                    float b0 = Vs[(ks * 8 + tig    ) * VST + nf * 8 + g];
                    float b1 = Vs[(ks * 8 + tig + 4) * VST + nf * 8 + g];
                    mma8(accO[0][nf], a[0][0], a[0][1], a[0][2], a[0][3], b0, b1);
                    mma8(accO[1][nf], a[1][0], a[1][1], a[1][2], a[1][3], b0, b1);
                }
            }
        }
    }

    // epilogue: normalize, write ctx [B,S,D] with head concat
    const int b = bh >> 4;
    const int h = bh & 15;
#pragma unroll
    for (int mf = 0; mf < 2; mf++) {
        float inv0 = 1.0f / l_[mf][0];
        float inv1 = 1.0f / l_[mf][1];
        int s0 = bxr * 128 + wrow + (mf << 4) + g;
        int s1 = s0 + 8;
#pragma unroll
        for (int nf = 0; nf < 8; nf++) {
            int e = (h << 6) + (nf << 3) + (tig << 1);
            float2 v0, v1;
            v0.x = accO[mf][nf][0] * inv0; v0.y = accO[mf][nf][1] * inv0;
            v1.x = accO[mf][nf][2] * inv1; v1.y = accO[mf][nf][3] * inv1;
            *(float2*)&ctx[((size_t)b * SS + s0) * DD + e] = v0;
            *(float2*)&ctx[((size_t)b * SS + s1) * DD + e] = v1;
        }
    }
}

// ---------------------------------------------------------------------------
extern "C" void kernel_launch(void* const* d_in, const int* in_sizes, int n_in,
                              void* d_out, int out_size)
{
    const float* q   = (const float*)d_in[0];
    const float* k   = (const float*)d_in[1];
    const float* v   = (const float*)d_in[2];
    // d_in[3] = mask (causal tril) — computed analytically in-kernel
    const float* w_q = (const float*)d_in[4];
    const float* w_k = (const float*)d_in[5];
    const float* w_v = (const float*)d_in[6];
    const float* w_o = (const float*)d_in[7];

    float* out  = (float*)d_out;
    float* keyh = out + OUT_PLANE;
    float* valh = out + 2 * (size_t)OUT_PLANE;

    float* qh = nullptr;
    float* ctx = nullptr;
    cudaGetSymbolAddress((void**)&qh, g_Qh);
    cudaGetSymbolAddress((void**)&ctx, g_ctx);

    static bool configured = false;
    if (!configured) {
        cudaFuncSetAttribute(attn_tc, cudaFuncAttributeMaxDynamicSharedMemorySize,
                             ATT_SMEM);
        configured = true;
    }

    dim3 ggrid(DD / 128, MM / 128);   // (8, 64)
    gemm_tc<<<ggrid, 128>>>(q, w_q, qh, 1);
    gemm_tc<<<ggrid, 128>>>(k, w_k, keyh, 1);
    gemm_tc<<<ggrid, 128>>>(v, w_v, valh, 1);

    dim3 agrid(SS / 128, BB * HH);    // (16, 64)
    attn_tc<<<agrid, 128, ATT_SMEM>>>(qh, keyh, valh, ctx);

    gemm_tc<<<ggrid, 128>>>(ctx, w_o, out, 0);
}

// round 5
// speedup vs baseline: 1.4665x; 1.4665x over previous
#include <cuda_runtime.h>
#include <cstdint>

// Problem constants
#define BB 4
#define SS 2048
#define DD 1024
#define HH 16
#define DKK 64
#define MM (BB*SS)            // 8192
#define OUT_PLANE (BB*SS*DD)  // 8388608

// Scratch (allocation-free rule: __device__ globals)
__device__ float g_Qh[BB*HH*SS*DKK];   // Q projected, head layout
__device__ float g_ctx[BB*SS*DD];      // attention context, [B,S,D]

// ---------------------------------------------------------------------------
// helpers
// ---------------------------------------------------------------------------
__device__ __forceinline__ float to_tf32(float x) {
    uint32_t u;
    asm("cvt.rna.tf32.f32 %0, %1;" : "=r"(u) : "f"(x));
    return __uint_as_float(u);
}

// D += A(16x8) * B(8x8), tf32 inputs, fp32 accum
__device__ __forceinline__ void mma8(float* c, float a0, float a1, float a2, float a3,
                                     float b0, float b1) {
    asm volatile(
        "mma.sync.aligned.m16n8k8.row.col.f32.tf32.tf32.f32 "
        "{%0,%1,%2,%3}, {%4,%5,%6,%7}, {%8,%9}, {%0,%1,%2,%3};\n"
        : "+f"(c[0]), "+f"(c[1]), "+f"(c[2]), "+f"(c[3])
        : "r"(__float_as_uint(a0)), "r"(__float_as_uint(a1)),
          "r"(__float_as_uint(a2)), "r"(__float_as_uint(a3)),
          "r"(__float_as_uint(b0)), "r"(__float_as_uint(b1)));
}

__device__ __forceinline__ uint32_t smem_u32(const void* p) {
    uint32_t a;
    asm("{ .reg .u64 t; cvta.to.shared.u64 t, %1; cvt.u32.u64 %0, t; }"
        : "=r"(a) : "l"(p));
    return a;
}

__device__ __forceinline__ void cp16(uint32_t saddr, const void* gptr) {
    asm volatile("cp.async.cg.shared.global [%0], [%1], 16;"
                 :: "r"(saddr), "l"(gptr));
}
#define CP_COMMIT() asm volatile("cp.async.commit_group;" ::: "memory")
#define CP_WAIT(n)  asm volatile("cp.async.wait_group %0;" :: "n"(n) : "memory")

// ---------------------------------------------------------------------------
// TF32 GEMM, cp.async 3-stage pipeline: C[m,e] = sum_d A[m,d] * W[e,d]
// Block tile 128x128, BK=16, 256 threads = 8 warps (4M x 2N), warp = 32x64.
// smem: 3 stages x (As[128][20] + Bs[128][20]) fp32 raw = 61440 B dynamic.
// tf32 rounding happens at fragment load (numerically == R2).
// ---------------------------------------------------------------------------
#define GST 20
#define STAGE_F (128 * GST)             // floats per stage per matrix
#define GEMM_SMEM (3 * STAGE_F * 2 * 4) // 61440 B

template<int HEAD>
__device__ __forceinline__ void gemm_body(const float* __restrict__ A,
                                          const float* __restrict__ W,
                                          float* __restrict__ out)
{
    extern __shared__ float dsm[];
    float* AsB = dsm;                   // [3][STAGE_F]
    float* BsB = dsm + 3 * STAGE_F;

    const int tid  = threadIdx.x;
    const int lane = tid & 31;
    const int w    = tid >> 5;
    const int g    = lane >> 2;
    const int tig  = lane & 3;
    const int wm   = w & 3;
    const int wn   = w >> 2;

    const int m0 = blockIdx.y << 7;
    const int n0 = blockIdx.x << 7;

    const int lr  = tid >> 2;           // 0..63
    const int lc4 = tid & 3;            // 0..3

    const uint32_t sA = smem_u32(AsB);
    const uint32_t sB = smem_u32(BsB);

    const float* Agl = A + (size_t)(m0 + lr) * DD + lc4 * 4;
    const float* Agh = A + (size_t)(m0 + lr + 64) * DD + lc4 * 4;
    const float* Wgl = W + (size_t)(n0 + lr) * DD + lc4 * 4;
    const float* Wgh = W + (size_t)(n0 + lr + 64) * DD + lc4 * 4;
    const uint32_t soff = (uint32_t)(lr * GST + lc4 * 4) * 4;
    const uint32_t shh  = (uint32_t)(64 * GST) * 4;

    // prologue: stages for chunks 0 and 1
#pragma unroll
    for (int c = 0; c < 2; c++) {
        uint32_t sb = (uint32_t)(c * STAGE_F) * 4;
        cp16(sA + sb + soff,       Agl + c * 16);
        cp16(sA + sb + soff + shh, Agh + c * 16);
        cp16(sB + sb + soff,       Wgl + c * 16);
        cp16(sB + sb + soff + shh, Wgh + c * 16);
        CP_COMMIT();
    }

    float acc[2][8][4];
#pragma unroll
    for (int mf = 0; mf < 2; mf++)
#pragma unroll
        for (int nf = 0; nf < 8; nf++)
#pragma unroll
            for (int r = 0; r < 4; r++) acc[mf][nf][r] = 0.0f;

    int s_cur = 0;   // slot of chunk t
    int s_nxt = 2;   // slot of chunk t+2
    for (int t = 0; t < 64; t++) {
        if (t < 63) { CP_WAIT(1); } else { CP_WAIT(0); }
        __syncthreads();
        if (t < 62) {
            uint32_t sb = (uint32_t)(s_nxt * STAGE_F) * 4;
            const float* a0p = Agl + (t + 2) * 16;
            const float* a1p = Agh + (t + 2) * 16;
            const float* b0p = Wgl + (t + 2) * 16;
            const float* b1p = Wgh + (t + 2) * 16;
            cp16(sA + sb + soff,       a0p);
            cp16(sA + sb + soff + shh, a1p);
            cp16(sB + sb + soff,       b0p);
            cp16(sB + sb + soff + shh, b1p);
            CP_COMMIT();
        }
        const float* as = AsB + s_cur * STAGE_F;
        const float* bs = BsB + s_cur * STAGE_F;
#pragma unroll
        for (int ks = 0; ks < 2; ks++) {
            float a[2][4];
#pragma unroll
            for (int mf = 0; mf < 2; mf++) {
                int rr = (wm << 5) + (mf << 4);
                a[mf][0] = to_tf32(as[(rr + g    ) * GST + ks * 8 + tig]);
                a[mf][1] = to_tf32(as[(rr + g + 8) * GST + ks * 8 + tig]);
                a[mf][2] = to_tf32(as[(rr + g    ) * GST + ks * 8 + tig + 4]);
                a[mf][3] = to_tf32(as[(rr + g + 8) * GST + ks * 8 + tig + 4]);
            }
#pragma unroll
            for (int nf = 0; nf < 8; nf++) {
                int nr = (wn << 6) + (nf << 3) + g;
                float b0 = to_tf32(bs[nr * GST + ks * 8 + tig]);
                float b1 = to_tf32(bs[nr * GST + ks * 8 + tig + 4]);
                mma8(acc[0][nf], a[0][0], a[0][1], a[0][2], a[0][3], b0, b1);
                mma8(acc[1][nf], a[1][0], a[1][1], a[1][2], a[1][3], b0, b1);
            }
        }
        s_cur = (s_cur == 2) ? 0 : s_cur + 1;
        s_nxt = (s_nxt == 2) ? 0 : s_nxt + 1;
    }

    // epilogue
#pragma unroll
    for (int mf = 0; mf < 2; mf++) {
#pragma unroll
        for (int half = 0; half < 2; half++) {
            int m = m0 + (wm << 5) + (mf << 4) + g + half * 8;
            int bq = m >> 11;
            int s  = m & 2047;
#pragma unroll
            for (int nf = 0; nf < 8; nf++) {
                int e = n0 + (wn << 6) + (nf << 3) + (tig << 1);
                float2 val;
                val.x = acc[mf][nf][half * 2 + 0];
                val.y = acc[mf][nf][half * 2 + 1];
                if (HEAD) {
                    int h = e >> 6, dk = e & 63;
                    *(float2*)&out[((((size_t)bq * HH + h) << 11) + s) * DKK + dk] = val;
                } else {
                    *(float2*)&out[(size_t)m * DD + e] = val;
                }
            }
        }
    }
}

__global__ __launch_bounds__(256, 2) void gemm_qkv(
    const float* __restrict__ q, const float* __restrict__ k,
    const float* __restrict__ v,
    const float* __restrict__ wq, const float* __restrict__ wk,
    const float* __restrict__ wv,
    float* __restrict__ oq, float* __restrict__ ok, float* __restrict__ ov)
{
    const float* A; const float* W; float* O;
    if (blockIdx.z == 0)      { A = q; W = wq; O = oq; }
    else if (blockIdx.z == 1) { A = k; W = wk; O = ok; }
    else                      { A = v; W = wv; O = ov; }
    gemm_body<1>(A, W, O);
}

__global__ __launch_bounds__(256, 2) void gemm_out_k(
    const float* __restrict__ A, const float* __restrict__ W,
    float* __restrict__ O)
{
    gemm_body<0>(A, W, O);
}

// ---------------------------------------------------------------------------
// TF32 causal flash attention. Grid: (S/128, B*H). Block: 256 thr (8 warps).
// Warp w owns 16 query rows; block = 128 queries, K/V staged once per 128 q.
// smem: Qs[128][68] + KP[128][68] (K rows 0-63 aliased under P) + Vs[64][72]
//       = 88064 B dynamic; __launch_bounds__(256,2) -> 2 blocks/SM.
// ---------------------------------------------------------------------------
#define QSTC 68
#define VSTC 72
#define ATT_SMEM ((128*QSTC + 128*QSTC + 64*VSTC) * 4)   // 88064

__global__ __launch_bounds__(256, 2) void attn_tc(const float* __restrict__ Q,
                                                  const float* __restrict__ K,
                                                  const float* __restrict__ V,
                                                  float* __restrict__ ctx)
{
    extern __shared__ float sm[];
    float* Qs = sm;                     // [128][QSTC]
    float* KP = sm + 128 * QSTC;        // [128][QSTC]
    float* Vs = sm + 2 * 128 * QSTC;    // [64][VSTC]

    const int tid  = threadIdx.x;
    const int lane = tid & 31;
    const int w    = tid >> 5;          // 0..7
    const int g    = lane >> 2;
    const int tig  = lane & 3;
    const int wrow = w << 4;            // 0..112
    const int bxr  = gridDim.x - 1 - blockIdx.x;   // heavy blocks first
    const int bh   = blockIdx.y;

    const size_t base = (size_t)bh * SS * DKK;
    const float* Qb = Q + base + (size_t)bxr * 128 * DKK;
    const int qwarp = bxr * 128 + wrow;           // warp's first absolute q row

    // stage Q (pre-scaled by 1/sqrt(64), tf32)
#pragma unroll
    for (int u = 0; u < 8; u++) {
        int idx = u * 256 + tid;
        int r = idx >> 4, c4 = idx & 15;
        float4 t = *(const float4*)(Qb + r * DKK + c4 * 4);
        float4 s;
        s.x = to_tf32(t.x * 0.125f);
        s.y = to_tf32(t.y * 0.125f);
        s.z = to_tf32(t.z * 0.125f);
        s.w = to_tf32(t.w * 0.125f);
        *(float4*)&Qs[r * QSTC + c4 * 4] = s;
    }
    __syncthreads();

    // Q a-fragments (persist whole block)
    float aQ[8][4];
#pragma unroll
    for (int ks = 0; ks < 8; ks++) {
        aQ[ks][0] = Qs[(wrow + g    ) * QSTC + ks * 8 + tig];
        aQ[ks][1] = Qs[(wrow + g + 8) * QSTC + ks * 8 + tig];
        aQ[ks][2] = Qs[(wrow + g    ) * QSTC + ks * 8 + tig + 4];
        aQ[ks][3] = Qs[(wrow + g + 8) * QSTC + ks * 8 + tig + 4];
    }

    float accO[8][4];
#pragma unroll
    for (int nf = 0; nf < 8; nf++)
#pragma unroll
        for (int r = 0; r < 4; r++) accO[nf][r] = 0.0f;
    float m0_ = -1e30f, m1_ = -1e30f, l0 = 0.0f, l1 = 0.0f;

    const int ktmax = 2 * bxr + 1;
    for (int kt = 0; kt <= ktmax; kt++) {
        __syncthreads();   // prior GEMM2 reads of KP/Vs done
        const float* Kt = K + base + (size_t)kt * 64 * DKK;
        const float* Vt = V + base + (size_t)kt * 64 * DKK;
#pragma unroll
        for (int u = 0; u < 4; u++) {
            int idx = u * 256 + tid;
            int r = idx >> 4, c4 = idx & 15;
            float4 kv = *(const float4*)(Kt + r * DKK + c4 * 4);
            float4 vv = *(const float4*)(Vt + r * DKK + c4 * 4);
            float4 s;
            s.x = to_tf32(kv.x); s.y = to_tf32(kv.y);
            s.z = to_tf32(kv.z); s.w = to_tf32(kv.w);
            *(float4*)&KP[r * QSTC + c4 * 4] = s;
            s.x = to_tf32(vv.x); s.y = to_tf32(vv.y);
            s.z = to_tf32(vv.z); s.w = to_tf32(vv.w);
            *(float4*)&Vs[r * VSTC + c4 * 4] = s;
        }
        __syncthreads();

        // warp fully above causal frontier? (only lower warps on last tile)
        const bool skip = (kt * 64) > (qwarp + 15);

        float sacc[8][4];
        if (!skip) {
#pragma unroll
            for (int nf = 0; nf < 8; nf++)
#pragma unroll
                for (int r = 0; r < 4; r++) sacc[nf][r] = 0.0f;

            // GEMM1: S(16x64) = Q @ K^T
#pragma unroll
            for (int ks = 0; ks < 8; ks++) {
#pragma unroll
                for (int nf = 0; nf < 8; nf++) {
                    float b0 = KP[(nf * 8 + g) * QSTC + ks * 8 + tig];
                    float b1 = KP[(nf * 8 + g) * QSTC + ks * 8 + tig + 4];
                    mma8(sacc[nf], aQ[ks][0], aQ[ks][1], aQ[ks][2], aQ[ks][3], b0, b1);
                }
            }

            // causal mask (absolute indices)
            if (kt * 64 + 63 > qwarp) {
                int r0 = qwarp + g, r1 = r0 + 8;
                int koff = kt * 64;
#pragma unroll
                for (int nf = 0; nf < 8; nf++) {
                    int c0 = koff + nf * 8 + tig * 2, c1 = c0 + 1;
                    if (c0 > r0) sacc[nf][0] = -1e30f;
                    if (c1 > r0) sacc[nf][1] = -1e30f;
                    if (c0 > r1) sacc[nf][2] = -1e30f;
                    if (c1 > r1) sacc[nf][3] = -1e30f;
                }
            }

            // online softmax (rows in quads: reduce over lane^1, lane^2)
            float rm0 = -1e30f, rm1 = -1e30f;
#pragma unroll
            for (int nf = 0; nf < 8; nf++) {
                rm0 = fmaxf(rm0, fmaxf(sacc[nf][0], sacc[nf][1]));
                rm1 = fmaxf(rm1, fmaxf(sacc[nf][2], sacc[nf][3]));
            }
            rm0 = fmaxf(rm0, __shfl_xor_sync(0xFFFFFFFFu, rm0, 1));
            rm0 = fmaxf(rm0, __shfl_xor_sync(0xFFFFFFFFu, rm0, 2));
            rm1 = fmaxf(rm1, __shfl_xor_sync(0xFFFFFFFFu, rm1, 1));
            rm1 = fmaxf(rm1, __shfl_xor_sync(0xFFFFFFFFu, rm1, 2));
            float mn0 = fmaxf(m0_, rm0), mn1 = fmaxf(m1_, rm1);
            float al0 = __expf(m0_ - mn0), al1 = __expf(m1_ - mn1);
            float rs0 = 0.0f, rs1 = 0.0f;
#pragma unroll
            for (int nf = 0; nf < 8; nf++) {
                sacc[nf][0] = __expf(sacc[nf][0] - mn0);
                sacc[nf][1] = __expf(sacc[nf][1] - mn0);
                sacc[nf][2] = __expf(sacc[nf][2] - mn1);
                sacc[nf][3] = __expf(sacc[nf][3] - mn1);
                rs0 += sacc[nf][0] + sacc[nf][1];
                rs1 += sacc[nf][2] + sacc[nf][3];
            }
            rs0 += __shfl_xor_sync(0xFFFFFFFFu, rs0, 1);
            rs0 += __shfl_xor_sync(0xFFFFFFFFu, rs0, 2);
            rs1 += __shfl_xor_sync(0xFFFFFFFFu, rs1, 1);
            rs1 += __shfl_xor_sync(0xFFFFFFFFu, rs1, 2);
            l0 = l0 * al0 + rs0;
            l1 = l1 * al1 + rs1;
            m0_ = mn0; m1_ = mn1;
#pragma unroll
            for (int nf = 0; nf < 8; nf++) {
                accO[nf][0] *= al0; accO[nf][1] *= al0;
                accO[nf][2] *= al1; accO[nf][3] *= al1;
            }
        }

        __syncthreads();   // all warps done reading KP as K

        if (!skip) {
            // write P into KP rows [wrow, wrow+16) (warp-private)
#pragma unroll
            for (int nf = 0; nf < 8; nf++) {
                int c = nf * 8 + tig * 2;
                KP[(wrow + g    ) * QSTC + c    ] = to_tf32(sacc[nf][0]);
                KP[(wrow + g    ) * QSTC + c + 1] = to_tf32(sacc[nf][1]);
                KP[(wrow + g + 8) * QSTC + c    ] = to_tf32(sacc[nf][2]);
                KP[(wrow + g + 8) * QSTC + c + 1] = to_tf32(sacc[nf][3]);
            }
            __syncwarp();

            // GEMM2: O(16x64) += P(16x64) @ V(64x64)
#pragma unroll
            for (int ks = 0; ks < 8; ks++) {
                float a0 = KP[(wrow + g    ) * QSTC + ks * 8 + tig];
                float a1 = KP[(wrow + g + 8) * QSTC + ks * 8 + tig];
                float a2 = KP[(wrow + g    ) * QSTC + ks * 8 + tig + 4];
                float a3 = KP[(wrow + g + 8) * QSTC + ks * 8 + tig + 4];
#pragma unroll
                for (int nf = 0; nf < 8; nf++) {
                    float b0 = Vs[(ks * 8 + tig    ) * VSTC + nf * 8 + g];
                    float b1 = Vs[(ks * 8 + tig + 4) * VSTC + nf * 8 + g];
                    mma8(accO[nf], a0, a1, a2, a3, b0, b1);
                }
            }
        }
    }

    // epilogue: normalize, write ctx [B,S,D] with head concat
    const int b = bh >> 4;
    const int h = bh & 15;
    float inv0 = 1.0f / l0, inv1 = 1.0f / l1;
    int s0 = qwarp + g;
    int s1 = s0 + 8;
#pragma unroll
    for (int nf = 0; nf < 8; nf++) {
        int e = (h << 6) + (nf << 3) + (tig << 1);
        float2 v0, v1;
        v0.x = accO[nf][0] * inv0; v0.y = accO[nf][1] * inv0;
        v1.x = accO[nf][2] * inv1; v1.y = accO[nf][3] * inv1;
        *(float2*)&ctx[((size_t)b * SS + s0) * DD + e] = v0;
        *(float2*)&ctx[((size_t)b * SS + s1) * DD + e] = v1;
    }
}

// ---------------------------------------------------------------------------
extern "C" void kernel_launch(void* const* d_in, const int* in_sizes, int n_in,
                              void* d_out, int out_size)
{
    const float* q   = (const float*)d_in[0];
    const float* k   = (const float*)d_in[1];
    const float* v   = (const float*)d_in[2];
    // d_in[3] = mask (causal tril) — computed analytically in-kernel
    const float* w_q = (const float*)d_in[4];
    const float* w_k = (const float*)d_in[5];
    const float* w_v = (const float*)d_in[6];
    const float* w_o = (const float*)d_in[7];

    float* out  = (float*)d_out;
    float* keyh = out + OUT_PLANE;
    float* valh = out + 2 * (size_t)OUT_PLANE;

    float* qh = nullptr;
    float* ctx = nullptr;
    cudaGetSymbolAddress((void**)&qh, g_Qh);
    cudaGetSymbolAddress((void**)&ctx, g_ctx);

    static bool configured = false;
    if (!configured) {
        cudaFuncSetAttribute(gemm_qkv, cudaFuncAttributeMaxDynamicSharedMemorySize,
                             GEMM_SMEM);
        cudaFuncSetAttribute(gemm_out_k, cudaFuncAttributeMaxDynamicSharedMemorySize,
                             GEMM_SMEM);
        cudaFuncSetAttribute(attn_tc, cudaFuncAttributeMaxDynamicSharedMemorySize,
                             ATT_SMEM);
        configured = true;
    }

    dim3 qkvgrid(DD / 128, MM / 128, 3);   // (8, 64, 3)
    gemm_qkv<<<qkvgrid, 256, GEMM_SMEM>>>(q, k, v, w_q, w_k, w_v, qh, keyh, valh);

    dim3 agrid(SS / 128, BB * HH);         // (16, 64)
    attn_tc<<<agrid, 256, ATT_SMEM>>>(qh, keyh, valh, ctx);

    dim3 ogrid(DD / 128, MM / 128, 1);     // (8, 64)
    gemm_out_k<<<ogrid, 256, GEMM_SMEM>>>(ctx, w_o, out);
}

// round 6
// speedup vs baseline: 1.5201x; 1.0365x over previous
#include <cuda_runtime.h>
#include <cstdint>

// Problem constants
#define BB 4
#define SS 2048
#define DD 1024
#define HH 16
#define DKK 64
#define MM (BB*SS)            // 8192
#define OUT_PLANE (BB*SS*DD)  // 8388608

// Scratch (allocation-free rule: __device__ globals)
__device__ float g_Qh[BB*HH*SS*DKK];   // Q projected, head layout
__device__ float g_ctx[BB*SS*DD];      // attention context, [B,S,D]

// ---------------------------------------------------------------------------
// helpers
// ---------------------------------------------------------------------------
__device__ __forceinline__ float to_tf32(float x) {
    uint32_t u;
    asm("cvt.rna.tf32.f32 %0, %1;" : "=r"(u) : "f"(x));
    return __uint_as_float(u);
}

// D += A(16x8) * B(8x8), tf32 inputs, fp32 accum
__device__ __forceinline__ void mma8(float* c, float a0, float a1, float a2, float a3,
                                     float b0, float b1) {
    asm volatile(
        "mma.sync.aligned.m16n8k8.row.col.f32.tf32.tf32.f32 "
        "{%0,%1,%2,%3}, {%4,%5,%6,%7}, {%8,%9}, {%0,%1,%2,%3};\n"
        : "+f"(c[0]), "+f"(c[1]), "+f"(c[2]), "+f"(c[3])
        : "r"(__float_as_uint(a0)), "r"(__float_as_uint(a1)),
          "r"(__float_as_uint(a2)), "r"(__float_as_uint(a3)),
          "r"(__float_as_uint(b0)), "r"(__float_as_uint(b1)));
}

__device__ __forceinline__ uint32_t smem_u32(const void* p) {
    uint32_t a;
    asm("{ .reg .u64 t; cvta.to.shared.u64 t, %1; cvt.u32.u64 %0, t; }"
        : "=r"(a) : "l"(p));
    return a;
}

__device__ __forceinline__ void cp16(uint32_t saddr, const void* gptr) {
    asm volatile("cp.async.cg.shared.global [%0], [%1], 16;"
                 :: "r"(saddr), "l"(gptr));
}
#define CP_COMMIT() asm volatile("cp.async.commit_group;" ::: "memory")
#define CP_WAIT(n)  asm volatile("cp.async.wait_group %0;" :: "n"(n) : "memory")

// ---------------------------------------------------------------------------
// TF32 GEMM, BK=32, 3-stage cp.async: C[m,e] = sum_d A[m,d] * W[e,d]
// Block tile 128x128, 256 threads = 8 warps (4M x 2N), warp = 32x64.
// smem: 3 stages x (As[128][36] + Bs[128][36]) fp32 = 110592 B dynamic.
// tf32 rounding at fragment load (numerically == prior rounds).
// ---------------------------------------------------------------------------
#define GST 36
#define STAGE_F (128 * GST)             // 4608 floats per stage per matrix
#define GEMM_SMEM (3 * STAGE_F * 2 * 4) // 110592 B

template<int HEAD>
__device__ __forceinline__ void gemm_body(const float* __restrict__ A,
                                          const float* __restrict__ W,
                                          float* __restrict__ out)
{
    extern __shared__ float dsm[];
    float* AsB = dsm;                   // [3][STAGE_F]
    float* BsB = dsm + 3 * STAGE_F;

    const int tid  = threadIdx.x;
    const int lane = tid & 31;
    const int w    = tid >> 5;
    const int g    = lane >> 2;
    const int tig  = lane & 3;
    const int wm   = w & 3;
    const int wn   = w >> 2;

    const int m0 = blockIdx.y << 7;
    const int n0 = blockIdx.x << 7;

    const uint32_t sA = smem_u32(AsB);
    const uint32_t sB = smem_u32(BsB);

    // loader mapping: float4 f = tid + i*256 (i<4): row = f>>3 (0..127), c4 = f&7
    const int lrow = tid >> 3;          // base row, +32 per i
    const int lc4  = tid & 7;           // 0..7

    const float* Ag = A + (size_t)(m0 + lrow) * DD + lc4 * 4;
    const float* Wg = W + (size_t)(n0 + lrow) * DD + lc4 * 4;
    const uint32_t soff = (uint32_t)(lrow * GST + lc4 * 4) * 4;
    const uint32_t srow32 = (uint32_t)(32 * GST) * 4;

    // prologue: chunks 0,1,2 -> stages 0,1,2
#pragma unroll
    for (int c = 0; c < 3; c++) {
        uint32_t sb = (uint32_t)(c * STAGE_F) * 4;
#pragma unroll
        for (int i = 0; i < 4; i++) {
            cp16(sA + sb + soff + i * srow32, Ag + (size_t)(i * 32) * DD + c * 32);
            cp16(sB + sb + soff + i * srow32, Wg + (size_t)(i * 32) * DD + c * 32);
        }
        CP_COMMIT();
    }

    float acc[2][8][4];
#pragma unroll
    for (int mf = 0; mf < 2; mf++)
#pragma unroll
        for (int nf = 0; nf < 8; nf++)
#pragma unroll
            for (int r = 0; r < 4; r++) acc[mf][nf][r] = 0.0f;

    int s_cur = 0;
    int s_nxt = 0;   // stage receiving chunk t+3... actually chunk t+3 goes to stage of t
    for (int t = 0; t < 32; t++) {
        if (t < 31) { CP_WAIT(2); } else { CP_WAIT(0); }
        __syncthreads();
        if (t < 29) {
            // chunk t+3 into the stage being vacated NEXT iteration is wrong;
            // with 3 stages, chunk t+3 reuses stage of chunk t — but stage t is
            // being computed now. So prefetch chunk t+3 AFTER compute? Instead:
            // standard: at iter t, issue chunk t+3 into stage (t+3)%3 == t%3.
            // That stage holds chunk t (in compute). Not allowed.
            // => issue chunk t+2's... chunk t+2 was already issued at iter t-1? No.
            // Correct 3-stage/2-ahead: prologue issued 0,1,2. At iter t we issue
            // nothing until compute done; but cp.async writes only land visible
            // after wait+sync, and we only WAIT 2-deep, so issuing into the
            // current compute stage would race. Issue into stage (t)%3 after
            // compute is the safe point — but that needs a second sync.
            // Resolution: issue chunk t+3 here targeting stage s_cur is a race;
            // instead target is fine because all warps passed the barrier ABOVE
            // this point only guarantees chunk t arrived, not that compute of
            // chunk t finished. So: we issue chunk t+3 at iter t+1's top (after
            // the barrier that follows compute of t). Implemented by issuing
            // chunk t+2 here? chunk t+2 already in flight from prologue shift.
            // => see restructured emission below (guarded by t >= 0): we issue
            // chunk t+3 - 1 = t+2 only for t >= 1. For simplicity we emit
            // chunk t+3 at NEXT iteration top via s_nxt bookkeeping.
        }
        // Emit chunk (t+2)+1 = t+3? Simpler correct scheme: at top of iter t
        // (after barrier), stage of chunk t-1 is fully consumed by ALL warps
        // (they passed this barrier after computing t-1). So issue chunk t+2
        // into stage (t+2)%3 = (t-1)%3. Guard: t >= 1 and t+2 <= 31.
        if (t >= 1 && t + 2 < 32) {
            uint32_t sb = (uint32_t)(((t + 2) % 3) * STAGE_F) * 4;
            const float* a2 = Ag + (t + 2) * 32;
            const float* w2 = Wg + (t + 2) * 32;
#pragma unroll
            for (int i = 0; i < 4; i++) {
                cp16(sA + sb + soff + i * srow32, a2 + (size_t)(i * 32) * DD);
                cp16(sB + sb + soff + i * srow32, w2 + (size_t)(i * 32) * DD);
            }
            CP_COMMIT();
        }
        const float* as = AsB + s_cur * STAGE_F;
        const float* bs = BsB + s_cur * STAGE_F;
#pragma unroll
        for (int ks = 0; ks < 4; ks++) {
            float a[2][4];
#pragma unroll
            for (int mf = 0; mf < 2; mf++) {
                int rr = (wm << 5) + (mf << 4);
                a[mf][0] = to_tf32(as[(rr + g    ) * GST + ks * 8 + tig]);
                a[mf][1] = to_tf32(as[(rr + g + 8) * GST + ks * 8 + tig]);
                a[mf][2] = to_tf32(as[(rr + g    ) * GST + ks * 8 + tig + 4]);
                a[mf][3] = to_tf32(as[(rr + g + 8) * GST + ks * 8 + tig + 4]);
            }
#pragma unroll
            for (int nf = 0; nf < 8; nf++) {
                int nr = (wn << 6) + (nf << 3) + g;
                float b0 = to_tf32(bs[nr * GST + ks * 8 + tig]);
                float b1 = to_tf32(bs[nr * GST + ks * 8 + tig + 4]);
                mma8(acc[0][nf], a[0][0], a[0][1], a[0][2], a[0][3], b0, b1);
                mma8(acc[1][nf], a[1][0], a[1][1], a[1][2], a[1][3], b0, b1);
            }
        }
        s_cur = (s_cur == 2) ? 0 : s_cur + 1;
        (void)s_nxt;
    }

    // epilogue
#pragma unroll
    for (int mf = 0; mf < 2; mf++) {
#pragma unroll
        for (int half = 0; half < 2; half++) {
            int m = m0 + (wm << 5) + (mf << 4) + g + half * 8;
            int bq = m >> 11;
            int s  = m & 2047;
#pragma unroll
            for (int nf = 0; nf < 8; nf++) {
                int e = n0 + (wn << 6) + (nf << 3) + (tig << 1);
                float2 val;
                val.x = acc[mf][nf][half * 2 + 0];
                val.y = acc[mf][nf][half * 2 + 1];
                if (HEAD) {
                    int h = e >> 6, dk = e & 63;
                    *(float2*)&out[((((size_t)bq * HH + h) << 11) + s) * DKK + dk] = val;
                } else {
                    *(float2*)&out[(size_t)m * DD + e] = val;
                }
            }
        }
    }
}

__global__ __launch_bounds__(256, 2) void gemm_qkv(
    const float* __restrict__ q, const float* __restrict__ k,
    const float* __restrict__ v,
    const float* __restrict__ wq, const float* __restrict__ wk,
    const float* __restrict__ wv,
    float* __restrict__ oq, float* __restrict__ ok, float* __restrict__ ov)
{
    const float* A; const float* W; float* O;
    if (blockIdx.z == 0)      { A = q; W = wq; O = oq; }
    else if (blockIdx.z == 1) { A = k; W = wk; O = ok; }
    else                      { A = v; W = wv; O = ov; }
    gemm_body<1>(A, W, O);
}

__global__ __launch_bounds__(256, 2) void gemm_out_k(
    const float* __restrict__ A, const float* __restrict__ W,
    float* __restrict__ O)
{
    gemm_body<0>(A, W, O);
}

// ---------------------------------------------------------------------------
// TF32 causal flash attention. Grid: (S/128, B*H). Block: 256 thr (8 warps).
// Warp w owns 16 query rows; block = 128 queries; K/V staged via cp.async.
// smem: Qs[128][68] + KP[128][68] (K rows 0-63 aliased under P) + Vs[64][72]
//       = 88064 B dynamic; 2 blocks/SM.
// ---------------------------------------------------------------------------
#define QSTC 68
#define VSTC 72
#define ATT_SMEM ((128*QSTC + 128*QSTC + 64*VSTC) * 4)   // 88064

__global__ __launch_bounds__(256, 2) void attn_tc(const float* __restrict__ Q,
                                                  const float* __restrict__ K,
                                                  const float* __restrict__ V,
                                                  float* __restrict__ ctx)
{
    extern __shared__ float sm[];
    float* Qs = sm;                     // [128][QSTC]
    float* KP = sm + 128 * QSTC;        // [128][QSTC]
    float* Vs = sm + 2 * 128 * QSTC;    // [64][VSTC]

    const int tid  = threadIdx.x;
    const int lane = tid & 31;
    const int w    = tid >> 5;          // 0..7
    const int g    = lane >> 2;
    const int tig  = lane & 3;
    const int wrow = w << 4;            // 0..112
    const int bxr  = gridDim.x - 1 - blockIdx.x;   // heavy blocks first
    const int bh   = blockIdx.y;

    const size_t base = (size_t)bh * SS * DKK;
    const float* Qb = Q + base + (size_t)bxr * 128 * DKK;
    const int qwarp = bxr * 128 + wrow;

    const uint32_t uKP = smem_u32(KP);
    const uint32_t uVs = smem_u32(Vs);

    // stage Q (pre-scaled by 1/sqrt(64), tf32)
#pragma unroll
    for (int u = 0; u < 8; u++) {
        int idx = u * 256 + tid;
        int r = idx >> 4, c4 = idx & 15;
        float4 t = *(const float4*)(Qb + r * DKK + c4 * 4);
        float4 s;
        s.x = to_tf32(t.x * 0.125f);
        s.y = to_tf32(t.y * 0.125f);
        s.z = to_tf32(t.z * 0.125f);
        s.w = to_tf32(t.w * 0.125f);
        *(float4*)&Qs[r * QSTC + c4 * 4] = s;
    }
    __syncthreads();

    // Q a-fragments (persist whole block)
    float aQ[8][4];
#pragma unroll
    for (int ks = 0; ks < 8; ks++) {
        aQ[ks][0] = Qs[(wrow + g    ) * QSTC + ks * 8 + tig];
        aQ[ks][1] = Qs[(wrow + g + 8) * QSTC + ks * 8 + tig];
        aQ[ks][2] = Qs[(wrow + g    ) * QSTC + ks * 8 + tig + 4];
        aQ[ks][3] = Qs[(wrow + g + 8) * QSTC + ks * 8 + tig + 4];
    }

    float accO[8][4];
#pragma unroll
    for (int nf = 0; nf < 8; nf++)
#pragma unroll
        for (int r = 0; r < 4; r++) accO[nf][r] = 0.0f;
    float m0_ = -1e30f, m1_ = -1e30f, l0 = 0.0f, l1 = 0.0f;

    const int ktmax = 2 * bxr + 1;
    for (int kt = 0; kt <= ktmax; kt++) {
        __syncthreads();   // prior GEMM2 reads of KP/Vs done
        const float* Kt = K + base + (size_t)kt * 64 * DKK;
        const float* Vt = V + base + (size_t)kt * 64 * DKK;
#pragma unroll
        for (int u = 0; u < 4; u++) {
            int idx = u * 256 + tid;
            int r = idx >> 4, c4 = idx & 15;
            cp16(uKP + (uint32_t)(r * QSTC + c4 * 4) * 4, Kt + r * DKK + c4 * 4);
            cp16(uVs + (uint32_t)(r * VSTC + c4 * 4) * 4, Vt + r * DKK + c4 * 4);
        }
        CP_COMMIT();
        CP_WAIT(0);
        __syncthreads();

        // warp fully above causal frontier? (only lower warps on last tile)
        const bool skip = (kt * 64) > (qwarp + 15);

        float sacc[8][4];
        if (!skip) {
#pragma unroll
            for (int nf = 0; nf < 8; nf++)
#pragma unroll
                for (int r = 0; r < 4; r++) sacc[nf][r] = 0.0f;

            // GEMM1: S(16x64) = Q @ K^T (tf32 rounding at read)
#pragma unroll
            for (int ks = 0; ks < 8; ks++) {
#pragma unroll
                for (int nf = 0; nf < 8; nf++) {
                    float b0 = to_tf32(KP[(nf * 8 + g) * QSTC + ks * 8 + tig]);
                    float b1 = to_tf32(KP[(nf * 8 + g) * QSTC + ks * 8 + tig + 4]);
                    mma8(sacc[nf], aQ[ks][0], aQ[ks][1], aQ[ks][2], aQ[ks][3], b0, b1);
                }
            }

            // causal mask (absolute indices)
            if (kt * 64 + 63 > qwarp) {
                int r0 = qwarp + g, r1 = r0 + 8;
                int koff = kt * 64;
#pragma unroll
                for (int nf = 0; nf < 8; nf++) {
                    int c0 = koff + nf * 8 + tig * 2, c1 = c0 + 1;
                    if (c0 > r0) sacc[nf][0] = -1e30f;
                    if (c1 > r0) sacc[nf][1] = -1e30f;
                    if (c0 > r1) sacc[nf][2] = -1e30f;
                    if (c1 > r1) sacc[nf][3] = -1e30f;
                }
            }

            // online softmax (rows in quads: reduce over lane^1, lane^2)
            float rm0 = -1e30f, rm1 = -1e30f;
#pragma unroll
            for (int nf = 0; nf < 8; nf++) {
                rm0 = fmaxf(rm0, fmaxf(sacc[nf][0], sacc[nf][1]));
                rm1 = fmaxf(rm1, fmaxf(sacc[nf][2], sacc[nf][3]));
            }
            rm0 = fmaxf(rm0, __shfl_xor_sync(0xFFFFFFFFu, rm0, 1));
            rm0 = fmaxf(rm0, __shfl_xor_sync(0xFFFFFFFFu, rm0, 2));
            rm1 = fmaxf(rm1, __shfl_xor_sync(0xFFFFFFFFu, rm1, 1));
            rm1 = fmaxf(rm1, __shfl_xor_sync(0xFFFFFFFFu, rm1, 2));
            float mn0 = fmaxf(m0_, rm0), mn1 = fmaxf(m1_, rm1);
            float al0 = __expf(m0_ - mn0), al1 = __expf(m1_ - mn1);
            float rs0 = 0.0f, rs1 = 0.0f;
#pragma unroll
            for (int nf = 0; nf < 8; nf++) {
                sacc[nf][0] = __expf(sacc[nf][0] - mn0);
                sacc[nf][1] = __expf(sacc[nf][1] - mn0);
                sacc[nf][2] = __expf(sacc[nf][2] - mn1);
                sacc[nf][3] = __expf(sacc[nf][3] - mn1);
                rs0 += sacc[nf][0] + sacc[nf][1];
                rs1 += sacc[nf][2] + sacc[nf][3];
            }
            rs0 += __shfl_xor_sync(0xFFFFFFFFu, rs0, 1);
            rs0 += __shfl_xor_sync(0xFFFFFFFFu, rs0, 2);
            rs1 += __shfl_xor_sync(0xFFFFFFFFu, rs1, 1);
            rs1 += __shfl_xor_sync(0xFFFFFFFFu, rs1, 2);
            l0 = l0 * al0 + rs0;
            l1 = l1 * al1 + rs1;
            m0_ = mn0; m1_ = mn1;
#pragma unroll
            for (int nf = 0; nf < 8; nf++) {
                accO[nf][0] *= al0; accO[nf][1] *= al0;
                accO[nf][2] *= al1; accO[nf][3] *= al1;
            }
        }

        __syncthreads();   // all warps done reading KP as K

        if (!skip) {
            // write P into KP rows [wrow, wrow+16) (warp-private), pre-rounded
#pragma unroll
            for (int nf = 0; nf < 8; nf++) {
                int c = nf * 8 + tig * 2;
                KP[(wrow + g    ) * QSTC + c    ] = to_tf32(sacc[nf][0]);
                KP[(wrow + g    ) * QSTC + c + 1] = to_tf32(sacc[nf][1]);
                KP[(wrow + g + 8) * QSTC + c    ] = to_tf32(sacc[nf][2]);
                KP[(wrow + g + 8) * QSTC + c + 1] = to_tf32(sacc[nf][3]);
            }
            __syncwarp();

            // GEMM2: O(16x64) += P(16x64) @ V(64x64)
#pragma unroll
            for (int ks = 0; ks < 8; ks++) {
                float a0 = KP[(wrow + g    ) * QSTC + ks * 8 + tig];
                float a1 = KP[(wrow + g + 8) * QSTC + ks * 8 + tig];
                float a2 = KP[(wrow + g    ) * QSTC + ks * 8 + tig + 4];
                float a3 = KP[(wrow + g + 8) * QSTC + ks * 8 + tig + 4];
#pragma unroll
                for (int nf = 0; nf < 8; nf++) {
                    float b0 = to_tf32(Vs[(ks * 8 + tig    ) * VSTC + nf * 8 + g]);
                    float b1 = to_tf32(Vs[(ks * 8 + tig + 4) * VSTC + nf * 8 + g]);
                    mma8(accO[nf], a0, a1, a2, a3, b0, b1);
                }
            }
        }
    }

    // epilogue: normalize, write ctx [B,S,D] with head concat
    const int b = bh >> 4;
    const int h = bh & 15;
    float inv0 = 1.0f / l0, inv1 = 1.0f / l1;
    int s0 = qwarp + g;
    int s1 = s0 + 8;
#pragma unroll
    for (int nf = 0; nf < 8; nf++) {
        int e = (h << 6) + (nf << 3) + (tig << 1);
        float2 v0, v1;
        v0.x = accO[nf][0] * inv0; v0.y = accO[nf][1] * inv0;
        v1.x = accO[nf][2] * inv1; v1.y = accO[nf][3] * inv1;
        *(float2*)&ctx[((size_t)b * SS + s0) * DD + e] = v0;
        *(float2*)&ctx[((size_t)b * SS + s1) * DD + e] = v1;
    }
}

// ---------------------------------------------------------------------------
extern "C" void kernel_launch(void* const* d_in, const int* in_sizes, int n_in,
                              void* d_out, int out_size)
{
    const float* q   = (const float*)d_in[0];
    const float* k   = (const float*)d_in[1];
    const float* v   = (const float*)d_in[2];
    // d_in[3] = mask (causal tril) — computed analytically in-kernel
    const float* w_q = (const float*)d_in[4];
    const float* w_k = (const float*)d_in[5];
    const float* w_v = (const float*)d_in[6];
    const float* w_o = (const float*)d_in[7];

    float* out  = (float*)d_out;
    float* keyh = out + OUT_PLANE;
    float* valh = out + 2 * (size_t)OUT_PLANE;

    float* qh = nullptr;
    float* ctx = nullptr;
    cudaGetSymbolAddress((void**)&qh, g_Qh);
    cudaGetSymbolAddress((void**)&ctx, g_ctx);

    static bool configured = false;
    if (!configured) {
        cudaFuncSetAttribute(gemm_qkv, cudaFuncAttributeMaxDynamicSharedMemorySize,
                             GEMM_SMEM);
        cudaFuncSetAttribute(gemm_out_k, cudaFuncAttributeMaxDynamicSharedMemorySize,
                             GEMM_SMEM);
        cudaFuncSetAttribute(attn_tc, cudaFuncAttributeMaxDynamicSharedMemorySize,
                             ATT_SMEM);
        configured = true;
    }

    dim3 qkvgrid(DD / 128, MM / 128, 3);   // (8, 64, 3)
    gemm_qkv<<<qkvgrid, 256, GEMM_SMEM>>>(q, k, v, w_q, w_k, w_v, qh, keyh, valh);

    dim3 agrid(SS / 128, BB * HH);         // (16, 64)
    attn_tc<<<agrid, 256, ATT_SMEM>>>(qh, keyh, valh, ctx);

    dim3 ogrid(DD / 128, MM / 128, 1);     // (8, 64)
    gemm_out_k<<<ogrid, 256, GEMM_SMEM>>>(ctx, w_o, out);
}

// round 7
// speedup vs baseline: 1.7471x; 1.1494x over previous
#include <cuda_runtime.h>
#include <cstdint>

// Problem constants
#define BB 4
#define SS 2048
#define DD 1024
#define HH 16
#define DKK 64
#define MM (BB*SS)            // 8192
#define OUT_PLANE (BB*SS*DD)  // 8388608
#define HPLANE (BB*HH*SS*DKK) // 8388608

// Scratch (allocation-free rule: __device__ globals)
__device__ float g_Qh[HPLANE];       // Q projected, head layout, tf32-rounded
__device__ float g_rKh[HPLANE];      // K projected, tf32-rounded (attn input)
__device__ float g_rVh[HPLANE];      // V projected, tf32-rounded (attn input)
__device__ float g_ctx[BB*SS*DD];    // attention context, tf32-rounded
__device__ float g_rw[4*DD*DD];      // tf32-rounded weights (q,k,v,o)

// ---------------------------------------------------------------------------
// helpers
// ---------------------------------------------------------------------------
__device__ __forceinline__ float to_tf32(float x) {
    uint32_t u;
    asm("cvt.rna.tf32.f32 %0, %1;" : "=r"(u) : "f"(x));
    return __uint_as_float(u);
}

// D += A(16x8) * B(8x8), tf32 inputs, fp32 accum
__device__ __forceinline__ void mma8(float* c, float a0, float a1, float a2, float a3,
                                     float b0, float b1) {
    asm volatile(
        "mma.sync.aligned.m16n8k8.row.col.f32.tf32.tf32.f32 "
        "{%0,%1,%2,%3}, {%4,%5,%6,%7}, {%8,%9}, {%0,%1,%2,%3};\n"
        : "+f"(c[0]), "+f"(c[1]), "+f"(c[2]), "+f"(c[3])
        : "r"(__float_as_uint(a0)), "r"(__float_as_uint(a1)),
          "r"(__float_as_uint(a2)), "r"(__float_as_uint(a3)),
          "r"(__float_as_uint(b0)), "r"(__float_as_uint(b1)));
}

__device__ __forceinline__ uint32_t smem_u32(const void* p) {
    uint32_t a;
    asm("{ .reg .u64 t; cvta.to.shared.u64 t, %1; cvt.u32.u64 %0, t; }"
        : "=r"(a) : "l"(p));
    return a;
}

__device__ __forceinline__ void cp16(uint32_t saddr, const void* gptr) {
    asm volatile("cp.async.cg.shared.global [%0], [%1], 16;"
                 :: "r"(saddr), "l"(gptr));
}
#define CP_COMMIT() asm volatile("cp.async.commit_group;" ::: "memory")
#define CP_WAIT(n)  asm volatile("cp.async.wait_group %0;" :: "n"(n) : "memory")

// ---------------------------------------------------------------------------
// weight pre-round: g_rw[plane] = tf32(w)   (4 planes of 1M floats)
// ---------------------------------------------------------------------------
__global__ __launch_bounds__(256) void round_w_k(const float* __restrict__ wq,
                                                 const float* __restrict__ wk,
                                                 const float* __restrict__ wv,
                                                 const float* __restrict__ wo)
{
    const float* src = (blockIdx.y == 0) ? wq : (blockIdx.y == 1) ? wk
                     : (blockIdx.y == 2) ? wv : wo;
    float* dst = g_rw + (size_t)blockIdx.y * (DD * DD);
    int i = (blockIdx.x * 256 + threadIdx.x) * 4;
    float4 v = *(const float4*)(src + i);
    v.x = to_tf32(v.x); v.y = to_tf32(v.y);
    v.z = to_tf32(v.z); v.w = to_tf32(v.w);
    *(float4*)(dst + i) = v;
}

// ---------------------------------------------------------------------------
// TF32 GEMM, BK=32, 3-stage cp.async: C[m,e] = sum_d A[m,d] * W[e,d]
// W MUST be pre-rounded to tf32. ACVT: round A-side fragments at read.
// Block tile 128x128, 256 threads = 8 warps (4M x 2N), warp = 32x64.
// HEAD epilogue: out_full (fp32, optional) + out_round (tf32, optional),
// both in [B,H,S,DK] head layout. HEAD=0: flat fp32 to out_full.
// ---------------------------------------------------------------------------
#define GST 36
#define STAGE_F (128 * GST)
#define GEMM_SMEM (3 * STAGE_F * 2 * 4) // 110592 B

template<int HEAD, int ACVT>
__device__ __forceinline__ void gemm_body(const float* __restrict__ A,
                                          const float* __restrict__ W,
                                          float* __restrict__ out_full,
                                          float* __restrict__ out_round)
{
    extern __shared__ float dsm[];
    float* AsB = dsm;                   // [3][STAGE_F]
    float* BsB = dsm + 3 * STAGE_F;

    const int tid  = threadIdx.x;
    const int lane = tid & 31;
    const int w    = tid >> 5;
    const int g    = lane >> 2;
    const int tig  = lane & 3;
    const int wm   = w & 3;
    const int wn   = w >> 2;

    const int m0 = blockIdx.y << 7;
    const int n0 = blockIdx.x << 7;

    const uint32_t sA = smem_u32(AsB);
    const uint32_t sB = smem_u32(BsB);

    const int lrow = tid >> 3;          // 0..31 base row, +32 per i
    const int lc4  = tid & 7;           // 0..7

    const float* Ag = A + (size_t)(m0 + lrow) * DD + lc4 * 4;
    const float* Wg = W + (size_t)(n0 + lrow) * DD + lc4 * 4;
    const uint32_t soff = (uint32_t)(lrow * GST + lc4 * 4) * 4;
    const uint32_t srow32 = (uint32_t)(32 * GST) * 4;

    // prologue: chunks 0,1,2 -> stages 0,1,2
#pragma unroll
    for (int c = 0; c < 3; c++) {
        uint32_t sb = (uint32_t)(c * STAGE_F) * 4;
#pragma unroll
        for (int i = 0; i < 4; i++) {
            cp16(sA + sb + soff + i * srow32, Ag + (size_t)(i * 32) * DD + c * 32);
            cp16(sB + sb + soff + i * srow32, Wg + (size_t)(i * 32) * DD + c * 32);
        }
        CP_COMMIT();
    }

    float acc[2][8][4];
#pragma unroll
    for (int mf = 0; mf < 2; mf++)
#pragma unroll
        for (int nf = 0; nf < 8; nf++)
#pragma unroll
            for (int r = 0; r < 4; r++) acc[mf][nf][r] = 0.0f;

    int s_cur = 0;
    for (int t = 0; t < 32; t++) {
        if (t < 31) { CP_WAIT(2); } else { CP_WAIT(0); }
        __syncthreads();
        // at top of iter t, stage of chunk t-1 is consumed by all warps:
        // issue chunk t+2 into stage (t+2)%3 == (t-1)%3
        if (t >= 1 && t + 2 < 32) {
            uint32_t sb = (uint32_t)(((t + 2) % 3) * STAGE_F) * 4;
            const float* a2 = Ag + (t + 2) * 32;
            const float* w2 = Wg + (t + 2) * 32;
#pragma unroll
            for (int i = 0; i < 4; i++) {
                cp16(sA + sb + soff + i * srow32, a2 + (size_t)(i * 32) * DD);
                cp16(sB + sb + soff + i * srow32, w2 + (size_t)(i * 32) * DD);
            }
            CP_COMMIT();
        }
        const float* as = AsB + s_cur * STAGE_F;
        const float* bs = BsB + s_cur * STAGE_F;
#pragma unroll
        for (int ks = 0; ks < 4; ks++) {
            float a[2][4];
#pragma unroll
            for (int mf = 0; mf < 2; mf++) {
                int rr = (wm << 5) + (mf << 4);
                float x0 = as[(rr + g    ) * GST + ks * 8 + tig];
                float x1 = as[(rr + g + 8) * GST + ks * 8 + tig];
                float x2 = as[(rr + g    ) * GST + ks * 8 + tig + 4];
                float x3 = as[(rr + g + 8) * GST + ks * 8 + tig + 4];
                if (ACVT) { x0 = to_tf32(x0); x1 = to_tf32(x1);
                            x2 = to_tf32(x2); x3 = to_tf32(x3); }
                a[mf][0] = x0; a[mf][1] = x1; a[mf][2] = x2; a[mf][3] = x3;
            }
#pragma unroll
            for (int nf = 0; nf < 8; nf++) {
                int nr = (wn << 6) + (nf << 3) + g;
                float b0 = bs[nr * GST + ks * 8 + tig];
                float b1 = bs[nr * GST + ks * 8 + tig + 4];
                mma8(acc[0][nf], a[0][0], a[0][1], a[0][2], a[0][3], b0, b1);
                mma8(acc[1][nf], a[1][0], a[1][1], a[1][2], a[1][3], b0, b1);
            }
        }
        s_cur = (s_cur == 2) ? 0 : s_cur + 1;
    }

    // epilogue
#pragma unroll
    for (int mf = 0; mf < 2; mf++) {
#pragma unroll
        for (int half = 0; half < 2; half++) {
            int m = m0 + (wm << 5) + (mf << 4) + g + half * 8;
            int bq = m >> 11;
            int s  = m & 2047;
#pragma unroll
            for (int nf = 0; nf < 8; nf++) {
                int e = n0 + (wn << 6) + (nf << 3) + (tig << 1);
                float2 val;
                val.x = acc[mf][nf][half * 2 + 0];
                val.y = acc[mf][nf][half * 2 + 1];
                if (HEAD) {
                    int h = e >> 6, dk = e & 63;
                    size_t idx = ((((size_t)bq * HH + h) << 11) + s) * DKK + dk;
                    if (out_full) *(float2*)&out_full[idx] = val;
                    if (out_round) {
                        float2 rv;
                        rv.x = to_tf32(val.x);
                        rv.y = to_tf32(val.y);
                        *(float2*)&out_round[idx] = rv;
                    }
                } else {
                    *(float2*)&out_full[(size_t)m * DD + e] = val;
                }
            }
        }
    }
}

__global__ __launch_bounds__(256, 2) void gemm_qkv(
    const float* __restrict__ q, const float* __restrict__ k,
    const float* __restrict__ v,
    float* __restrict__ keyh, float* __restrict__ valh)
{
    const float* A; float* ofull; float* oround;
    const float* W = g_rw + (size_t)blockIdx.z * (DD * DD);
    if (blockIdx.z == 0)      { A = q; ofull = nullptr; oround = g_Qh; }
    else if (blockIdx.z == 1) { A = k; ofull = keyh;    oround = g_rKh; }
    else                      { A = v; ofull = valh;    oround = g_rVh; }
    gemm_body<1, 1>(A, W, ofull, oround);
}

__global__ __launch_bounds__(256, 2) void gemm_out_k(float* __restrict__ O)
{
    // A = g_ctx (pre-rounded by attn), W = g_rw plane 3 (pre-rounded)
    gemm_body<0, 0>(g_ctx, g_rw + (size_t)3 * DD * DD, O, nullptr);
}

// ---------------------------------------------------------------------------
// TF32 causal flash attention. Grid: (S/128, B*H). Block: 256 thr (8 warps).
// Inputs Q/K/V pre-rounded to tf32 (scratch copies) -> no CVT in inner loops.
// Warp w owns 16 query rows; block = 128 queries; K/V staged via cp.async.
// smem: Qs[128][68] + KP[128][68] + Vs[64][72] = 88064 B; 2 blocks/SM.
// ---------------------------------------------------------------------------
#define QSTC 68
#define VSTC 72
#define ATT_SMEM ((128*QSTC + 128*QSTC + 64*VSTC) * 4)   // 88064

__global__ __launch_bounds__(256, 2) void attn_tc(float* __restrict__ ctx)
{
    extern __shared__ float sm[];
    float* Qs = sm;                     // [128][QSTC]
    float* KP = sm + 128 * QSTC;        // [128][QSTC]
    float* Vs = sm + 2 * 128 * QSTC;    // [64][VSTC]

    const int tid  = threadIdx.x;
    const int lane = tid & 31;
    const int w    = tid >> 5;          // 0..7
    const int g    = lane >> 2;
    const int tig  = lane & 3;
    const int wrow = w << 4;            // 0..112
    const int bxr  = gridDim.x - 1 - blockIdx.x;   // heavy blocks first
    const int bh   = blockIdx.y;

    const size_t base = (size_t)bh * SS * DKK;
    const float* Qb = g_Qh + base + (size_t)bxr * 128 * DKK;
    const int qwarp = bxr * 128 + wrow;

    const uint32_t uKP = smem_u32(KP);
    const uint32_t uVs = smem_u32(Vs);

    // stage Q: pre-rounded; *0.125f is exact (power of two) so still tf32
#pragma unroll
    for (int u = 0; u < 8; u++) {
        int idx = u * 256 + tid;
        int r = idx >> 4, c4 = idx & 15;
        float4 t = *(const float4*)(Qb + r * DKK + c4 * 4);
        t.x *= 0.125f; t.y *= 0.125f; t.z *= 0.125f; t.w *= 0.125f;
        *(float4*)&Qs[r * QSTC + c4 * 4] = t;
    }
    __syncthreads();

    // Q a-fragments (persist whole block)
    float aQ[8][4];
#pragma unroll
    for (int ks = 0; ks < 8; ks++) {
        aQ[ks][0] = Qs[(wrow + g    ) * QSTC + ks * 8 + tig];
        aQ[ks][1] = Qs[(wrow + g + 8) * QSTC + ks * 8 + tig];
        aQ[ks][2] = Qs[(wrow + g    ) * QSTC + ks * 8 + tig + 4];
        aQ[ks][3] = Qs[(wrow + g + 8) * QSTC + ks * 8 + tig + 4];
    }

    float accO[8][4];
#pragma unroll
    for (int nf = 0; nf < 8; nf++)
#pragma unroll
        for (int r = 0; r < 4; r++) accO[nf][r] = 0.0f;
    float m0_ = -1e30f, m1_ = -1e30f, l0 = 0.0f, l1 = 0.0f;

    const int ktmax = 2 * bxr + 1;
    for (int kt = 0; kt <= ktmax; kt++) {
        __syncthreads();   // prior GEMM2 reads of KP/Vs done
        const float* Kt = g_rKh + base + (size_t)kt * 64 * DKK;
        const float* Vt = g_rVh + base + (size_t)kt * 64 * DKK;
#pragma unroll
        for (int u = 0; u < 4; u++) {
            int idx = u * 256 + tid;
            int r = idx >> 4, c4 = idx & 15;
            cp16(uKP + (uint32_t)(r * QSTC + c4 * 4) * 4, Kt + r * DKK + c4 * 4);
            cp16(uVs + (uint32_t)(r * VSTC + c4 * 4) * 4, Vt + r * DKK + c4 * 4);
        }
        CP_COMMIT();
        CP_WAIT(0);
        __syncthreads();

        // warp fully above causal frontier? (only lower warps on last tile)
        const bool skip = (kt * 64) > (qwarp + 15);

        float sacc[8][4];
        if (!skip) {
#pragma unroll
            for (int nf = 0; nf < 8; nf++)
#pragma unroll
                for (int r = 0; r < 4; r++) sacc[nf][r] = 0.0f;

            // GEMM1: S(16x64) = Q @ K^T  (operands pre-rounded)
#pragma unroll
            for (int ks = 0; ks < 8; ks++) {
#pragma unroll
                for (int nf = 0; nf < 8; nf++) {
                    float b0 = KP[(nf * 8 + g) * QSTC + ks * 8 + tig];
                    float b1 = KP[(nf * 8 + g) * QSTC + ks * 8 + tig + 4];
                    mma8(sacc[nf], aQ[ks][0], aQ[ks][1], aQ[ks][2], aQ[ks][3], b0, b1);
                }
            }

            // causal mask (absolute indices)
            if (kt * 64 + 63 > qwarp) {
                int r0 = qwarp + g, r1 = r0 + 8;
                int koff = kt * 64;
#pragma unroll
                for (int nf = 0; nf < 8; nf++) {
                    int c0 = koff + nf * 8 + tig * 2, c1 = c0 + 1;
                    if (c0 > r0) sacc[nf][0] = -1e30f;
                    if (c1 > r0) sacc[nf][1] = -1e30f;
                    if (c0 > r1) sacc[nf][2] = -1e30f;
                    if (c1 > r1) sacc[nf][3] = -1e30f;
                }
            }

            // online softmax (rows in quads: reduce over lane^1, lane^2)
            float rm0 = -1e30f, rm1 = -1e30f;
#pragma unroll
            for (int nf = 0; nf < 8; nf++) {
                rm0 = fmaxf(rm0, fmaxf(sacc[nf][0], sacc[nf][1]));
                rm1 = fmaxf(rm1, fmaxf(sacc[nf][2], sacc[nf][3]));
            }
            rm0 = fmaxf(rm0, __shfl_xor_sync(0xFFFFFFFFu, rm0, 1));
            rm0 = fmaxf(rm0, __shfl_xor_sync(0xFFFFFFFFu, rm0, 2));
            rm1 = fmaxf(rm1, __shfl_xor_sync(0xFFFFFFFFu, rm1, 1));
            rm1 = fmaxf(rm1, __shfl_xor_sync(0xFFFFFFFFu, rm1, 2));
            float mn0 = fmaxf(m0_, rm0), mn1 = fmaxf(m1_, rm1);
            float al0 = __expf(m0_ - mn0), al1 = __expf(m1_ - mn1);
            float rs0 = 0.0f, rs1 = 0.0f;
#pragma unroll
            for (int nf = 0; nf < 8; nf++) {
                sacc[nf][0] = __expf(sacc[nf][0] - mn0);
                sacc[nf][1] = __expf(sacc[nf][1] - mn0);
                sacc[nf][2] = __expf(sacc[nf][2] - mn1);
                sacc[nf][3] = __expf(sacc[nf][3] - mn1);
                rs0 += sacc[nf][0] + sacc[nf][1];
                rs1 += sacc[nf][2] + sacc[nf][3];
            }
            rs0 += __shfl_xor_sync(0xFFFFFFFFu, rs0, 1);
            rs0 += __shfl_xor_sync(0xFFFFFFFFu, rs0, 2);
            rs1 += __shfl_xor_sync(0xFFFFFFFFu, rs1, 1);
            rs1 += __shfl_xor_sync(0xFFFFFFFFu, rs1, 2);
            l0 = l0 * al0 + rs0;
            l1 = l1 * al1 + rs1;
            m0_ = mn0; m1_ = mn1;
#pragma unroll
            for (int nf = 0; nf < 8; nf++) {
                accO[nf][0] *= al0; accO[nf][1] *= al0;
                accO[nf][2] *= al1; accO[nf][3] *= al1;
            }
        }

        __syncthreads();   // all warps done reading KP as K

        if (!skip) {
            // write P into KP rows [wrow, wrow+16) (warp-private), pre-rounded
#pragma unroll
            for (int nf = 0; nf < 8; nf++) {
                int c = nf * 8 + tig * 2;
                KP[(wrow + g    ) * QSTC + c    ] = to_tf32(sacc[nf][0]);
                KP[(wrow + g    ) * QSTC + c + 1] = to_tf32(sacc[nf][1]);
                KP[(wrow + g + 8) * QSTC + c    ] = to_tf32(sacc[nf][2]);
                KP[(wrow + g + 8) * QSTC + c + 1] = to_tf32(sacc[nf][3]);
            }
            __syncwarp();

            // GEMM2: O(16x64) += P(16x64) @ V(64x64)  (V pre-rounded)
#pragma unroll
            for (int ks = 0; ks < 8; ks++) {
                float a0 = KP[(wrow + g    ) * QSTC + ks * 8 + tig];
                float a1 = KP[(wrow + g + 8) * QSTC + ks * 8 + tig];
                float a2 = KP[(wrow + g    ) * QSTC + ks * 8 + tig + 4];
                float a3 = KP[(wrow + g + 8) * QSTC + ks * 8 + tig + 4];
#pragma unroll
                for (int nf = 0; nf < 8; nf++) {
                    float b0 = Vs[(ks * 8 + tig    ) * VSTC + nf * 8 + g];
                    float b1 = Vs[(ks * 8 + tig + 4) * VSTC + nf * 8 + g];
                    mma8(accO[nf], a0, a1, a2, a3, b0, b1);
                }
            }
        }
    }

    // epilogue: normalize, write ctx tf32-rounded (out-GEMM consumes raw)
    const int b = bh >> 4;
    const int h = bh & 15;
    float inv0 = 1.0f / l0, inv1 = 1.0f / l1;
    int s0 = qwarp + g;
    int s1 = s0 + 8;
#pragma unroll
    for (int nf = 0; nf < 8; nf++) {
        int e = (h << 6) + (nf << 3) + (tig << 1);
        float2 v0, v1;
        v0.x = to_tf32(accO[nf][0] * inv0); v0.y = to_tf32(accO[nf][1] * inv0);
        v1.x = to_tf32(accO[nf][2] * inv1); v1.y = to_tf32(accO[nf][3] * inv1);
        *(float2*)&ctx[((size_t)b * SS + s0) * DD + e] = v0;
        *(float2*)&ctx[((size_t)b * SS + s1) * DD + e] = v1;
    }
}

// ---------------------------------------------------------------------------
extern "C" void kernel_launch(void* const* d_in, const int* in_sizes, int n_in,
                              void* d_out, int out_size)
{
    const float* q   = (const float*)d_in[0];
    const float* k   = (const float*)d_in[1];
    const float* v   = (const float*)d_in[2];
    // d_in[3] = mask (causal tril) — computed analytically in-kernel
    const float* w_q = (const float*)d_in[4];
    const float* w_k = (const float*)d_in[5];
    const float* w_v = (const float*)d_in[6];
    const float* w_o = (const float*)d_in[7];

    float* out  = (float*)d_out;
    float* keyh = out + OUT_PLANE;
    float* valh = out + 2 * (size_t)OUT_PLANE;

    float* ctx = nullptr;
    cudaGetSymbolAddress((void**)&ctx, g_ctx);

    static bool configured = false;
    if (!configured) {
        cudaFuncSetAttribute(gemm_qkv, cudaFuncAttributeMaxDynamicSharedMemorySize,
                             GEMM_SMEM);
        cudaFuncSetAttribute(gemm_out_k, cudaFuncAttributeMaxDynamicSharedMemorySize,
                             GEMM_SMEM);
        cudaFuncSetAttribute(attn_tc, cudaFuncAttributeMaxDynamicSharedMemorySize,
                             ATT_SMEM);
        configured = true;
    }

    dim3 wgrid(DD * DD / 1024, 4);         // (1024, 4)
    round_w_k<<<wgrid, 256>>>(w_q, w_k, w_v, w_o);

    dim3 qkvgrid(DD / 128, MM / 128, 3);   // (8, 64, 3)
    gemm_qkv<<<qkvgrid, 256, GEMM_SMEM>>>(q, k, v, keyh, valh);

    dim3 agrid(SS / 128, BB * HH);         // (16, 64)
    attn_tc<<<agrid, 256, ATT_SMEM>>>(ctx);

    dim3 ogrid(DD / 128, MM / 128, 1);     // (8, 64)
    gemm_out_k<<<ogrid, 256, GEMM_SMEM>>>(out);
}

// round 8
// speedup vs baseline: 1.8682x; 1.0693x over previous
#include <cuda_runtime.h>
#include <cstdint>

// Problem constants
#define BB 4
#define SS 2048
#define DD 1024
#define HH 16
#define DKK 64
#define MM (BB*SS)            // 8192
#define OUT_PLANE (BB*SS*DD)  // 8388608
#define HPLANE (BB*HH*SS*DKK) // 8388608

// Scratch (allocation-free rule: __device__ globals)
__device__ float g_Qh[HPLANE];       // Q projected, head layout, tf32-rounded
__device__ float g_rKh[HPLANE];      // K projected, tf32-rounded (attn input)
__device__ float g_rVh[HPLANE];      // V projected, tf32-rounded (attn input)
__device__ float g_ctx[BB*SS*DD];    // attention context, tf32-rounded
__device__ float g_rw[4*DD*DD];      // tf32-rounded weights (q,k,v,o)

// ---------------------------------------------------------------------------
// helpers
// ---------------------------------------------------------------------------
__device__ __forceinline__ float to_tf32(float x) {
    uint32_t u;
    asm("cvt.rna.tf32.f32 %0, %1;" : "=r"(u) : "f"(x));
    return __uint_as_float(u);
}

// D += A(16x8) * B(8x8), tf32 inputs, fp32 accum
__device__ __forceinline__ void mma8(float* c, float a0, float a1, float a2, float a3,
                                     float b0, float b1) {
    asm volatile(
        "mma.sync.aligned.m16n8k8.row.col.f32.tf32.tf32.f32 "
        "{%0,%1,%2,%3}, {%4,%5,%6,%7}, {%8,%9}, {%0,%1,%2,%3};\n"
        : "+f"(c[0]), "+f"(c[1]), "+f"(c[2]), "+f"(c[3])
        : "r"(__float_as_uint(a0)), "r"(__float_as_uint(a1)),
          "r"(__float_as_uint(a2)), "r"(__float_as_uint(a3)),
          "r"(__float_as_uint(b0)), "r"(__float_as_uint(b1)));
}

__device__ __forceinline__ uint32_t smem_u32(const void* p) {
    uint32_t a;
    asm("{ .reg .u64 t; cvta.to.shared.u64 t, %1; cvt.u32.u64 %0, t; }"
        : "=r"(a) : "l"(p));
    return a;
}

__device__ __forceinline__ void cp16(uint32_t saddr, const void* gptr) {
    asm volatile("cp.async.cg.shared.global [%0], [%1], 16;"
                 :: "r"(saddr), "l"(gptr));
}
#define CP_COMMIT() asm volatile("cp.async.commit_group;" ::: "memory")
#define CP_WAIT(n)  asm volatile("cp.async.wait_group %0;" :: "n"(n) : "memory")

// ---------------------------------------------------------------------------
// weight pre-round: g_rw[plane] = tf32(w)   (4 planes of 1M floats)
// ---------------------------------------------------------------------------
__global__ __launch_bounds__(256) void round_w_k(const float* __restrict__ wq,
                                                 const float* __restrict__ wk,
                                                 const float* __restrict__ wv,
                                                 const float* __restrict__ wo)
{
    const float* src = (blockIdx.y == 0) ? wq : (blockIdx.y == 1) ? wk
                     : (blockIdx.y == 2) ? wv : wo;
    float* dst = g_rw + (size_t)blockIdx.y * (DD * DD);
    int i = (blockIdx.x * 256 + threadIdx.x) * 4;
    float4 v = *(const float4*)(src + i);
    v.x = to_tf32(v.x); v.y = to_tf32(v.y);
    v.z = to_tf32(v.z); v.w = to_tf32(v.w);
    *(float4*)(dst + i) = v;
}

// ---------------------------------------------------------------------------
// TF32 GEMM, BK=32, 3-stage cp.async: C[m,e] = sum_d A[m,d] * W[e,d]
// W MUST be pre-rounded to tf32. ACVT: round A-side fragments at read.
// Block tile 128x128, 256 threads = 8 warps (4M x 2N), warp = 32x64.
// ---------------------------------------------------------------------------
#define GST 36
#define STAGE_F (128 * GST)
#define GEMM_SMEM (3 * STAGE_F * 2 * 4) // 110592 B

template<int HEAD, int ACVT>
__device__ __forceinline__ void gemm_body(const float* __restrict__ A,
                                          const float* __restrict__ W,
                                          float* __restrict__ out_full,
                                          float* __restrict__ out_round)
{
    extern __shared__ float dsm[];
    float* AsB = dsm;                   // [3][STAGE_F]
    float* BsB = dsm + 3 * STAGE_F;

    const int tid  = threadIdx.x;
    const int lane = tid & 31;
    const int w    = tid >> 5;
    const int g    = lane >> 2;
    const int tig  = lane & 3;
    const int wm   = w & 3;
    const int wn   = w >> 2;

    const int m0 = blockIdx.y << 7;
    const int n0 = blockIdx.x << 7;

    const uint32_t sA = smem_u32(AsB);
    const uint32_t sB = smem_u32(BsB);

    const int lrow = tid >> 3;          // 0..31 base row, +32 per i
    const int lc4  = tid & 7;           // 0..7

    const float* Ag = A + (size_t)(m0 + lrow) * DD + lc4 * 4;
    const float* Wg = W + (size_t)(n0 + lrow) * DD + lc4 * 4;
    const uint32_t soff = (uint32_t)(lrow * GST + lc4 * 4) * 4;
    const uint32_t srow32 = (uint32_t)(32 * GST) * 4;

    // prologue: chunks 0,1,2 -> stages 0,1,2
#pragma unroll
    for (int c = 0; c < 3; c++) {
        uint32_t sb = (uint32_t)(c * STAGE_F) * 4;
#pragma unroll
        for (int i = 0; i < 4; i++) {
            cp16(sA + sb + soff + i * srow32, Ag + (size_t)(i * 32) * DD + c * 32);
            cp16(sB + sb + soff + i * srow32, Wg + (size_t)(i * 32) * DD + c * 32);
        }
        CP_COMMIT();
    }

    float acc[2][8][4];
#pragma unroll
    for (int mf = 0; mf < 2; mf++)
#pragma unroll
        for (int nf = 0; nf < 8; nf++)
#pragma unroll
            for (int r = 0; r < 4; r++) acc[mf][nf][r] = 0.0f;

    int s_cur = 0;
    for (int t = 0; t < 32; t++) {
        if (t < 31) { CP_WAIT(2); } else { CP_WAIT(0); }
        __syncthreads();
        // at top of iter t, stage of chunk t-1 is consumed by all warps:
        // issue chunk t+2 into stage (t+2)%3 == (t-1)%3
        if (t >= 1 && t + 2 < 32) {
            uint32_t sb = (uint32_t)(((t + 2) % 3) * STAGE_F) * 4;
            const float* a2 = Ag + (t + 2) * 32;
            const float* w2 = Wg + (t + 2) * 32;
#pragma unroll
            for (int i = 0; i < 4; i++) {
                cp16(sA + sb + soff + i * srow32, a2 + (size_t)(i * 32) * DD);
                cp16(sB + sb + soff + i * srow32, w2 + (size_t)(i * 32) * DD);
            }
            CP_COMMIT();
        }
        const float* as = AsB + s_cur * STAGE_F;
        const float* bs = BsB + s_cur * STAGE_F;
#pragma unroll
        for (int ks = 0; ks < 4; ks++) {
            float a[2][4];
#pragma unroll
            for (int mf = 0; mf < 2; mf++) {
                int rr = (wm << 5) + (mf << 4);
                float x0 = as[(rr + g    ) * GST + ks * 8 + tig];
                float x1 = as[(rr + g + 8) * GST + ks * 8 + tig];
                float x2 = as[(rr + g    ) * GST + ks * 8 + tig + 4];
                float x3 = as[(rr + g + 8) * GST + ks * 8 + tig + 4];
                if (ACVT) { x0 = to_tf32(x0); x1 = to_tf32(x1);
                            x2 = to_tf32(x2); x3 = to_tf32(x3); }
                a[mf][0] = x0; a[mf][1] = x1; a[mf][2] = x2; a[mf][3] = x3;
            }
#pragma unroll
            for (int nf = 0; nf < 8; nf++) {
                int nr = (wn << 6) + (nf << 3) + g;
                float b0 = bs[nr * GST + ks * 8 + tig];
                float b1 = bs[nr * GST + ks * 8 + tig + 4];
                mma8(acc[0][nf], a[0][0], a[0][1], a[0][2], a[0][3], b0, b1);
                mma8(acc[1][nf], a[1][0], a[1][1], a[1][2], a[1][3], b0, b1);
            }
        }
        s_cur = (s_cur == 2) ? 0 : s_cur + 1;
    }

    // epilogue
#pragma unroll
    for (int mf = 0; mf < 2; mf++) {
#pragma unroll
        for (int half = 0; half < 2; half++) {
            int m = m0 + (wm << 5) + (mf << 4) + g + half * 8;
            int bq = m >> 11;
            int s  = m & 2047;
#pragma unroll
            for (int nf = 0; nf < 8; nf++) {
                int e = n0 + (wn << 6) + (nf << 3) + (tig << 1);
                float2 val;
                val.x = acc[mf][nf][half * 2 + 0];
                val.y = acc[mf][nf][half * 2 + 1];
                if (HEAD) {
                    int h = e >> 6, dk = e & 63;
                    size_t idx = ((((size_t)bq * HH + h) << 11) + s) * DKK + dk;
                    if (out_full) *(float2*)&out_full[idx] = val;
                    if (out_round) {
                        float2 rv;
                        rv.x = to_tf32(val.x);
                        rv.y = to_tf32(val.y);
                        *(float2*)&out_round[idx] = rv;
                    }
                } else {
                    *(float2*)&out_full[(size_t)m * DD + e] = val;
                }
            }
        }
    }
}

__global__ __launch_bounds__(256, 2) void gemm_qkv(
    const float* __restrict__ q, const float* __restrict__ k,
    const float* __restrict__ v,
    float* __restrict__ keyh, float* __restrict__ valh)
{
    const float* A; float* ofull; float* oround;
    const float* W = g_rw + (size_t)blockIdx.z * (DD * DD);
    if (blockIdx.z == 0)      { A = q; ofull = nullptr; oround = g_Qh; }
    else if (blockIdx.z == 1) { A = k; ofull = keyh;    oround = g_rKh; }
    else                      { A = v; ofull = valh;    oround = g_rVh; }
    gemm_body<1, 1>(A, W, ofull, oround);
}

__global__ __launch_bounds__(256, 2) void gemm_out_k(float* __restrict__ O)
{
    // A = g_ctx (pre-rounded by attn), W = g_rw plane 3 (pre-rounded)
    gemm_body<0, 0>(g_ctx, g_rw + (size_t)3 * DD * DD, O, nullptr);
}

// ---------------------------------------------------------------------------
// TF32 causal flash attention, double-buffered K/V. Grid: (S/128, B*H).
// Block: 256 thr (8 warps). Warp w owns 16 query rows.
// smem: QP[128][68] (Q staging, then P) + K[2][64][68] + V[2][64][72]
//       = 106496 B; 2 blocks/SM. Two barriers per tile, prefetch overlapped.
// ---------------------------------------------------------------------------
#define QSTC 68
#define VSTC 72
#define KBUF (64 * QSTC)
#define VBUF (64 * VSTC)
#define ATT_SMEM ((128*QSTC + 2*KBUF + 2*VBUF) * 4)   // 106496

__global__ __launch_bounds__(256, 2) void attn_tc(float* __restrict__ ctx)
{
    extern __shared__ float sm[];
    float* QP = sm;                       // [128][QSTC]: Q staging, then P
    float* Kb = sm + 128 * QSTC;          // [2][64][QSTC]
    float* Vb = sm + 128 * QSTC + 2 * KBUF; // [2][64][VSTC]

    const int tid  = threadIdx.x;
    const int lane = tid & 31;
    const int w    = tid >> 5;          // 0..7
    const int g    = lane >> 2;
    const int tig  = lane & 3;
    const int wrow = w << 4;            // 0..112
    const int bxr  = gridDim.x - 1 - blockIdx.x;   // heavy blocks first
    const int bh   = blockIdx.y;

    const size_t base = (size_t)bh * SS * DKK;
    const float* Qb = g_Qh + base + (size_t)bxr * 128 * DKK;
    const int qwarp = bxr * 128 + wrow;

    const uint32_t uKb = smem_u32(Kb);
    const uint32_t uVb = smem_u32(Vb);

    // loader mapping (per tile): idx = u*256+tid -> r = idx>>4, c4 = idx&15
    const int ldr = tid >> 4;           // base row, +16 per u
    const int ldc = tid & 15;

    // prefetch tile 0 into buffer 0
    {
        const float* K0 = g_rKh + base;
        const float* V0 = g_rVh + base;
#pragma unroll
        for (int u = 0; u < 4; u++) {
            int r = u * 16 + ldr;
            cp16(uKb + (uint32_t)(r * QSTC + ldc * 4) * 4, K0 + r * DKK + ldc * 4);
            cp16(uVb + (uint32_t)(r * VSTC + ldc * 4) * 4, V0 + r * DKK + ldc * 4);
        }
        CP_COMMIT();
    }

    // stage Q: pre-rounded; *0.125f is exact (power of two) so still tf32
#pragma unroll
    for (int u = 0; u < 8; u++) {
        int idx = u * 256 + tid;
        int r = idx >> 4, c4 = idx & 15;
        float4 t = *(const float4*)(Qb + r * DKK + c4 * 4);
        t.x *= 0.125f; t.y *= 0.125f; t.z *= 0.125f; t.w *= 0.125f;
        *(float4*)&QP[r * QSTC + c4 * 4] = t;
    }
    __syncthreads();

    // Q a-fragments (persist whole block; QP region becomes P afterwards)
    float aQ[8][4];
#pragma unroll
    for (int ks = 0; ks < 8; ks++) {
        aQ[ks][0] = QP[(wrow + g    ) * QSTC + ks * 8 + tig];
        aQ[ks][1] = QP[(wrow + g + 8) * QSTC + ks * 8 + tig];
        aQ[ks][2] = QP[(wrow + g    ) * QSTC + ks * 8 + tig + 4];
        aQ[ks][3] = QP[(wrow + g + 8) * QSTC + ks * 8 + tig + 4];
    }

    float accO[8][4];
#pragma unroll
    for (int nf = 0; nf < 8; nf++)
#pragma unroll
        for (int r = 0; r < 4; r++) accO[nf][r] = 0.0f;
    float m0_ = -1e30f, m1_ = -1e30f, l0 = 0.0f, l1 = 0.0f;

    const int ktmax = 2 * bxr + 1;
    for (int kt = 0; kt <= ktmax; kt++) {
        // all warps are done with buffers of tile kt-1 (same parity as kt+1)
        __syncthreads();

        if (kt + 1 <= ktmax) {
            const int bsel = (kt + 1) & 1;
            const float* Kn = g_rKh + base + (size_t)(kt + 1) * 64 * DKK;
            const float* Vn = g_rVh + base + (size_t)(kt + 1) * 64 * DKK;
            const uint32_t kb = uKb + (uint32_t)(bsel * KBUF) * 4;
            const uint32_t vb = uVb + (uint32_t)(bsel * VBUF) * 4;
#pragma unroll
            for (int u = 0; u < 4; u++) {
                int r = u * 16 + ldr;
                cp16(kb + (uint32_t)(r * QSTC + ldc * 4) * 4, Kn + r * DKK + ldc * 4);
                cp16(vb + (uint32_t)(r * VSTC + ldc * 4) * 4, Vn + r * DKK + ldc * 4);
            }
            CP_COMMIT();
            CP_WAIT(1);    // tile kt arrived; kt+1 still in flight
        } else {
            CP_WAIT(0);    // last tile
        }
        __syncthreads();   // kt data visible to all warps

        const float* Kc = Kb + (kt & 1) * KBUF;
        const float* Vc = Vb + (kt & 1) * VBUF;

        // warp fully above causal frontier? (only lower warps on last tile)
        const bool skip = (kt * 64) > (qwarp + 15);

        if (!skip) {
            float sacc[8][4];
#pragma unroll
            for (int nf = 0; nf < 8; nf++)
#pragma unroll
                for (int r = 0; r < 4; r++) sacc[nf][r] = 0.0f;

            // GEMM1: S(16x64) = Q @ K^T  (operands pre-rounded)
#pragma unroll
            for (int ks = 0; ks < 8; ks++) {
#pragma unroll
                for (int nf = 0; nf < 8; nf++) {
                    float b0 = Kc[(nf * 8 + g) * QSTC + ks * 8 + tig];
                    float b1 = Kc[(nf * 8 + g) * QSTC + ks * 8 + tig + 4];
                    mma8(sacc[nf], aQ[ks][0], aQ[ks][1], aQ[ks][2], aQ[ks][3], b0, b1);
                }
            }

            // causal mask (absolute indices)
            if (kt * 64 + 63 > qwarp) {
                int r0 = qwarp + g, r1 = r0 + 8;
                int koff = kt * 64;
#pragma unroll
                for (int nf = 0; nf < 8; nf++) {
                    int c0 = koff + nf * 8 + tig * 2, c1 = c0 + 1;
                    if (c0 > r0) sacc[nf][0] = -1e30f;
                    if (c1 > r0) sacc[nf][1] = -1e30f;
                    if (c0 > r1) sacc[nf][2] = -1e30f;
                    if (c1 > r1) sacc[nf][3] = -1e30f;
                }
            }

            // online softmax (rows in quads: reduce over lane^1, lane^2)
            float rm0 = -1e30f, rm1 = -1e30f;
#pragma unroll
            for (int nf = 0; nf < 8; nf++) {
                rm0 = fmaxf(rm0, fmaxf(sacc[nf][0], sacc[nf][1]));
                rm1 = fmaxf(rm1, fmaxf(sacc[nf][2], sacc[nf][3]));
            }
            rm0 = fmaxf(rm0, __shfl_xor_sync(0xFFFFFFFFu, rm0, 1));
            rm0 = fmaxf(rm0, __shfl_xor_sync(0xFFFFFFFFu, rm0, 2));
            rm1 = fmaxf(rm1, __shfl_xor_sync(0xFFFFFFFFu, rm1, 1));
            rm1 = fmaxf(rm1, __shfl_xor_sync(0xFFFFFFFFu, rm1, 2));
            float mn0 = fmaxf(m0_, rm0), mn1 = fmaxf(m1_, rm1);
            float al0 = __expf(m0_ - mn0), al1 = __expf(m1_ - mn1);
            float rs0 = 0.0f, rs1 = 0.0f;
#pragma unroll
            for (int nf = 0; nf < 8; nf++) {
                sacc[nf][0] = __expf(sacc[nf][0] - mn0);
                sacc[nf][1] = __expf(sacc[nf][1] - mn0);
                sacc[nf][2] = __expf(sacc[nf][2] - mn1);
                sacc[nf][3] = __expf(sacc[nf][3] - mn1);
                rs0 += sacc[nf][0] + sacc[nf][1];
                rs1 += sacc[nf][2] + sacc[nf][3];
            }
            rs0 += __shfl_xor_sync(0xFFFFFFFFu, rs0, 1);
            rs0 += __shfl_xor_sync(0xFFFFFFFFu, rs0, 2);
            rs1 += __shfl_xor_sync(0xFFFFFFFFu, rs1, 1);
            rs1 += __shfl_xor_sync(0xFFFFFFFFu, rs1, 2);
            l0 = l0 * al0 + rs0;
            l1 = l1 * al1 + rs1;
            m0_ = mn0; m1_ = mn1;
#pragma unroll
            for (int nf = 0; nf < 8; nf++) {
                accO[nf][0] *= al0; accO[nf][1] *= al0;
                accO[nf][2] *= al1; accO[nf][3] *= al1;
            }

            // write P into QP rows [wrow, wrow+16) (warp-private), pre-rounded
#pragma unroll
            for (int nf = 0; nf < 8; nf++) {
                int c = nf * 8 + tig * 2;
                QP[(wrow + g    ) * QSTC + c    ] = to_tf32(sacc[nf][0]);
                QP[(wrow + g    ) * QSTC + c + 1] = to_tf32(sacc[nf][1]);
                QP[(wrow + g + 8) * QSTC + c    ] = to_tf32(sacc[nf][2]);
                QP[(wrow + g + 8) * QSTC + c + 1] = to_tf32(sacc[nf][3]);
            }
            __syncwarp();

            // GEMM2: O(16x64) += P(16x64) @ V(64x64)  (V pre-rounded)
#pragma unroll
            for (int ks = 0; ks < 8; ks++) {
                float a0 = QP[(wrow + g    ) * QSTC + ks * 8 + tig];
                float a1 = QP[(wrow + g + 8) * QSTC + ks * 8 + tig];
                float a2 = QP[(wrow + g    ) * QSTC + ks * 8 + tig + 4];
                float a3 = QP[(wrow + g + 8) * QSTC + ks * 8 + tig + 4];
#pragma unroll
                for (int nf = 0; nf < 8; nf++) {
                    float b0 = Vc[(ks * 8 + tig    ) * VSTC + nf * 8 + g];
                    float b1 = Vc[(ks * 8 + tig + 4) * VSTC + nf * 8 + g];
                    mma8(accO[nf], a0, a1, a2, a3, b0, b1);
                }
            }
        }
    }

    // epilogue: normalize, write ctx tf32-rounded (out-GEMM consumes raw)
    const int b = bh >> 4;
    const int h = bh & 15;
    float inv0 = 1.0f / l0, inv1 = 1.0f / l1;
    int s0 = qwarp + g;
    int s1 = s0 + 8;
#pragma unroll
    for (int nf = 0; nf < 8; nf++) {
        int e = (h << 6) + (nf << 3) + (tig << 1);
        float2 v0, v1;
        v0.x = to_tf32(accO[nf][0] * inv0); v0.y = to_tf32(accO[nf][1] * inv0);
        v1.x = to_tf32(accO[nf][2] * inv1); v1.y = to_tf32(accO[nf][3] * inv1);
        *(float2*)&ctx[((size_t)b * SS + s0) * DD + e] = v0;
        *(float2*)&ctx[((size_t)b * SS + s1) * DD + e] = v1;
    }
}

// ---------------------------------------------------------------------------
extern "C" void kernel_launch(void* const* d_in, const int* in_sizes, int n_in,
                              void* d_out, int out_size)
{
    const float* q   = (const float*)d_in[0];
    const float* k   = (const float*)d_in[1];
    const float* v   = (const float*)d_in[2];
    // d_in[3] = mask (causal tril) — computed analytically in-kernel
    const float* w_q = (const float*)d_in[4];
    const float* w_k = (const float*)d_in[5];
    const float* w_v = (const float*)d_in[6];
    const float* w_o = (const float*)d_in[7];

    float* out  = (float*)d_out;
    float* keyh = out + OUT_PLANE;
    float* valh = out + 2 * (size_t)OUT_PLANE;

    float* ctx = nullptr;
    cudaGetSymbolAddress((void**)&ctx, g_ctx);

    static bool configured = false;
    if (!configured) {
        cudaFuncSetAttribute(gemm_qkv, cudaFuncAttributeMaxDynamicSharedMemorySize,
                             GEMM_SMEM);
        cudaFuncSetAttribute(gemm_out_k, cudaFuncAttributeMaxDynamicSharedMemorySize,
                             GEMM_SMEM);
        cudaFuncSetAttribute(attn_tc, cudaFuncAttributeMaxDynamicSharedMemorySize,
                             ATT_SMEM);
        configured = true;
    }

    dim3 wgrid(DD * DD / 1024, 4);         // (1024, 4)
    round_w_k<<<wgrid, 256>>>(w_q, w_k, w_v, w_o);

    dim3 qkvgrid(DD / 128, MM / 128, 3);   // (8, 64, 3)
    gemm_qkv<<<qkvgrid, 256, GEMM_SMEM>>>(q, k, v, keyh, valh);

    dim3 agrid(SS / 128, BB * HH);         // (16, 64)
    attn_tc<<<agrid, 256, ATT_SMEM>>>(ctx);

    dim3 ogrid(DD / 128, MM / 128, 1);     // (8, 64)
    gemm_out_k<<<ogrid, 256, GEMM_SMEM>>>(out);
}

// round 9
// speedup vs baseline: 2.0189x; 1.0807x over previous
#include <cuda_runtime.h>
#include <cstdint>

// Problem constants
#define BB 4
#define SS 2048
#define DD 1024
#define HH 16
#define DKK 64
#define MM (BB*SS)            // 8192
#define OUT_PLANE (BB*SS*DD)  // 8388608
#define HPLANE (BB*HH*SS*DKK) // 8388608

// Scratch (allocation-free rule: __device__ globals)
__device__ float g_Qh[HPLANE];        // Q projected, head layout, tf32-rounded
__device__ float g_rKh[HPLANE];       // K projected, tf32-rounded (attn input)
__device__ float g_rVh[HPLANE];       // V projected, tf32-rounded (attn input)
__device__ float g_ctx[BB*SS*DD];     // attention context, A2 fragment layout
__device__ float g_rw[4*DD*DD];       // weights, W2 fragment-pair layout
__device__ float g_pA[3*(size_t)MM*DD]; // q,k,v permuted to A2 + tf32-rounded

// Fragment layouts (for mma.sync m16n8k8 tf32):
//  A2: float4 quad per (jm=m/16, jk=k/8, lane): {A[16jm+g][8jk+tig], A[..+8][..],
//      A[g][tig+4], A[g+8][tig+4]}  g=lane>>2, tig=lane&3.
//      float index = ((jm*128 + jk)*32 + lane)*4
//  W2: float2 pair per (jn=n/8, jk=k/8, lane): {W[8jn+g][8jk+tig], W[..][tig+4]}
//      float index = ((jn*128 + jk)*32 + lane)*2

// ---------------------------------------------------------------------------
// helpers
// ---------------------------------------------------------------------------
__device__ __forceinline__ float to_tf32(float x) {
    uint32_t u;
    asm("cvt.rna.tf32.f32 %0, %1;" : "=r"(u) : "f"(x));
    return __uint_as_float(u);
}

__device__ __forceinline__ void mma8(float* c, float a0, float a1, float a2, float a3,
                                     float b0, float b1) {
    asm volatile(
        "mma.sync.aligned.m16n8k8.row.col.f32.tf32.tf32.f32 "
        "{%0,%1,%2,%3}, {%4,%5,%6,%7}, {%8,%9}, {%0,%1,%2,%3};\n"
        : "+f"(c[0]), "+f"(c[1]), "+f"(c[2]), "+f"(c[3])
        : "r"(__float_as_uint(a0)), "r"(__float_as_uint(a1)),
          "r"(__float_as_uint(a2)), "r"(__float_as_uint(a3)),
          "r"(__float_as_uint(b0)), "r"(__float_as_uint(b1)));
}

__device__ __forceinline__ uint32_t smem_u32(const void* p) {
    uint32_t a;
    asm("{ .reg .u64 t; cvta.to.shared.u64 t, %1; cvt.u32.u64 %0, t; }"
        : "=r"(a) : "l"(p));
    return a;
}

__device__ __forceinline__ void cp16(uint32_t saddr, const void* gptr) {
    asm volatile("cp.async.cg.shared.global [%0], [%1], 16;"
                 :: "r"(saddr), "l"(gptr));
}
#define CP_COMMIT() asm volatile("cp.async.commit_group;" ::: "memory")
#define CP_WAIT(n)  asm volatile("cp.async.wait_group %0;" :: "n"(n) : "memory")

// ---------------------------------------------------------------------------
// weight pre-round + permute to W2 fragment-pair layout (4 planes)
// block: 64 n-rows x 128 k-cols tile.  grid (16, 8, 4)
// ---------------------------------------------------------------------------
__global__ __launch_bounds__(256) void round_w_k(const float* __restrict__ wq,
                                                 const float* __restrict__ wk,
                                                 const float* __restrict__ wv,
                                                 const float* __restrict__ wo)
{
    __shared__ float SW[64][132];
    const int jnT = blockIdx.x;     // 0..15
    const int jkT = blockIdx.y;     // 0..7
    const int z   = blockIdx.z;
    const float* src = (z == 0) ? wq : (z == 1) ? wk : (z == 2) ? wv : wo;
    float* dst = g_rw + (size_t)z * DD * DD;
    const int t = threadIdx.x;
#pragma unroll
    for (int i = 0; i < 8; i++) {
        int f = i * 256 + t;        // 2048 float4 = 64 rows x 32 f4
        int r = f >> 5, c4 = f & 31;
        float4 vv = *(const float4*)(src + (size_t)(jnT * 64 + r) * DD
                                         + jkT * 128 + c4 * 4);
        *(float4*)&SW[r][c4 * 4] = vv;
    }
    __syncthreads();
#pragma unroll
    for (int i = 0; i < 8; i++) {
        int f = i * 256 + t;        // 2048 output float4
        int jnjk = f >> 4;          // 0..127
        int jn_l = jnjk >> 4, jk_l = jnjk & 15;
        int rem = f & 15;
        int l0 = rem * 2, l1 = l0 + 1;
        int g0 = l0 >> 2, t0 = l0 & 3, g1 = l1 >> 2, t1 = l1 & 3;
        float4 o;
        o.x = to_tf32(SW[jn_l * 8 + g0][jk_l * 8 + t0]);
        o.y = to_tf32(SW[jn_l * 8 + g0][jk_l * 8 + t0 + 4]);
        o.z = to_tf32(SW[jn_l * 8 + g1][jk_l * 8 + t1]);
        o.w = to_tf32(SW[jn_l * 8 + g1][jk_l * 8 + t1 + 4]);
        size_t f4 = (((size_t)(jnT * 8 + jn_l)) * 128 + jkT * 16 + jk_l) * 16 + rem;
        *(float4*)(dst + f4 * 4) = o;
    }
}

// ---------------------------------------------------------------------------
// input permute to A2 quad layout + tf32 round (q,k,v planes)
// block: 16 rows x 512 cols.  grid (512, 2, 3)
// ---------------------------------------------------------------------------
__global__ __launch_bounds__(256) void permute_in_k(const float* __restrict__ q,
                                                    const float* __restrict__ k,
                                                    const float* __restrict__ v)
{
    __shared__ float SP[16][516];
    const int jm = blockIdx.x;      // 0..511
    const int ch = blockIdx.y;      // 0..1
    const int z  = blockIdx.z;
    const float* src = (z == 0) ? q : (z == 1) ? k : v;
    float* dst = g_pA + (size_t)z * MM * DD;
    const int t = threadIdx.x;
#pragma unroll
    for (int i = 0; i < 8; i++) {
        int f = i * 256 + t;        // 2048 float4 = 16 rows x 128 f4
        int r = f >> 7, c4 = f & 127;
        float4 vv = *(const float4*)(src + (size_t)(jm * 16 + r) * DD
                                         + ch * 512 + c4 * 4);
        *(float4*)&SP[r][c4 * 4] = vv;
    }
    __syncthreads();
#pragma unroll
    for (int i = 0; i < 8; i++) {
        int f = i * 256 + t;        // 2048 output quads
        int jk_l = f >> 5;          // 0..63
        int lane = f & 31;
        int g = lane >> 2, tig = lane & 3;
        int kb = jk_l * 8 + tig;
        float4 o;
        o.x = to_tf32(SP[g    ][kb]);
        o.y = to_tf32(SP[g + 8][kb]);
        o.z = to_tf32(SP[g    ][kb + 4]);
        o.w = to_tf32(SP[g + 8][kb + 4]);
        size_t f4 = ((size_t)jm * 128 + ch * 64 + jk_l) * 32 + lane;
        *(float4*)(dst + f4 * 4) = o;
    }
}

// ---------------------------------------------------------------------------
// TF32 GEMM on fragment-major operands. C[m,e] = sum_d A[m,d] * W[e,d]
// A in A2 layout, W in W2 layout, both pre-rounded to tf32.
// Block tile 128x128, BK=32, 3-stage cp.async, 256 thr = 8 warps (4M x 2N).
// smem per stage: A 16KB + B 16KB; 3 stages = 96KB.
// ---------------------------------------------------------------------------
#define GEMM_SMEM (6 * 4096 * 4)   // 98304 B

template<int HEAD>
__device__ __forceinline__ void gemm_body(const float* __restrict__ A2,
                                          const float* __restrict__ W2,
                                          float* __restrict__ out_full,
                                          float* __restrict__ out_round)
{
    extern __shared__ float dsm[];
    float* AsB = dsm;               // [3][4096]
    float* BsB = dsm + 3 * 4096;    // [3][4096]

    const int tid  = threadIdx.x;
    const int lane = tid & 31;
    const int w    = tid >> 5;
    const int g    = lane >> 2;
    const int tig  = lane & 3;
    const int wm   = w & 3;
    const int wn   = w >> 2;

    const int m0  = blockIdx.y << 7;
    const int n0  = blockIdx.x << 7;
    const int jm0 = blockIdx.y * 8;
    const int jn0 = blockIdx.x * 16;

    const uint32_t sA = smem_u32(AsB);
    const uint32_t sB = smem_u32(BsB);

    // loaders: A: 8 groups of 32 threads, one jm each; B: 16 groups of 16.
    const int ajm = tid >> 5, ati = tid & 31;
    const int bjn = tid >> 4, bti = tid & 15;
    const float* Ag = A2 + (size_t)(jm0 + ajm) * 16384;   // per-jm stride 128*128
    const float* Bg = W2 + (size_t)(jn0 + bjn) * 8192;    // per-jn stride 128*64
    const uint32_t aoff = (uint32_t)(ajm * 512) * 4;
    const uint32_t boff = (uint32_t)(bjn * 256) * 4;

    // prologue: chunks 0,1,2 -> stages 0,1,2
#pragma unroll
    for (int c = 0; c < 3; c++) {
        uint32_t sb = (uint32_t)(c * 4096) * 4;
#pragma unroll
        for (int i = 0; i < 4; i++) {
            cp16(sA + sb + aoff + (uint32_t)((ati + i * 32) * 16),
                 Ag + c * 512 + (ati + i * 32) * 4);
            cp16(sB + sb + boff + (uint32_t)((bti + i * 16) * 16),
                 Bg + c * 256 + (bti + i * 16) * 4);
        }
        CP_COMMIT();
    }

    float acc[2][8][4];
#pragma unroll
    for (int mf = 0; mf < 2; mf++)
#pragma unroll
        for (int nf = 0; nf < 8; nf++)
#pragma unroll
            for (int r = 0; r < 4; r++) acc[mf][nf][r] = 0.0f;

    int s_cur = 0;
    for (int t = 0; t < 32; t++) {
        if (t < 31) { CP_WAIT(1); } else { CP_WAIT(0); }
        __syncthreads();
        // stage (t+2)%3 == (t-1)%3 holds chunk t-1, consumed by all warps
        if (t >= 1 && t + 2 < 32) {
            uint32_t sb = (uint32_t)(((t + 2) % 3) * 4096) * 4;
#pragma unroll
            for (int i = 0; i < 4; i++) {
                cp16(sA + sb + aoff + (uint32_t)((ati + i * 32) * 16),
                     Ag + (t + 2) * 512 + (ati + i * 32) * 4);
                cp16(sB + sb + boff + (uint32_t)((bti + i * 16) * 16),
                     Bg + (t + 2) * 256 + (bti + i * 16) * 4);
            }
            CP_COMMIT();
        }
        const float* as = AsB + s_cur * 4096;
        const float* bs = BsB + s_cur * 4096;
#pragma unroll
        for (int ks = 0; ks < 4; ks++) {
            float4 a0 = *(const float4*)&as[(wm * 2 + 0) * 512 + ks * 128 + lane * 4];
            float4 a1 = *(const float4*)&as[(wm * 2 + 1) * 512 + ks * 128 + lane * 4];
#pragma unroll
            for (int nf = 0; nf < 8; nf++) {
                float2 b = *(const float2*)&bs[(wn * 8 + nf) * 256 + ks * 64 + lane * 2];
                mma8(acc[0][nf], a0.x, a0.y, a0.z, a0.w, b.x, b.y);
                mma8(acc[1][nf], a1.x, a1.y, a1.z, a1.w, b.x, b.y);
            }
        }
        s_cur = (s_cur == 2) ? 0 : s_cur + 1;
    }

    // epilogue (row/col ownership unchanged from operand layouts)
#pragma unroll
    for (int mf = 0; mf < 2; mf++) {
#pragma unroll
        for (int half = 0; half < 2; half++) {
            int m = m0 + (wm << 5) + (mf << 4) + g + half * 8;
            int bq = m >> 11;
            int s  = m & 2047;
#pragma unroll
            for (int nf = 0; nf < 8; nf++) {
                int e = n0 + (wn << 6) + (nf << 3) + (tig << 1);
                float2 val;
                val.x = acc[mf][nf][half * 2 + 0];
                val.y = acc[mf][nf][half * 2 + 1];
                if (HEAD) {
                    int h = e >> 6, dk = e & 63;
                    size_t idx = ((((size_t)bq * HH + h) << 11) + s) * DKK + dk;
                    if (out_full) *(float2*)&out_full[idx] = val;
                    if (out_round) {
                        float2 rv;
                        rv.x = to_tf32(val.x);
                        rv.y = to_tf32(val.y);
                        *(float2*)&out_round[idx] = rv;
                    }
                } else {
                    *(float2*)&out_full[(size_t)m * DD + e] = val;
                }
            }
        }
    }
}

__global__ __launch_bounds__(256, 2) void gemm_qkv(
    float* __restrict__ keyh, float* __restrict__ valh)
{
    const int z = blockIdx.z;
    const float* A2 = g_pA + (size_t)z * MM * DD;
    const float* W2 = g_rw + (size_t)z * DD * DD;
    float* ofull; float* oround;
    if (z == 0)      { ofull = nullptr; oround = g_Qh; }
    else if (z == 1) { ofull = keyh;    oround = g_rKh; }
    else             { ofull = valh;    oround = g_rVh; }
    gemm_body<1>(A2, W2, ofull, oround);
}

__global__ __launch_bounds__(256, 2) void gemm_out_k(float* __restrict__ O)
{
    gemm_body<0>(g_ctx, g_rw + (size_t)3 * DD * DD, O, nullptr);
}

// ---------------------------------------------------------------------------
// TF32 causal flash attention, double-buffered K/V. Grid: (S/128, B*H).
// Block: 256 thr (8 warps). Warp w owns 16 query rows.
// smem: QP[128][68] (Q staging -> P -> O staging) + K[2][64][68] + V[2][64][72]
// Epilogue writes g_ctx in A2 layout (coalesced via QP staging).
// ---------------------------------------------------------------------------
#define QSTC 68
#define VSTC 72
#define KBUF (64 * QSTC)
#define VBUF (64 * VSTC)
#define ATT_SMEM ((128*QSTC + 2*KBUF + 2*VBUF) * 4)   // 106496

__global__ __launch_bounds__(256, 2) void attn_tc()
{
    extern __shared__ float sm[];
    float* QP = sm;                         // [128][QSTC]
    float* Kb = sm + 128 * QSTC;            // [2][64][QSTC]
    float* Vb = sm + 128 * QSTC + 2 * KBUF; // [2][64][VSTC]

    const int tid  = threadIdx.x;
    const int lane = tid & 31;
    const int w    = tid >> 5;
    const int g    = lane >> 2;
    const int tig  = lane & 3;
    const int wrow = w << 4;
    const int bxr  = gridDim.x - 1 - blockIdx.x;   // heavy blocks first
    const int bh   = blockIdx.y;

    const size_t base = (size_t)bh * SS * DKK;
    const float* Qb = g_Qh + base + (size_t)bxr * 128 * DKK;
    const int qwarp = bxr * 128 + wrow;

    const uint32_t uKb = smem_u32(Kb);
    const uint32_t uVb = smem_u32(Vb);

    const int ldr = tid >> 4;
    const int ldc = tid & 15;

    // prefetch tile 0 into buffer 0
    {
        const float* K0 = g_rKh + base;
        const float* V0 = g_rVh + base;
#pragma unroll
        for (int u = 0; u < 4; u++) {
            int r = u * 16 + ldr;
            cp16(uKb + (uint32_t)(r * QSTC + ldc * 4) * 4, K0 + r * DKK + ldc * 4);
            cp16(uVb + (uint32_t)(r * VSTC + ldc * 4) * 4, V0 + r * DKK + ldc * 4);
        }
        CP_COMMIT();
    }

    // stage Q: pre-rounded; *0.125f is exact (power of two) so still tf32
#pragma unroll
    for (int u = 0; u < 8; u++) {
        int idx = u * 256 + tid;
        int r = idx >> 4, c4 = idx & 15;
        float4 t = *(const float4*)(Qb + r * DKK + c4 * 4);
        t.x *= 0.125f; t.y *= 0.125f; t.z *= 0.125f; t.w *= 0.125f;
        *(float4*)&QP[r * QSTC + c4 * 4] = t;
    }
    __syncthreads();

    float aQ[8][4];
#pragma unroll
    for (int ks = 0; ks < 8; ks++) {
        aQ[ks][0] = QP[(wrow + g    ) * QSTC + ks * 8 + tig];
        aQ[ks][1] = QP[(wrow + g + 8) * QSTC + ks * 8 + tig];
        aQ[ks][2] = QP[(wrow + g    ) * QSTC + ks * 8 + tig + 4];
        aQ[ks][3] = QP[(wrow + g + 8) * QSTC + ks * 8 + tig + 4];
    }

    float accO[8][4];
#pragma unroll
    for (int nf = 0; nf < 8; nf++)
#pragma unroll
        for (int r = 0; r < 4; r++) accO[nf][r] = 0.0f;
    float m0_ = -1e30f, m1_ = -1e30f, l0 = 0.0f, l1 = 0.0f;

    const int ktmax = 2 * bxr + 1;
    for (int kt = 0; kt <= ktmax; kt++) {
        __syncthreads();

        if (kt + 1 <= ktmax) {
            const int bsel = (kt + 1) & 1;
            const float* Kn = g_rKh + base + (size_t)(kt + 1) * 64 * DKK;
            const float* Vn = g_rVh + base + (size_t)(kt + 1) * 64 * DKK;
            const uint32_t kb = uKb + (uint32_t)(bsel * KBUF) * 4;
            const uint32_t vb = uVb + (uint32_t)(bsel * VBUF) * 4;
#pragma unroll
            for (int u = 0; u < 4; u++) {
                int r = u * 16 + ldr;
                cp16(kb + (uint32_t)(r * QSTC + ldc * 4) * 4, Kn + r * DKK + ldc * 4);
                cp16(vb + (uint32_t)(r * VSTC + ldc * 4) * 4, Vn + r * DKK + ldc * 4);
            }
            CP_COMMIT();
            CP_WAIT(1);
        } else {
            CP_WAIT(0);
        }
        __syncthreads();

        const float* Kc = Kb + (kt & 1) * KBUF;
        const float* Vc = Vb + (kt & 1) * VBUF;

        const bool skip = (kt * 64) > (qwarp + 15);

        if (!skip) {
            float sacc[8][4];
#pragma unroll
            for (int nf = 0; nf < 8; nf++)
#pragma unroll
                for (int r = 0; r < 4; r++) sacc[nf][r] = 0.0f;

#pragma unroll
            for (int ks = 0; ks < 8; ks++) {
#pragma unroll
                for (int nf = 0; nf < 8; nf++) {
                    float b0 = Kc[(nf * 8 + g) * QSTC + ks * 8 + tig];
                    float b1 = Kc[(nf * 8 + g) * QSTC + ks * 8 + tig + 4];
                    mma8(sacc[nf], aQ[ks][0], aQ[ks][1], aQ[ks][2], aQ[ks][3], b0, b1);
                }
            }

            if (kt * 64 + 63 > qwarp) {
                int r0 = qwarp + g, r1 = r0 + 8;
                int koff = kt * 64;
#pragma unroll
                for (int nf = 0; nf < 8; nf++) {
                    int c0 = koff + nf * 8 + tig * 2, c1 = c0 + 1;
                    if (c0 > r0) sacc[nf][0] = -1e30f;
                    if (c1 > r0) sacc[nf][1] = -1e30f;
                    if (c0 > r1) sacc[nf][2] = -1e30f;
                    if (c1 > r1) sacc[nf][3] = -1e30f;
                }
            }

            float rm0 = -1e30f, rm1 = -1e30f;
#pragma unroll
            for (int nf = 0; nf < 8; nf++) {
                rm0 = fmaxf(rm0, fmaxf(sacc[nf][0], sacc[nf][1]));
                rm1 = fmaxf(rm1, fmaxf(sacc[nf][2], sacc[nf][3]));
            }
            rm0 = fmaxf(rm0, __shfl_xor_sync(0xFFFFFFFFu, rm0, 1));
            rm0 = fmaxf(rm0, __shfl_xor_sync(0xFFFFFFFFu, rm0, 2));
            rm1 = fmaxf(rm1, __shfl_xor_sync(0xFFFFFFFFu, rm1, 1));
            rm1 = fmaxf(rm1, __shfl_xor_sync(0xFFFFFFFFu, rm1, 2));
            float mn0 = fmaxf(m0_, rm0), mn1 = fmaxf(m1_, rm1);
            float al0 = __expf(m0_ - mn0), al1 = __expf(m1_ - mn1);
            float rs0 = 0.0f, rs1 = 0.0f;
#pragma unroll
            for (int nf = 0; nf < 8; nf++) {
                sacc[nf][0] = __expf(sacc[nf][0] - mn0);
                sacc[nf][1] = __expf(sacc[nf][1] - mn0);
                sacc[nf][2] = __expf(sacc[nf][2] - mn1);
                sacc[nf][3] = __expf(sacc[nf][3] - mn1);
                rs0 += sacc[nf][0] + sacc[nf][1];
                rs1 += sacc[nf][2] + sacc[nf][3];
            }
            rs0 += __shfl_xor_sync(0xFFFFFFFFu, rs0, 1);
            rs0 += __shfl_xor_sync(0xFFFFFFFFu, rs0, 2);
            rs1 += __shfl_xor_sync(0xFFFFFFFFu, rs1, 1);
            rs1 += __shfl_xor_sync(0xFFFFFFFFu, rs1, 2);
            l0 = l0 * al0 + rs0;
            l1 = l1 * al1 + rs1;
            m0_ = mn0; m1_ = mn1;
#pragma unroll
            for (int nf = 0; nf < 8; nf++) {
                accO[nf][0] *= al0; accO[nf][1] *= al0;
                accO[nf][2] *= al1; accO[nf][3] *= al1;
            }

            // write P into QP rows [wrow, wrow+16) (warp-private), pre-rounded
#pragma unroll
            for (int nf = 0; nf < 8; nf++) {
                int c = nf * 8 + tig * 2;
                QP[(wrow + g    ) * QSTC + c    ] = to_tf32(sacc[nf][0]);
                QP[(wrow + g    ) * QSTC + c + 1] = to_tf32(sacc[nf][1]);
                QP[(wrow + g + 8) * QSTC + c    ] = to_tf32(sacc[nf][2]);
                QP[(wrow + g + 8) * QSTC + c + 1] = to_tf32(sacc[nf][3]);
            }
            __syncwarp();

#pragma unroll
            for (int ks = 0; ks < 8; ks++) {
                float a0 = QP[(wrow + g    ) * QSTC + ks * 8 + tig];
                float a1 = QP[(wrow + g + 8) * QSTC + ks * 8 + tig];
                float a2 = QP[(wrow + g    ) * QSTC + ks * 8 + tig + 4];
                float a3 = QP[(wrow + g + 8) * QSTC + ks * 8 + tig + 4];
#pragma unroll
                for (int nf = 0; nf < 8; nf++) {
                    float b0 = Vc[(ks * 8 + tig    ) * VSTC + nf * 8 + g];
                    float b1 = Vc[(ks * 8 + tig + 4) * VSTC + nf * 8 + g];
                    mma8(accO[nf], a0, a1, a2, a3, b0, b1);
                }
            }
        }
    }

    // epilogue: normalize + round into QP (own rows), then cooperative
    // coalesced write of g_ctx in A2 fragment-quad layout.
    {
        float inv0 = 1.0f / l0, inv1 = 1.0f / l1;
#pragma unroll
        for (int nf = 0; nf < 8; nf++) {
            int c = nf * 8 + tig * 2;
            QP[(wrow + g    ) * QSTC + c    ] = to_tf32(accO[nf][0] * inv0);
            QP[(wrow + g    ) * QSTC + c + 1] = to_tf32(accO[nf][1] * inv0);
            QP[(wrow + g + 8) * QSTC + c    ] = to_tf32(accO[nf][2] * inv1);
            QP[(wrow + g + 8) * QSTC + c + 1] = to_tf32(accO[nf][3] * inv1);
        }
    }
    __syncthreads();
    {
        const int b = bh >> 4;
        const int h = bh & 15;
        const int jm0 = b * 128 + bxr * 8;   // (b*2048 + bxr*128)/16
#pragma unroll
        for (int i = 0; i < 8; i++) {
            int f = i * 256 + tid;           // 2048 quads
            int jm_l = f >> 8;
            int rem = f & 255;
            int jk_l = rem >> 5;
            int ln = rem & 31;
            int gg = ln >> 2, tt = ln & 3;
            int rb = jm_l * 16 + gg;
            int cb = jk_l * 8 + tt;
            float4 o;
            o.x = QP[rb * QSTC + cb];
            o.y = QP[(rb + 8) * QSTC + cb];
            o.z = QP[rb * QSTC + cb + 4];
            o.w = QP[(rb + 8) * QSTC + cb + 4];
            size_t f4 = (((size_t)(jm0 + jm_l)) * 128 + h * 8 + jk_l) * 32 + ln;
            *(float4*)(g_ctx + f4 * 4) = o;
        }
    }
}

// ---------------------------------------------------------------------------
extern "C" void kernel_launch(void* const* d_in, const int* in_sizes, int n_in,
                              void* d_out, int out_size)
{
    const float* q   = (const float*)d_in[0];
    const float* k   = (const float*)d_in[1];
    const float* v   = (const float*)d_in[2];
    // d_in[3] = mask (causal tril) — computed analytically in-kernel
    const float* w_q = (const float*)d_in[4];
    const float* w_k = (const float*)d_in[5];
    const float* w_v = (const float*)d_in[6];
    const float* w_o = (const float*)d_in[7];

    float* out  = (float*)d_out;
    float* keyh = out + OUT_PLANE;
    float* valh = out + 2 * (size_t)OUT_PLANE;

    static bool configured = false;
    if (!configured) {
        cudaFuncSetAttribute(gemm_qkv, cudaFuncAttributeMaxDynamicSharedMemorySize,
                             GEMM_SMEM);
        cudaFuncSetAttribute(gemm_out_k, cudaFuncAttributeMaxDynamicSharedMemorySize,
                             GEMM_SMEM);
        cudaFuncSetAttribute(attn_tc, cudaFuncAttributeMaxDynamicSharedMemorySize,
                             ATT_SMEM);
        configured = true;
    }

    dim3 wgrid(16, 8, 4);
    round_w_k<<<wgrid, 256>>>(w_q, w_k, w_v, w_o);

    dim3 pgrid(MM / 16, 2, 3);             // (512, 2, 3)
    permute_in_k<<<pgrid, 256>>>(q, k, v);

    dim3 qkvgrid(DD / 128, MM / 128, 3);   // (8, 64, 3)
    gemm_qkv<<<qkvgrid, 256, GEMM_SMEM>>>(keyh, valh);

    dim3 agrid(SS / 128, BB * HH);         // (16, 64)
    attn_tc<<<agrid, 256, ATT_SMEM>>>();

    dim3 ogrid(DD / 128, MM / 128, 1);     // (8, 64)
    gemm_out_k<<<ogrid, 256, GEMM_SMEM>>>(out);
}

// round 10
// speedup vs baseline: 2.0328x; 1.0069x over previous
#include <cuda_runtime.h>
#include <cstdint>

// Problem constants
#define BB 4
#define SS 2048
#define DD 1024
#define HH 16
#define DKK 64
#define MM (BB*SS)            // 8192
#define OUT_PLANE (BB*SS*DD)  // 8388608
#define HPLANE (BB*HH*SS*DKK) // 8388608

// Scratch (allocation-free rule: __device__ globals)
__device__ float g_Qh[HPLANE];        // Q proj, A2-quad layout, tf32*0.125
__device__ float g_rKh[HPLANE];       // K proj, K4-quad layout, tf32
__device__ float g_rVh[HPLANE];       // V proj, V4-quad layout, tf32
__device__ float g_ctx[BB*SS*DD];     // attention context, A2 layout, tf32
__device__ float g_rw[4*DD*DD];       // weights, W2 fragment-pair layout
__device__ float g_pA[3*(size_t)MM*DD]; // q,k,v inputs, A2 layout, tf32

// Fragment layouts (mma.sync m16n8k8 tf32), g=lane>>2, tig=lane&3:
//  A2 quad (jm=m/16, jk=k/8, lane): {A[16jm+g][8jk+tig], A[+8][..],
//          A[g][tig+4], A[+8][tig+4]}; float idx = ((jm*NJK + jk)*32 + lane)*4
//  W2 pair (jn=n/8, jk=k/8, lane): {W[8jn+g][8jk+tig], W[..][tig+4]}
//  K4 quad (bh, kt, jn=key/8, jkp=dk/16, lane):
//          {K[8jn+g][16jkp+tig], [+4], [+8], [+12]}   (1024 quads / tile)
//  V4 quad (bh, kt, jn=dk/8, jkp=key/16, lane):
//          {V[16jkp+tig][8jn+g], V[+4][..], V[+8][..], V[+12][..]}

// ---------------------------------------------------------------------------
// helpers
// ---------------------------------------------------------------------------
__device__ __forceinline__ float to_tf32(float x) {
    uint32_t u;
    asm("cvt.rna.tf32.f32 %0, %1;" : "=r"(u) : "f"(x));
    return __uint_as_float(u);
}

__device__ __forceinline__ void mma8(float* c, float a0, float a1, float a2, float a3,
                                     float b0, float b1) {
    asm volatile(
        "mma.sync.aligned.m16n8k8.row.col.f32.tf32.tf32.f32 "
        "{%0,%1,%2,%3}, {%4,%5,%6,%7}, {%8,%9}, {%0,%1,%2,%3};\n"
        : "+f"(c[0]), "+f"(c[1]), "+f"(c[2]), "+f"(c[3])
        : "r"(__float_as_uint(a0)), "r"(__float_as_uint(a1)),
          "r"(__float_as_uint(a2)), "r"(__float_as_uint(a3)),
          "r"(__float_as_uint(b0)), "r"(__float_as_uint(b1)));
}

__device__ __forceinline__ uint32_t smem_u32(const void* p) {
    uint32_t a;
    asm("{ .reg .u64 t; cvta.to.shared.u64 t, %1; cvt.u32.u64 %0, t; }"
        : "=r"(a) : "l"(p));
    return a;
}

__device__ __forceinline__ void cp16(uint32_t saddr, const void* gptr) {
    asm volatile("cp.async.cg.shared.global [%0], [%1], 16;"
                 :: "r"(saddr), "l"(gptr));
}
#define CP_COMMIT() asm volatile("cp.async.commit_group;" ::: "memory")
#define CP_WAIT(n)  asm volatile("cp.async.wait_group %0;" :: "n"(n) : "memory")

// ---------------------------------------------------------------------------
// weight pre-round + permute to W2 layout (4 planes). grid (16, 8, 4)
// ---------------------------------------------------------------------------
__global__ __launch_bounds__(256) void round_w_k(const float* __restrict__ wq,
                                                 const float* __restrict__ wk,
                                                 const float* __restrict__ wv,
                                                 const float* __restrict__ wo)
{
    __shared__ float SW[64][132];
    const int jnT = blockIdx.x;
    const int jkT = blockIdx.y;
    const int z   = blockIdx.z;
    const float* src = (z == 0) ? wq : (z == 1) ? wk : (z == 2) ? wv : wo;
    float* dst = g_rw + (size_t)z * DD * DD;
    const int t = threadIdx.x;
#pragma unroll
    for (int i = 0; i < 8; i++) {
        int f = i * 256 + t;
        int r = f >> 5, c4 = f & 31;
        float4 vv = *(const float4*)(src + (size_t)(jnT * 64 + r) * DD
                                         + jkT * 128 + c4 * 4);
        *(float4*)&SW[r][c4 * 4] = vv;
    }
    __syncthreads();
#pragma unroll
    for (int i = 0; i < 8; i++) {
        int f = i * 256 + t;
        int jnjk = f >> 4;
        int jn_l = jnjk >> 4, jk_l = jnjk & 15;
        int rem = f & 15;
        int l0 = rem * 2, l1 = l0 + 1;
        int g0 = l0 >> 2, t0 = l0 & 3, g1 = l1 >> 2, t1 = l1 & 3;
        float4 o;
        o.x = to_tf32(SW[jn_l * 8 + g0][jk_l * 8 + t0]);
        o.y = to_tf32(SW[jn_l * 8 + g0][jk_l * 8 + t0 + 4]);
        o.z = to_tf32(SW[jn_l * 8 + g1][jk_l * 8 + t1]);
        o.w = to_tf32(SW[jn_l * 8 + g1][jk_l * 8 + t1 + 4]);
        size_t f4 = (((size_t)(jnT * 8 + jn_l)) * 128 + jkT * 16 + jk_l) * 16 + rem;
        *(float4*)(dst + f4 * 4) = o;
    }
}

// ---------------------------------------------------------------------------
// input permute to A2 + tf32 round (q,k,v planes). grid (512, 2, 3)
// ---------------------------------------------------------------------------
__global__ __launch_bounds__(256) void permute_in_k(const float* __restrict__ q,
                                                    const float* __restrict__ k,
                                                    const float* __restrict__ v)
{
    __shared__ float SP[16][516];
    const int jm = blockIdx.x;
    const int ch = blockIdx.y;
    const int z  = blockIdx.z;
    const float* src = (z == 0) ? q : (z == 1) ? k : v;
    float* dst = g_pA + (size_t)z * MM * DD;
    const int t = threadIdx.x;
#pragma unroll
    for (int i = 0; i < 8; i++) {
        int f = i * 256 + t;
        int r = f >> 7, c4 = f & 127;
        float4 vv = *(const float4*)(src + (size_t)(jm * 16 + r) * DD
                                         + ch * 512 + c4 * 4);
        *(float4*)&SP[r][c4 * 4] = vv;
    }
    __syncthreads();
#pragma unroll
    for (int i = 0; i < 8; i++) {
        int f = i * 256 + t;
        int jk_l = f >> 5;
        int lane = f & 31;
        int g = lane >> 2, tig = lane & 3;
        int kb = jk_l * 8 + tig;
        float4 o;
        o.x = to_tf32(SP[g    ][kb]);
        o.y = to_tf32(SP[g + 8][kb]);
        o.z = to_tf32(SP[g    ][kb + 4]);
        o.w = to_tf32(SP[g + 8][kb + 4]);
        size_t f4 = ((size_t)jm * 128 + ch * 64 + jk_l) * 32 + lane;
        *(float4*)(dst + f4 * 4) = o;
    }
}

// ---------------------------------------------------------------------------
// TF32 GEMM on fragment-major operands, BK=32, 3-stage cp.async.
// MODE: 0 = flat fp32 out; 1 = Q (g_Qh A2, *0.125); 2 = K (out + g_rKh K4);
//       3 = V (out + g_rVh V4).
// ---------------------------------------------------------------------------
#define GEMM_SMEM (6 * 4096 * 4)   // 98304 B

template<int MODE>
__device__ __forceinline__ void gemm_body(const float* __restrict__ A2,
                                          const float* __restrict__ W2,
                                          float* __restrict__ out_full)
{
    extern __shared__ float dsm[];
    float* AsB = dsm;               // [3][4096]
    float* BsB = dsm + 3 * 4096;

    const int tid  = threadIdx.x;
    const int lane = tid & 31;
    const int w    = tid >> 5;
    const int g    = lane >> 2;
    const int tig  = lane & 3;
    const int wm   = w & 3;
    const int wn   = w >> 2;

    const int m0  = blockIdx.y << 7;
    const int n0  = blockIdx.x << 7;
    const int jm0 = blockIdx.y * 8;
    const int jn0 = blockIdx.x * 16;

    const uint32_t sA = smem_u32(AsB);
    const uint32_t sB = smem_u32(BsB);

    const int ajm = tid >> 5, ati = tid & 31;
    const int bjn = tid >> 4, bti = tid & 15;
    const float* Ag = A2 + (size_t)(jm0 + ajm) * 16384;
    const float* Bg = W2 + (size_t)(jn0 + bjn) * 8192;
    const uint32_t aoff = (uint32_t)(ajm * 512) * 4;
    const uint32_t boff = (uint32_t)(bjn * 256) * 4;

#pragma unroll
    for (int c = 0; c < 3; c++) {
        uint32_t sb = (uint32_t)(c * 4096) * 4;
#pragma unroll
        for (int i = 0; i < 4; i++) {
            cp16(sA + sb + aoff + (uint32_t)((ati + i * 32) * 16),
                 Ag + c * 512 + (ati + i * 32) * 4);
            cp16(sB + sb + boff + (uint32_t)((bti + i * 16) * 16),
                 Bg + c * 256 + (bti + i * 16) * 4);
        }
        CP_COMMIT();
    }

    float acc[2][8][4];
#pragma unroll
    for (int mf = 0; mf < 2; mf++)
#pragma unroll
        for (int nf = 0; nf < 8; nf++)
#pragma unroll
            for (int r = 0; r < 4; r++) acc[mf][nf][r] = 0.0f;

    int s_cur = 0;
    for (int t = 0; t < 32; t++) {
        if (t < 31) { CP_WAIT(1); } else { CP_WAIT(0); }
        __syncthreads();
        if (t >= 1 && t + 2 < 32) {
            uint32_t sb = (uint32_t)(((t + 2) % 3) * 4096) * 4;
#pragma unroll
            for (int i = 0; i < 4; i++) {
                cp16(sA + sb + aoff + (uint32_t)((ati + i * 32) * 16),
                     Ag + (t + 2) * 512 + (ati + i * 32) * 4);
                cp16(sB + sb + boff + (uint32_t)((bti + i * 16) * 16),
                     Bg + (t + 2) * 256 + (bti + i * 16) * 4);
            }
            CP_COMMIT();
        }
        const float* as = AsB + s_cur * 4096;
        const float* bs = BsB + s_cur * 4096;
#pragma unroll
        for (int ks = 0; ks < 4; ks++) {
            float4 a0 = *(const float4*)&as[(wm * 2 + 0) * 512 + ks * 128 + lane * 4];
            float4 a1 = *(const float4*)&as[(wm * 2 + 1) * 512 + ks * 128 + lane * 4];
#pragma unroll
            for (int nf = 0; nf < 8; nf++) {
                float2 b = *(const float2*)&bs[(wn * 8 + nf) * 256 + ks * 64 + lane * 2];
                mma8(acc[0][nf], a0.x, a0.y, a0.z, a0.w, b.x, b.y);
                mma8(acc[1][nf], a1.x, a1.y, a1.z, a1.w, b.x, b.y);
            }
        }
        s_cur = (s_cur == 2) ? 0 : s_cur + 1;
    }

    if (MODE == 0) {
        // flat fp32 epilogue (direct)
#pragma unroll
        for (int mf = 0; mf < 2; mf++) {
#pragma unroll
            for (int half = 0; half < 2; half++) {
                int m = m0 + (wm << 5) + (mf << 4) + g + half * 8;
#pragma unroll
                for (int nf = 0; nf < 8; nf++) {
                    int e = n0 + (wn << 6) + (nf << 3) + (tig << 1);
                    float2 val;
                    val.x = acc[mf][nf][half * 2 + 0];
                    val.y = acc[mf][nf][half * 2 + 1];
                    *(float2*)&out_full[(size_t)m * DD + e] = val;
                }
            }
        }
        return;
    }

    // staged epilogue: C tile -> smem [128][132]
    __syncthreads();
    float* stage = dsm;
#pragma unroll
    for (int mf = 0; mf < 2; mf++) {
#pragma unroll
        for (int half = 0; half < 2; half++) {
            int r = (wm << 5) + (mf << 4) + (half << 3) + g;
#pragma unroll
            for (int nf = 0; nf < 8; nf++) {
                int c = (wn << 6) + (nf << 3) + (tig << 1);
                float2 val;
                val.x = acc[mf][nf][half * 2 + 0];
                val.y = acc[mf][nf][half * 2 + 1];
                *(float2*)&stage[r * 132 + c] = val;
            }
        }
    }
    __syncthreads();

    const int bq = m0 >> 11;
    const int h0 = n0 >> 6;

    if (MODE == 2 || MODE == 3) {
        // fp32 head-layout output, coalesced
#pragma unroll
        for (int i = 0; i < 16; i++) {
            int f = i * 256 + tid;
            int row = f >> 5, c4 = f & 31;
            float4 v = *(const float4*)&stage[row * 132 + c4 * 4];
            int m = m0 + row;
            int s = m & 2047;
            int e = n0 + c4 * 4;
            int h = e >> 6, dk = e & 63;
            *(float4*)&out_full[((((size_t)bq * HH + h) << 11) + s) * DKK + dk] = v;
        }
    }

    if (MODE == 1) {
        const int jmb = (m0 & 2047) >> 4;
#pragma unroll
        for (int i = 0; i < 16; i++) {
            int f = i * 256 + tid;
            int ln = f & 31, qi = f >> 5;
            int jk = qi & 7, jm_l = (qi >> 3) & 7, hs = qi >> 6;
            int g2 = ln >> 2, t2 = ln & 3;
            int r = jm_l * 16 + g2, c = hs * 64 + jk * 8 + t2;
            float4 o;
            o.x = to_tf32(stage[r * 132 + c])       * 0.125f;
            o.y = to_tf32(stage[(r + 8) * 132 + c]) * 0.125f;
            o.z = to_tf32(stage[r * 132 + c + 4])       * 0.125f;
            o.w = to_tf32(stage[(r + 8) * 132 + c + 4]) * 0.125f;
            size_t qd = (((size_t)(bq * HH + h0 + hs) * 128 + jmb + jm_l) * 8 + jk) * 32 + ln;
            *(float4*)(g_Qh + qd * 4) = o;
        }
    } else if (MODE == 2) {
        const int kt0 = (m0 & 2047) >> 6;
#pragma unroll
        for (int i = 0; i < 16; i++) {
            int f = i * 256 + tid;
            int ln = f & 31, qi = f >> 5;
            int jkp = qi & 3, jn = (qi >> 2) & 7, ktl = (qi >> 5) & 1, hs = qi >> 6;
            int g2 = ln >> 2, t2 = ln & 3;
            int r = ktl * 64 + jn * 8 + g2;
            int c = hs * 64 + jkp * 16 + t2;
            float4 o;
            o.x = to_tf32(stage[r * 132 + c]);
            o.y = to_tf32(stage[r * 132 + c + 4]);
            o.z = to_tf32(stage[r * 132 + c + 8]);
            o.w = to_tf32(stage[r * 132 + c + 12]);
            size_t qd = ((size_t)(bq * HH + h0 + hs) * 32 + kt0 + ktl) * 1024
                      + (jn * 4 + jkp) * 32 + ln;
            *(float4*)(g_rKh + qd * 4) = o;
        }
    } else if (MODE == 3) {
        const int kt0 = (m0 & 2047) >> 6;
#pragma unroll
        for (int i = 0; i < 16; i++) {
            int f = i * 256 + tid;
            int ln = f & 31, qi = f >> 5;
            int jkp = qi & 3, jn = (qi >> 2) & 7, ktl = (qi >> 5) & 1, hs = qi >> 6;
            int g2 = ln >> 2, t2 = ln & 3;
            int rr = ktl * 64 + jkp * 16 + t2;
            int c = hs * 64 + jn * 8 + g2;
            float4 o;
            o.x = to_tf32(stage[rr * 132 + c]);
            o.y = to_tf32(stage[(rr + 4) * 132 + c]);
            o.z = to_tf32(stage[(rr + 8) * 132 + c]);
            o.w = to_tf32(stage[(rr + 12) * 132 + c]);
            size_t qd = ((size_t)(bq * HH + h0 + hs) * 32 + kt0 + ktl) * 1024
                      + (jn * 4 + jkp) * 32 + ln;
            *(float4*)(g_rVh + qd * 4) = o;
        }
    }
}

__global__ __launch_bounds__(256, 2) void gemm_qkv(
    float* __restrict__ keyh, float* __restrict__ valh)
{
    const int z = blockIdx.z;
    const float* A2 = g_pA + (size_t)z * MM * DD;
    const float* W2 = g_rw + (size_t)z * DD * DD;
    if (z == 0)      gemm_body<1>(A2, W2, nullptr);
    else if (z == 1) gemm_body<2>(A2, W2, keyh);
    else             gemm_body<3>(A2, W2, valh);
}

__global__ __launch_bounds__(256, 2) void gemm_out_k(float* __restrict__ O)
{
    gemm_body<0>(g_ctx, g_rw + (size_t)3 * DD * DD, O);
}

// ---------------------------------------------------------------------------
// TF32 causal flash attention, fragment-major K4/V4 + A2 Q, double-buffered.
// Grid: (S/128, B*H). Block: 256 thr (8 warps). Warp w owns 16 query rows.
// smem: QP[128][68] (P + O staging) + K4[2][4096] + V4[2][4096] = 100352 B.
// ---------------------------------------------------------------------------
#define QSTC 68
#define ATT_SMEM ((128*QSTC + 4*4096) * 4)   // 100352

__global__ __launch_bounds__(256, 2) void attn_tc()
{
    extern __shared__ float sm[];
    float* QP = sm;                      // [128][QSTC]
    float* Kb = sm + 128 * QSTC;         // [2][4096]
    float* Vb = sm + 128 * QSTC + 2 * 4096;

    const int tid  = threadIdx.x;
    const int lane = tid & 31;
    const int w    = tid >> 5;
    const int g    = lane >> 2;
    const int tig  = lane & 3;
    const int wrow = w << 4;
    const int bxr  = gridDim.x - 1 - blockIdx.x;   // heavy blocks first
    const int bh   = blockIdx.y;

    const int qwarp = bxr * 128 + wrow;

    const uint32_t uKb = smem_u32(Kb);
    const uint32_t uVb = smem_u32(Vb);

    const float* Ktiles = g_rKh + (size_t)bh * 32 * 4096;
    const float* Vtiles = g_rVh + (size_t)bh * 32 * 4096;

    // prefetch tile 0 into buffer 0
    {
#pragma unroll
        for (int u = 0; u < 4; u++) {
            int f = u * 256 + tid;
            cp16(uKb + (uint32_t)f * 16, Ktiles + f * 4);
            cp16(uVb + (uint32_t)f * 16, Vtiles + f * 4);
        }
        CP_COMMIT();
    }

    // Q fragments straight from global A2 layout (pre-scaled, pre-rounded)
    float aQ[8][4];
    {
        const float* Qf = g_Qh + ((size_t)bh * 128 + bxr * 8 + w) * 1024;
#pragma unroll
        for (int ks = 0; ks < 8; ks++) {
            float4 q4 = *(const float4*)(Qf + ks * 128 + lane * 4);
            aQ[ks][0] = q4.x; aQ[ks][1] = q4.y;
            aQ[ks][2] = q4.z; aQ[ks][3] = q4.w;
        }
    }

    float accO[8][4];
#pragma unroll
    for (int nf = 0; nf < 8; nf++)
#pragma unroll
        for (int r = 0; r < 4; r++) accO[nf][r] = 0.0f;
    float m0_ = -1e30f, m1_ = -1e30f, l0 = 0.0f, l1 = 0.0f;

    const int ktmax = 2 * bxr + 1;
    for (int kt = 0; kt <= ktmax; kt++) {
        __syncthreads();

        if (kt + 1 <= ktmax) {
            const int bsel = (kt + 1) & 1;
            const float* Kn = Ktiles + (size_t)(kt + 1) * 4096;
            const float* Vn = Vtiles + (size_t)(kt + 1) * 4096;
            const uint32_t kb = uKb + (uint32_t)(bsel * 4096) * 4;
            const uint32_t vb = uVb + (uint32_t)(bsel * 4096) * 4;
#pragma unroll
            for (int u = 0; u < 4; u++) {
                int f = u * 256 + tid;
                cp16(kb + (uint32_t)f * 16, Kn + f * 4);
                cp16(vb + (uint32_t)f * 16, Vn + f * 4);
            }
            CP_COMMIT();
            CP_WAIT(1);
        } else {
            CP_WAIT(0);
        }
        __syncthreads();

        const float* Kc = Kb + (kt & 1) * 4096;
        const float* Vc = Vb + (kt & 1) * 4096;

        const bool skip = (kt * 64) > (qwarp + 15);

        if (!skip) {
            float sacc[8][4];
#pragma unroll
            for (int nf = 0; nf < 8; nf++)
#pragma unroll
                for (int r = 0; r < 4; r++) sacc[nf][r] = 0.0f;

            // GEMM1: S = Q @ K^T, K4 quads (one LDS.128 feeds 2 k-steps)
#pragma unroll
            for (int jkp = 0; jkp < 4; jkp++) {
#pragma unroll
                for (int nf = 0; nf < 8; nf++) {
                    float4 bq = *(const float4*)&Kc[((nf * 4 + jkp) * 32 + lane) * 4];
                    mma8(sacc[nf], aQ[2*jkp][0], aQ[2*jkp][1], aQ[2*jkp][2],
                         aQ[2*jkp][3], bq.x, bq.y);
                    mma8(sacc[nf], aQ[2*jkp+1][0], aQ[2*jkp+1][1], aQ[2*jkp+1][2],
                         aQ[2*jkp+1][3], bq.z, bq.w);
                }
            }

            if (kt * 64 + 63 > qwarp) {
                int r0 = qwarp + g, r1 = r0 + 8;
                int koff = kt * 64;
#pragma unroll
                for (int nf = 0; nf < 8; nf++) {
                    int c0 = koff + nf * 8 + tig * 2, c1 = c0 + 1;
                    if (c0 > r0) sacc[nf][0] = -1e30f;
                    if (c1 > r0) sacc[nf][1] = -1e30f;
                    if (c0 > r1) sacc[nf][2] = -1e30f;
                    if (c1 > r1) sacc[nf][3] = -1e30f;
                }
            }

            float rm0 = -1e30f, rm1 = -1e30f;
#pragma unroll
            for (int nf = 0; nf < 8; nf++) {
                rm0 = fmaxf(rm0, fmaxf(sacc[nf][0], sacc[nf][1]));
                rm1 = fmaxf(rm1, fmaxf(sacc[nf][2], sacc[nf][3]));
            }
            rm0 = fmaxf(rm0, __shfl_xor_sync(0xFFFFFFFFu, rm0, 1));
            rm0 = fmaxf(rm0, __shfl_xor_sync(0xFFFFFFFFu, rm0, 2));
            rm1 = fmaxf(rm1, __shfl_xor_sync(0xFFFFFFFFu, rm1, 1));
            rm1 = fmaxf(rm1, __shfl_xor_sync(0xFFFFFFFFu, rm1, 2));
            float mn0 = fmaxf(m0_, rm0), mn1 = fmaxf(m1_, rm1);
            float al0 = __expf(m0_ - mn0), al1 = __expf(m1_ - mn1);
            float rs0 = 0.0f, rs1 = 0.0f;
#pragma unroll
            for (int nf = 0; nf < 8; nf++) {
                sacc[nf][0] = __expf(sacc[nf][0] - mn0);
                sacc[nf][1] = __expf(sacc[nf][1] - mn0);
                sacc[nf][2] = __expf(sacc[nf][2] - mn1);
                sacc[nf][3] = __expf(sacc[nf][3] - mn1);
                rs0 += sacc[nf][0] + sacc[nf][1];
                rs1 += sacc[nf][2] + sacc[nf][3];
            }
            rs0 += __shfl_xor_sync(0xFFFFFFFFu, rs0, 1);
            rs0 += __shfl_xor_sync(0xFFFFFFFFu, rs0, 2);
            rs1 += __shfl_xor_sync(0xFFFFFFFFu, rs1, 1);
            rs1 += __shfl_xor_sync(0xFFFFFFFFu, rs1, 2);
            l0 = l0 * al0 + rs0;
            l1 = l1 * al1 + rs1;
            m0_ = mn0; m1_ = mn1;
#pragma unroll
            for (int nf = 0; nf < 8; nf++) {
                accO[nf][0] *= al0; accO[nf][1] *= al0;
                accO[nf][2] *= al1; accO[nf][3] *= al1;
            }

            // write P into QP rows [wrow, wrow+16) (warp-private), pre-rounded
#pragma unroll
            for (int nf = 0; nf < 8; nf++) {
                int c = nf * 8 + tig * 2;
                QP[(wrow + g    ) * QSTC + c    ] = to_tf32(sacc[nf][0]);
                QP[(wrow + g    ) * QSTC + c + 1] = to_tf32(sacc[nf][1]);
                QP[(wrow + g + 8) * QSTC + c    ] = to_tf32(sacc[nf][2]);
                QP[(wrow + g + 8) * QSTC + c + 1] = to_tf32(sacc[nf][3]);
            }
            __syncwarp();

            // GEMM2: O += P @ V, V4 quads
#pragma unroll
            for (int jkp = 0; jkp < 4; jkp++) {
                int k0c = (2*jkp) * 8, k1c = (2*jkp+1) * 8;
                float p00 = QP[(wrow + g    ) * QSTC + k0c + tig];
                float p01 = QP[(wrow + g + 8) * QSTC + k0c + tig];
                float p02 = QP[(wrow + g    ) * QSTC + k0c + tig + 4];
                float p03 = QP[(wrow + g + 8) * QSTC + k0c + tig + 4];
                float p10 = QP[(wrow + g    ) * QSTC + k1c + tig];
                float p11 = QP[(wrow + g + 8) * QSTC + k1c + tig];
                float p12 = QP[(wrow + g    ) * QSTC + k1c + tig + 4];
                float p13 = QP[(wrow + g + 8) * QSTC + k1c + tig + 4];
#pragma unroll
                for (int nf = 0; nf < 8; nf++) {
                    float4 bq = *(const float4*)&Vc[((nf * 4 + jkp) * 32 + lane) * 4];
                    mma8(accO[nf], p00, p01, p02, p03, bq.x, bq.y);
                    mma8(accO[nf], p10, p11, p12, p13, bq.z, bq.w);
                }
            }
        }
    }

    // epilogue: normalize + round into QP, then coalesced A2 write of g_ctx
    {
        float inv0 = 1.0f / l0, inv1 = 1.0f / l1;
#pragma unroll
        for (int nf = 0; nf < 8; nf++) {
            int c = nf * 8 + tig * 2;
            QP[(wrow + g    ) * QSTC + c    ] = to_tf32(accO[nf][0] * inv0);
            QP[(wrow + g    ) * QSTC + c + 1] = to_tf32(accO[nf][1] * inv0);
            QP[(wrow + g + 8) * QSTC + c    ] = to_tf32(accO[nf][2] * inv1);
            QP[(wrow + g + 8) * QSTC + c + 1] = to_tf32(accO[nf][3] * inv1);
        }
    }
    __syncthreads();
    {
        const int b = bh >> 4;
        const int h = bh & 15;
        const int jm0 = b * 128 + bxr * 8;
#pragma unroll
        for (int i = 0; i < 8; i++) {
            int f = i * 256 + tid;
            int jm_l = f >> 8;
            int rem = f & 255;
            int jk_l = rem >> 5;
            int ln = rem & 31;
            int gg = ln >> 2, tt = ln & 3;
            int rb = jm_l * 16 + gg;
            int cb = jk_l * 8 + tt;
            float4 o;
            o.x = QP[rb * QSTC + cb];
            o.y = QP[(rb + 8) * QSTC + cb];
            o.z = QP[rb * QSTC + cb + 4];
            o.w = QP[(rb + 8) * QSTC + cb + 4];
            size_t f4 = (((size_t)(jm0 + jm_l)) * 128 + h * 8 + jk_l) * 32 + ln;
            *(float4*)(g_ctx + f4 * 4) = o;
        }
    }
}

// ---------------------------------------------------------------------------
extern "C" void kernel_launch(void* const* d_in, const int* in_sizes, int n_in,
                              void* d_out, int out_size)
{
    const float* q   = (const float*)d_in[0];
    const float* k   = (const float*)d_in[1];
    const float* v   = (const float*)d_in[2];
    // d_in[3] = mask (causal tril) — computed analytically in-kernel
    const float* w_q = (const float*)d_in[4];
    const float* w_k = (const float*)d_in[5];
    const float* w_v = (const float*)d_in[6];
    const float* w_o = (const float*)d_in[7];

    float* out  = (float*)d_out;
    float* keyh = out + OUT_PLANE;
    float* valh = out + 2 * (size_t)OUT_PLANE;

    static bool configured = false;
    if (!configured) {
        cudaFuncSetAttribute(gemm_qkv, cudaFuncAttributeMaxDynamicSharedMemorySize,
                             GEMM_SMEM);
        cudaFuncSetAttribute(gemm_out_k, cudaFuncAttributeMaxDynamicSharedMemorySize,
                             GEMM_SMEM);
        cudaFuncSetAttribute(attn_tc, cudaFuncAttributeMaxDynamicSharedMemorySize,
                             ATT_SMEM);
        configured = true;
    }

    dim3 wgrid(16, 8, 4);
    round_w_k<<<wgrid, 256>>>(w_q, w_k, w_v, w_o);

    dim3 pgrid(MM / 16, 2, 3);             // (512, 2, 3)
    permute_in_k<<<pgrid, 256>>>(q, k, v);

    dim3 qkvgrid(DD / 128, MM / 128, 3);   // (8, 64, 3)
    gemm_qkv<<<qkvgrid, 256, GEMM_SMEM>>>(keyh, valh);

    dim3 agrid(SS / 128, BB * HH);         // (16, 64)
    attn_tc<<<agrid, 256, ATT_SMEM>>>();

    dim3 ogrid(DD / 128, MM / 128, 1);     // (8, 64)
    gemm_out_k<<<ogrid, 256, GEMM_SMEM>>>(out);
}

// round 11
// speedup vs baseline: 2.1426x; 1.0540x over previous
#include <cuda_runtime.h>
#include <cstdint>

// Problem constants
#define BB 4
#define SS 2048
#define DD 1024
#define HH 16
#define DKK 64
#define MM (BB*SS)            // 8192
#define OUT_PLANE (BB*SS*DD)  // 8388608
#define HPLANE (BB*HH*SS*DKK) // 8388608

// Scratch (allocation-free rule: __device__ globals)
__device__ float g_Qh[HPLANE];        // Q proj, A2-quad layout, tf32*0.125
__device__ float g_rKh[HPLANE];       // K proj, K4-quad layout, tf32
__device__ float g_rVh[HPLANE];       // V proj, V4-quad layout, tf32
__device__ float g_ctx[BB*SS*DD];     // attention context, A2 layout, tf32
__device__ float g_rw[4*DD*DD];       // weights, W2 fragment-pair layout
__device__ float g_pA[3*(size_t)MM*DD]; // q,k,v inputs, A2 layout, tf32

// Fragment layouts (mma.sync m16n8k8 tf32), g=lane>>2, tig=lane&3:
//  A2 quad (jm=m/16, jk=k/8, lane): {A[16jm+g][8jk+tig], A[+8][..],
//          A[g][tig+4], A[+8][tig+4]}; float idx = ((jm*NJK + jk)*32 + lane)*4
//  W2 pair (jn=n/8, jk=k/8, lane): {W[8jn+g][8jk+tig], W[..][tig+4]}
//  K4 quad (bh, kt, jn=key/8, jkp=dk/16, lane):
//          {K[8jn+g][16jkp+tig], [+4], [+8], [+12]}   (1024 quads / tile)
//  V4 quad (bh, kt, jn=dk/8, jkp=key/16, lane):
//          {V[16jkp+tig][8jn+g], V[+4][..], V[+8][..], V[+12][..]}

// ---------------------------------------------------------------------------
// helpers
// ---------------------------------------------------------------------------
__device__ __forceinline__ float to_tf32(float x) {
    uint32_t u;
    asm("cvt.rna.tf32.f32 %0, %1;" : "=r"(u) : "f"(x));
    return __uint_as_float(u);
}

__device__ __forceinline__ void mma8(float* c, float a0, float a1, float a2, float a3,
                                     float b0, float b1) {
    asm volatile(
        "mma.sync.aligned.m16n8k8.row.col.f32.tf32.tf32.f32 "
        "{%0,%1,%2,%3}, {%4,%5,%6,%7}, {%8,%9}, {%0,%1,%2,%3};\n"
        : "+f"(c[0]), "+f"(c[1]), "+f"(c[2]), "+f"(c[3])
        : "r"(__float_as_uint(a0)), "r"(__float_as_uint(a1)),
          "r"(__float_as_uint(a2)), "r"(__float_as_uint(a3)),
          "r"(__float_as_uint(b0)), "r"(__float_as_uint(b1)));
}

__device__ __forceinline__ uint32_t smem_u32(const void* p) {
    uint32_t a;
    asm("{ .reg .u64 t; cvta.to.shared.u64 t, %1; cvt.u32.u64 %0, t; }"
        : "=r"(a) : "l"(p));
    return a;
}

__device__ __forceinline__ void cp16(uint32_t saddr, const void* gptr) {
    asm volatile("cp.async.cg.shared.global [%0], [%1], 16;"
                 :: "r"(saddr), "l"(gptr));
}
#define CP_COMMIT() asm volatile("cp.async.commit_group;" ::: "memory")
#define CP_WAIT(n)  asm volatile("cp.async.wait_group %0;" :: "n"(n) : "memory")

// ---------------------------------------------------------------------------
// weight pre-round + permute to W2 layout (4 planes). grid (16, 8, 4)
// ---------------------------------------------------------------------------
__global__ __launch_bounds__(256) void round_w_k(const float* __restrict__ wq,
                                                 const float* __restrict__ wk,
                                                 const float* __restrict__ wv,
                                                 const float* __restrict__ wo)
{
    __shared__ float SW[64][132];
    const int jnT = blockIdx.x;
    const int jkT = blockIdx.y;
    const int z   = blockIdx.z;
    const float* src = (z == 0) ? wq : (z == 1) ? wk : (z == 2) ? wv : wo;
    float* dst = g_rw + (size_t)z * DD * DD;
    const int t = threadIdx.x;
#pragma unroll
    for (int i = 0; i < 8; i++) {
        int f = i * 256 + t;
        int r = f >> 5, c4 = f & 31;
        float4 vv = *(const float4*)(src + (size_t)(jnT * 64 + r) * DD
                                         + jkT * 128 + c4 * 4);
        *(float4*)&SW[r][c4 * 4] = vv;
    }
    __syncthreads();
#pragma unroll
    for (int i = 0; i < 8; i++) {
        int f = i * 256 + t;
        int jnjk = f >> 4;
        int jn_l = jnjk >> 4, jk_l = jnjk & 15;
        int rem = f & 15;
        int l0 = rem * 2, l1 = l0 + 1;
        int g0 = l0 >> 2, t0 = l0 & 3, g1 = l1 >> 2, t1 = l1 & 3;
        float4 o;
        o.x = to_tf32(SW[jn_l * 8 + g0][jk_l * 8 + t0]);
        o.y = to_tf32(SW[jn_l * 8 + g0][jk_l * 8 + t0 + 4]);
        o.z = to_tf32(SW[jn_l * 8 + g1][jk_l * 8 + t1]);
        o.w = to_tf32(SW[jn_l * 8 + g1][jk_l * 8 + t1 + 4]);
        size_t f4 = (((size_t)(jnT * 8 + jn_l)) * 128 + jkT * 16 + jk_l) * 16 + rem;
        *(float4*)(dst + f4 * 4) = o;
    }
}

// ---------------------------------------------------------------------------
// input permute to A2 + tf32 round (q,k,v planes). grid (512, 2, 3)
// ---------------------------------------------------------------------------
__global__ __launch_bounds__(256) void permute_in_k(const float* __restrict__ q,
                                                    const float* __restrict__ k,
                                                    const float* __restrict__ v)
{
    __shared__ float SP[16][516];
    const int jm = blockIdx.x;
    const int ch = blockIdx.y;
    const int z  = blockIdx.z;
    const float* src = (z == 0) ? q : (z == 1) ? k : v;
    float* dst = g_pA + (size_t)z * MM * DD;
    const int t = threadIdx.x;
#pragma unroll
    for (int i = 0; i < 8; i++) {
        int f = i * 256 + t;
        int r = f >> 7, c4 = f & 127;
        float4 vv = *(const float4*)(src + (size_t)(jm * 16 + r) * DD
                                         + ch * 512 + c4 * 4);
        *(float4*)&SP[r][c4 * 4] = vv;
    }
    __syncthreads();
#pragma unroll
    for (int i = 0; i < 8; i++) {
        int f = i * 256 + t;
        int jk_l = f >> 5;
        int lane = f & 31;
        int g = lane >> 2, tig = lane & 3;
        int kb = jk_l * 8 + tig;
        float4 o;
        o.x = to_tf32(SP[g    ][kb]);
        o.y = to_tf32(SP[g + 8][kb]);
        o.z = to_tf32(SP[g    ][kb + 4]);
        o.w = to_tf32(SP[g + 8][kb + 4]);
        size_t f4 = ((size_t)jm * 128 + ch * 64 + jk_l) * 32 + lane;
        *(float4*)(dst + f4 * 4) = o;
    }
}

// ---------------------------------------------------------------------------
// TF32 GEMM on fragment-major operands, BK=32, 3-stage cp.async.
// MODE: 0 = flat fp32 out; 1 = Q (g_Qh A2, *0.125); 2 = K (out + g_rKh K4);
//       3 = V (out + g_rVh V4).
// ---------------------------------------------------------------------------
#define GEMM_SMEM (6 * 4096 * 4)   // 98304 B

template<int MODE>
__device__ __forceinline__ void gemm_body(const float* __restrict__ A2,
                                          const float* __restrict__ W2,
                                          float* __restrict__ out_full)
{
    extern __shared__ float dsm[];
    float* AsB = dsm;               // [3][4096]
    float* BsB = dsm + 3 * 4096;

    const int tid  = threadIdx.x;
    const int lane = tid & 31;
    const int w    = tid >> 5;
    const int g    = lane >> 2;
    const int tig  = lane & 3;
    const int wm   = w & 3;
    const int wn   = w >> 2;

    const int m0  = blockIdx.y << 7;
    const int n0  = blockIdx.x << 7;
    const int jm0 = blockIdx.y * 8;
    const int jn0 = blockIdx.x * 16;

    const uint32_t sA = smem_u32(AsB);
    const uint32_t sB = smem_u32(BsB);

    const int ajm = tid >> 5, ati = tid & 31;
    const int bjn = tid >> 4, bti = tid & 15;
    const float* Ag = A2 + (size_t)(jm0 + ajm) * 16384;
    const float* Bg = W2 + (size_t)(jn0 + bjn) * 8192;
    const uint32_t aoff = (uint32_t)(ajm * 512) * 4;
    const uint32_t boff = (uint32_t)(bjn * 256) * 4;

#pragma unroll
    for (int c = 0; c < 3; c++) {
        uint32_t sb = (uint32_t)(c * 4096) * 4;
#pragma unroll
        for (int i = 0; i < 4; i++) {
            cp16(sA + sb + aoff + (uint32_t)((ati + i * 32) * 16),
                 Ag + c * 512 + (ati + i * 32) * 4);
            cp16(sB + sb + boff + (uint32_t)((bti + i * 16) * 16),
                 Bg + c * 256 + (bti + i * 16) * 4);
        }
        CP_COMMIT();
    }

    float acc[2][8][4];
#pragma unroll
    for (int mf = 0; mf < 2; mf++)
#pragma unroll
        for (int nf = 0; nf < 8; nf++)
#pragma unroll
            for (int r = 0; r < 4; r++) acc[mf][nf][r] = 0.0f;

    int s_cur = 0;
    for (int t = 0; t < 32; t++) {
        if (t < 31) { CP_WAIT(1); } else { CP_WAIT(0); }
        __syncthreads();
        if (t >= 1 && t + 2 < 32) {
            uint32_t sb = (uint32_t)(((t + 2) % 3) * 4096) * 4;
#pragma unroll
            for (int i = 0; i < 4; i++) {
                cp16(sA + sb + aoff + (uint32_t)((ati + i * 32) * 16),
                     Ag + (t + 2) * 512 + (ati + i * 32) * 4);
                cp16(sB + sb + boff + (uint32_t)((bti + i * 16) * 16),
                     Bg + (t + 2) * 256 + (bti + i * 16) * 4);
            }
            CP_COMMIT();
        }
        const float* as = AsB + s_cur * 4096;
        const float* bs = BsB + s_cur * 4096;
#pragma unroll
        for (int ks = 0; ks < 4; ks++) {
            float4 a0 = *(const float4*)&as[(wm * 2 + 0) * 512 + ks * 128 + lane * 4];
            float4 a1 = *(const float4*)&as[(wm * 2 + 1) * 512 + ks * 128 + lane * 4];
#pragma unroll
            for (int nf = 0; nf < 8; nf++) {
                float2 b = *(const float2*)&bs[(wn * 8 + nf) * 256 + ks * 64 + lane * 2];
                mma8(acc[0][nf], a0.x, a0.y, a0.z, a0.w, b.x, b.y);
                mma8(acc[1][nf], a1.x, a1.y, a1.z, a1.w, b.x, b.y);
            }
        }
        s_cur = (s_cur == 2) ? 0 : s_cur + 1;
    }

    if (MODE == 0) {
#pragma unroll
        for (int mf = 0; mf < 2; mf++) {
#pragma unroll
            for (int half = 0; half < 2; half++) {
                int m = m0 + (wm << 5) + (mf << 4) + g + half * 8;
#pragma unroll
                for (int nf = 0; nf < 8; nf++) {
                    int e = n0 + (wn << 6) + (nf << 3) + (tig << 1);
                    float2 val;
                    val.x = acc[mf][nf][half * 2 + 0];
                    val.y = acc[mf][nf][half * 2 + 1];
                    *(float2*)&out_full[(size_t)m * DD + e] = val;
                }
            }
        }
        return;
    }

    // staged epilogue: C tile -> smem [128][132]
    __syncthreads();
    float* stage = dsm;
#pragma unroll
    for (int mf = 0; mf < 2; mf++) {
#pragma unroll
        for (int half = 0; half < 2; half++) {
            int r = (wm << 5) + (mf << 4) + (half << 3) + g;
#pragma unroll
            for (int nf = 0; nf < 8; nf++) {
                int c = (wn << 6) + (nf << 3) + (tig << 1);
                float2 val;
                val.x = acc[mf][nf][half * 2 + 0];
                val.y = acc[mf][nf][half * 2 + 1];
                *(float2*)&stage[r * 132 + c] = val;
            }
        }
    }
    __syncthreads();

    const int bq = m0 >> 11;
    const int h0 = n0 >> 6;

    if (MODE == 2 || MODE == 3) {
#pragma unroll
        for (int i = 0; i < 16; i++) {
            int f = i * 256 + tid;
            int row = f >> 5, c4 = f & 31;
            float4 v = *(const float4*)&stage[row * 132 + c4 * 4];
            int m = m0 + row;
            int s = m & 2047;
            int e = n0 + c4 * 4;
            int h = e >> 6, dk = e & 63;
            *(float4*)&out_full[((((size_t)bq * HH + h) << 11) + s) * DKK + dk] = v;
        }
    }

    if (MODE == 1) {
        const int jmb = (m0 & 2047) >> 4;
#pragma unroll
        for (int i = 0; i < 16; i++) {
            int f = i * 256 + tid;
            int ln = f & 31, qi = f >> 5;
            int jk = qi & 7, jm_l = (qi >> 3) & 7, hs = qi >> 6;
            int g2 = ln >> 2, t2 = ln & 3;
            int r = jm_l * 16 + g2, c = hs * 64 + jk * 8 + t2;
            float4 o;
            o.x = to_tf32(stage[r * 132 + c])       * 0.125f;
            o.y = to_tf32(stage[(r + 8) * 132 + c]) * 0.125f;
            o.z = to_tf32(stage[r * 132 + c + 4])       * 0.125f;
            o.w = to_tf32(stage[(r + 8) * 132 + c + 4]) * 0.125f;
            size_t qd = (((size_t)(bq * HH + h0 + hs) * 128 + jmb + jm_l) * 8 + jk) * 32 + ln;
            *(float4*)(g_Qh + qd * 4) = o;
        }
    } else if (MODE == 2) {
        const int kt0 = (m0 & 2047) >> 6;
#pragma unroll
        for (int i = 0; i < 16; i++) {
            int f = i * 256 + tid;
            int ln = f & 31, qi = f >> 5;
            int jkp = qi & 3, jn = (qi >> 2) & 7, ktl = (qi >> 5) & 1, hs = qi >> 6;
            int g2 = ln >> 2, t2 = ln & 3;
            int r = ktl * 64 + jn * 8 + g2;
            int c = hs * 64 + jkp * 16 + t2;
            float4 o;
            o.x = to_tf32(stage[r * 132 + c]);
            o.y = to_tf32(stage[r * 132 + c + 4]);
            o.z = to_tf32(stage[r * 132 + c + 8]);
            o.w = to_tf32(stage[r * 132 + c + 12]);
            size_t qd = ((size_t)(bq * HH + h0 + hs) * 32 + kt0 + ktl) * 1024
                      + (jn * 4 + jkp) * 32 + ln;
            *(float4*)(g_rKh + qd * 4) = o;
        }
    } else if (MODE == 3) {
        const int kt0 = (m0 & 2047) >> 6;
#pragma unroll
        for (int i = 0; i < 16; i++) {
            int f = i * 256 + tid;
            int ln = f & 31, qi = f >> 5;
            int jkp = qi & 3, jn = (qi >> 2) & 7, ktl = (qi >> 5) & 1, hs = qi >> 6;
            int g2 = ln >> 2, t2 = ln & 3;
            int rr = ktl * 64 + jkp * 16 + t2;
            int c = hs * 64 + jn * 8 + g2;
            float4 o;
            o.x = to_tf32(stage[rr * 132 + c]);
            o.y = to_tf32(stage[(rr + 4) * 132 + c]);
            o.z = to_tf32(stage[(rr + 8) * 132 + c]);
            o.w = to_tf32(stage[(rr + 12) * 132 + c]);
            size_t qd = ((size_t)(bq * HH + h0 + hs) * 32 + kt0 + ktl) * 1024
                      + (jn * 4 + jkp) * 32 + ln;
            *(float4*)(g_rVh + qd * 4) = o;
        }
    }
}

__global__ __launch_bounds__(256, 2) void gemm_qkv(
    float* __restrict__ keyh, float* __restrict__ valh)
{
    const int z = blockIdx.z;
    const float* A2 = g_pA + (size_t)z * MM * DD;
    const float* W2 = g_rw + (size_t)z * DD * DD;
    if (z == 0)      gemm_body<1>(A2, W2, nullptr);
    else if (z == 1) gemm_body<2>(A2, W2, keyh);
    else             gemm_body<3>(A2, W2, valh);
}

__global__ __launch_bounds__(256, 2) void gemm_out_k(float* __restrict__ O)
{
    gemm_body<0>(g_ctx, g_rw + (size_t)3 * DD * DD, O);
}

// ---------------------------------------------------------------------------
// TF32 causal flash attention, M=32 per warp. Grid: (S/128, B*H).
// Block: 128 thr (4 warps); warp w owns 32 query rows (2 m-frags).
// smem: QP[128][68] (P + O staging) + K4[2][4096] + V4[2][4096] = 100352 B.
// __launch_bounds__(128,2): reg cap 256, 2 blocks/SM (196KB smem).
// ---------------------------------------------------------------------------
#define QSTC 68
#define ATT_SMEM ((128*QSTC + 4*4096) * 4)   // 100352

__global__ __launch_bounds__(128, 2) void attn_tc()
{
    extern __shared__ float sm[];
    float* QP = sm;                      // [128][QSTC]
    float* Kb = sm + 128 * QSTC;         // [2][4096]
    float* Vb = sm + 128 * QSTC + 2 * 4096;

    const int tid  = threadIdx.x;
    const int lane = tid & 31;
    const int w    = tid >> 5;           // 0..3
    const int g    = lane >> 2;
    const int tig  = lane & 3;
    const int wrow = w << 5;             // 0,32,64,96
    const int bxr  = gridDim.x - 1 - blockIdx.x;   // heavy blocks first
    const int bh   = blockIdx.y;

    const int qwarp = bxr * 128 + wrow;

    const uint32_t uKb = smem_u32(Kb);
    const uint32_t uVb = smem_u32(Vb);

    const float* Ktiles = g_rKh + (size_t)bh * 32 * 4096;
    const float* Vtiles = g_rVh + (size_t)bh * 32 * 4096;

    // prefetch tile 0 into buffer 0 (1024 quads each, 128 threads)
    {
#pragma unroll
        for (int u = 0; u < 8; u++) {
            int f = u * 128 + tid;
            cp16(uKb + (uint32_t)f * 16, Ktiles + f * 4);
            cp16(uVb + (uint32_t)f * 16, Vtiles + f * 4);
        }
        CP_COMMIT();
    }

    // Q fragments straight from global A2 layout (pre-scaled, pre-rounded)
    float aQ[2][8][4];
#pragma unroll
    for (int mf = 0; mf < 2; mf++) {
        const float* Qf = g_Qh + ((size_t)bh * 128 + bxr * 8 + w * 2 + mf) * 1024;
#pragma unroll
        for (int ks = 0; ks < 8; ks++) {
            float4 q4 = *(const float4*)(Qf + ks * 128 + lane * 4);
            aQ[mf][ks][0] = q4.x; aQ[mf][ks][1] = q4.y;
            aQ[mf][ks][2] = q4.z; aQ[mf][ks][3] = q4.w;
        }
    }

    float accO[2][8][4];
#pragma unroll
    for (int mf = 0; mf < 2; mf++)
#pragma unroll
        for (int nf = 0; nf < 8; nf++)
#pragma unroll
            for (int r = 0; r < 4; r++) accO[mf][nf][r] = 0.0f;
    float m_[2][2] = {{-1e30f, -1e30f}, {-1e30f, -1e30f}};
    float l_[2][2] = {{0.0f, 0.0f}, {0.0f, 0.0f}};

    const int ktmax = 2 * bxr + 1;
    for (int kt = 0; kt <= ktmax; kt++) {
        __syncthreads();

        if (kt + 1 <= ktmax) {
            const int bsel = (kt + 1) & 1;
            const float* Kn = Ktiles + (size_t)(kt + 1) * 4096;
            const float* Vn = Vtiles + (size_t)(kt + 1) * 4096;
            const uint32_t kb = uKb + (uint32_t)(bsel * 4096) * 4;
            const uint32_t vb = uVb + (uint32_t)(bsel * 4096) * 4;
#pragma unroll
            for (int u = 0; u < 8; u++) {
                int f = u * 128 + tid;
                cp16(kb + (uint32_t)f * 16, Kn + f * 4);
                cp16(vb + (uint32_t)f * 16, Vn + f * 4);
            }
            CP_COMMIT();
            CP_WAIT(1);
        } else {
            CP_WAIT(0);
        }
        __syncthreads();

        const float* Kc = Kb + (kt & 1) * 4096;
        const float* Vc = Vb + (kt & 1) * 4096;

        const bool skip = (kt * 64) > (qwarp + 31);

        if (!skip) {
            float sacc[2][8][4];
#pragma unroll
            for (int mf = 0; mf < 2; mf++)
#pragma unroll
                for (int nf = 0; nf < 8; nf++)
#pragma unroll
                    for (int r = 0; r < 4; r++) sacc[mf][nf][r] = 0.0f;

            // GEMM1: S = Q @ K^T, K4 quads (one LDS.128 feeds 2 k-steps x 2 mf)
#pragma unroll
            for (int jkp = 0; jkp < 4; jkp++) {
#pragma unroll
                for (int nf = 0; nf < 8; nf++) {
                    float4 bq = *(const float4*)&Kc[((nf * 4 + jkp) * 32 + lane) * 4];
#pragma unroll
                    for (int mf = 0; mf < 2; mf++) {
                        mma8(sacc[mf][nf], aQ[mf][2*jkp][0], aQ[mf][2*jkp][1],
                             aQ[mf][2*jkp][2], aQ[mf][2*jkp][3], bq.x, bq.y);
                        mma8(sacc[mf][nf], aQ[mf][2*jkp+1][0], aQ[mf][2*jkp+1][1],
                             aQ[mf][2*jkp+1][2], aQ[mf][2*jkp+1][3], bq.z, bq.w);
                    }
                }
            }

            // causal mask (absolute indices)
            if (kt * 64 + 63 > qwarp) {
                int koff = kt * 64;
#pragma unroll
                for (int mf = 0; mf < 2; mf++) {
                    int r0 = qwarp + (mf << 4) + g, r1 = r0 + 8;
#pragma unroll
                    for (int nf = 0; nf < 8; nf++) {
                        int c0 = koff + nf * 8 + tig * 2, c1 = c0 + 1;
                        if (c0 > r0) sacc[mf][nf][0] = -1e30f;
                        if (c1 > r0) sacc[mf][nf][1] = -1e30f;
                        if (c0 > r1) sacc[mf][nf][2] = -1e30f;
                        if (c1 > r1) sacc[mf][nf][3] = -1e30f;
                    }
                }
            }

            // online softmax per (mf, row-half)
#pragma unroll
            for (int mf = 0; mf < 2; mf++) {
                float rm0 = -1e30f, rm1 = -1e30f;
#pragma unroll
                for (int nf = 0; nf < 8; nf++) {
                    rm0 = fmaxf(rm0, fmaxf(sacc[mf][nf][0], sacc[mf][nf][1]));
                    rm1 = fmaxf(rm1, fmaxf(sacc[mf][nf][2], sacc[mf][nf][3]));
                }
                rm0 = fmaxf(rm0, __shfl_xor_sync(0xFFFFFFFFu, rm0, 1));
                rm0 = fmaxf(rm0, __shfl_xor_sync(0xFFFFFFFFu, rm0, 2));
                rm1 = fmaxf(rm1, __shfl_xor_sync(0xFFFFFFFFu, rm1, 1));
                rm1 = fmaxf(rm1, __shfl_xor_sync(0xFFFFFFFFu, rm1, 2));
                float mn0 = fmaxf(m_[mf][0], rm0), mn1 = fmaxf(m_[mf][1], rm1);
                float al0 = __expf(m_[mf][0] - mn0), al1 = __expf(m_[mf][1] - mn1);
                float rs0 = 0.0f, rs1 = 0.0f;
#pragma unroll
                for (int nf = 0; nf < 8; nf++) {
                    sacc[mf][nf][0] = __expf(sacc[mf][nf][0] - mn0);
                    sacc[mf][nf][1] = __expf(sacc[mf][nf][1] - mn0);
                    sacc[mf][nf][2] = __expf(sacc[mf][nf][2] - mn1);
                    sacc[mf][nf][3] = __expf(sacc[mf][nf][3] - mn1);
                    rs0 += sacc[mf][nf][0] + sacc[mf][nf][1];
                    rs1 += sacc[mf][nf][2] + sacc[mf][nf][3];
                }
                rs0 += __shfl_xor_sync(0xFFFFFFFFu, rs0, 1);
                rs0 += __shfl_xor_sync(0xFFFFFFFFu, rs0, 2);
                rs1 += __shfl_xor_sync(0xFFFFFFFFu, rs1, 1);
                rs1 += __shfl_xor_sync(0xFFFFFFFFu, rs1, 2);
                l_[mf][0] = l_[mf][0] * al0 + rs0;
                l_[mf][1] = l_[mf][1] * al1 + rs1;
                m_[mf][0] = mn0; m_[mf][1] = mn1;
#pragma unroll
                for (int nf = 0; nf < 8; nf++) {
                    accO[mf][nf][0] *= al0; accO[mf][nf][1] *= al0;
                    accO[mf][nf][2] *= al1; accO[mf][nf][3] *= al1;
                }
            }

            // write P into QP rows [wrow, wrow+32) (warp-private), pre-rounded
#pragma unroll
            for (int mf = 0; mf < 2; mf++) {
                int rb = wrow + (mf << 4);
#pragma unroll
                for (int nf = 0; nf < 8; nf++) {
                    int c = nf * 8 + tig * 2;
                    float2 p0, p1;
                    p0.x = to_tf32(sacc[mf][nf][0]);
                    p0.y = to_tf32(sacc[mf][nf][1]);
                    p1.x = to_tf32(sacc[mf][nf][2]);
                    p1.y = to_tf32(sacc[mf][nf][3]);
                    *(float2*)&QP[(rb + g    ) * QSTC + c] = p0;
                    *(float2*)&QP[(rb + g + 8) * QSTC + c] = p1;
                }
            }
            __syncwarp();

            // GEMM2: O += P @ V, V4 quads shared across both m-frags
#pragma unroll
            for (int jkp = 0; jkp < 4; jkp++) {
                int k0c = (2*jkp) * 8, k1c = (2*jkp+1) * 8;
                float p[2][8];
#pragma unroll
                for (int mf = 0; mf < 2; mf++) {
                    int rb = wrow + (mf << 4);
                    p[mf][0] = QP[(rb + g    ) * QSTC + k0c + tig];
                    p[mf][1] = QP[(rb + g + 8) * QSTC + k0c + tig];
                    p[mf][2] = QP[(rb + g    ) * QSTC + k0c + tig + 4];
                    p[mf][3] = QP[(rb + g + 8) * QSTC + k0c + tig + 4];
                    p[mf][4] = QP[(rb + g    ) * QSTC + k1c + tig];
                    p[mf][5] = QP[(rb + g + 8) * QSTC + k1c + tig];
                    p[mf][6] = QP[(rb + g    ) * QSTC + k1c + tig + 4];
                    p[mf][7] = QP[(rb + g + 8) * QSTC + k1c + tig + 4];
                }
#pragma unroll
                for (int nf = 0; nf < 8; nf++) {
                    float4 bq = *(const float4*)&Vc[((nf * 4 + jkp) * 32 + lane) * 4];
#pragma unroll
                    for (int mf = 0; mf < 2; mf++) {
                        mma8(accO[mf][nf], p[mf][0], p[mf][1], p[mf][2], p[mf][3],
                             bq.x, bq.y);
                        mma8(accO[mf][nf], p[mf][4], p[mf][5], p[mf][6], p[mf][7],
                             bq.z, bq.w);
                    }
                }
            }
        }
    }

    // epilogue: normalize + round into QP, then coalesced A2 write of g_ctx
#pragma unroll
    for (int mf = 0; mf < 2; mf++) {
        float inv0 = 1.0f / l_[mf][0], inv1 = 1.0f / l_[mf][1];
        int rb = wrow + (mf << 4);
#pragma unroll
        for (int nf = 0; nf < 8; nf++) {
            int c = nf * 8 + tig * 2;
            float2 p0, p1;
            p0.x = to_tf32(accO[mf][nf][0] * inv0);
            p0.y = to_tf32(accO[mf][nf][1] * inv0);
            p1.x = to_tf32(accO[mf][nf][2] * inv1);
            p1.y = to_tf32(accO[mf][nf][3] * inv1);
            *(float2*)&QP[(rb + g    ) * QSTC + c] = p0;
            *(float2*)&QP[(rb + g + 8) * QSTC + c] = p1;
        }
    }
    __syncthreads();
    {
        const int b = bh >> 4;
        const int h = bh & 15;
        const int jm0 = b * 128 + bxr * 8;
#pragma unroll
        for (int i = 0; i < 16; i++) {
            int f = i * 128 + tid;            // 2048 quads
            int jm_l = f >> 8;
            int rem = f & 255;
            int jk_l = rem >> 5;
            int ln = rem & 31;
            int gg = ln >> 2, tt = ln & 3;
            int rb = jm_l * 16 + gg;
            int cb = jk_l * 8 + tt;
            float4 o;
            o.x = QP[rb * QSTC + cb];
            o.y = QP[(rb + 8) * QSTC + cb];
            o.z = QP[rb * QSTC + cb + 4];
            o.w = QP[(rb + 8) * QSTC + cb + 4];
            size_t f4 = (((size_t)(jm0 + jm_l)) * 128 + h * 8 + jk_l) * 32 + ln;
            *(float4*)(g_ctx + f4 * 4) = o;
        }
    }
}

// ---------------------------------------------------------------------------
extern "C" void kernel_launch(void* const* d_in, const int* in_sizes, int n_in,
                              void* d_out, int out_size)
{
    const float* q   = (const float*)d_in[0];
    const float* k   = (const float*)d_in[1];
    const float* v   = (const float*)d_in[2];
    // d_in[3] = mask (causal tril) — computed analytically in-kernel
    const float* w_q = (const float*)d_in[4];
    const float* w_k = (const float*)d_in[5];
    const float* w_v = (const float*)d_in[6];
    const float* w_o = (const float*)d_in[7];

    float* out  = (float*)d_out;
    float* keyh = out + OUT_PLANE;
    float* valh = out + 2 * (size_t)OUT_PLANE;

    static bool configured = false;
    if (!configured) {
        cudaFuncSetAttribute(gemm_qkv, cudaFuncAttributeMaxDynamicSharedMemorySize,
                             GEMM_SMEM);
        cudaFuncSetAttribute(gemm_out_k, cudaFuncAttributeMaxDynamicSharedMemorySize,
                             GEMM_SMEM);
        cudaFuncSetAttribute(attn_tc, cudaFuncAttributeMaxDynamicSharedMemorySize,
                             ATT_SMEM);
        configured = true;
    }

    dim3 wgrid(16, 8, 4);
    round_w_k<<<wgrid, 256>>>(w_q, w_k, w_v, w_o);

    dim3 pgrid(MM / 16, 2, 3);             // (512, 2, 3)
    permute_in_k<<<pgrid, 256>>>(q, k, v);

    dim3 qkvgrid(DD / 128, MM / 128, 3);   // (8, 64, 3)
    gemm_qkv<<<qkvgrid, 256, GEMM_SMEM>>>(keyh, valh);

    dim3 agrid(SS / 128, BB * HH);         // (16, 64)
    attn_tc<<<agrid, 128, ATT_SMEM>>>();

    dim3 ogrid(DD / 128, MM / 128, 1);     // (8, 64)
    gemm_out_k<<<ogrid, 256, GEMM_SMEM>>>(out);
}

// round 12
// speedup vs baseline: 3.6795x; 1.7173x over previous
#include <cuda_runtime.h>
#include <cuda_fp16.h>
#include <cstdint>

// Problem constants
#define BB 4
#define SS 2048
#define DD 1024
#define HH 16
#define DKK 64
#define MM (BB*SS)            // 8192
#define OUT_PLANE (BB*SS*DD)  // 8388608
#define HPLANE (BB*HH*SS*DKK) // 8388608

// Scratch (allocation-free rule: __device__ globals), all fp16 fragment layouts
__device__ __half g_Qh[HPLANE];        // Q proj, A-frag quads, *0.125
__device__ __half g_rKh[HPLANE];       // K proj, B-frag pairs (GEMM1)
__device__ __half g_rVh[HPLANE];       // V proj, B-frag pairs (GEMM2)
__device__ __half g_ctx[BB*SS*DD];     // attention context, A-frag quads
__device__ __half g_rw[4*DD*DD];       // weights, B-frag pairs
__device__ __half g_pA[3*(size_t)MM*DD]; // q,k,v inputs, A-frag quads

// fp16 m16n8k16 fragment layouts, g=lane>>2, t=lane&3:
//  A quad (jm=m/16, jk16=k/16, lane): uint4 {a0,a1,a2,a3}:
//    a0={A[16jm+g][16jk16+2t],[+1]}, a1=row+8 same, a2=cols+8,+9, a3=row+8 cols+8,+9
//    uint4 idx = (jm*NJK16 + jk16)*32 + lane
//  B pair (jn=n/8, jk16, lane): uint2 {b0,b1}:
//    b0={B[16jk16+2t][8jn+g],B[16jk16+2t+1][..]}, b1=rows+8,+9
//    (for W/K stored K-major rows: b0={W[8jn+g][16jk16+2t],[+1]}, b1=cols+8,+9)

// ---------------------------------------------------------------------------
// helpers
// ---------------------------------------------------------------------------
__device__ __forceinline__ uint32_t f2h2(float lo, float hi) {
    __half2 h = __floats2half2_rn(lo, hi);
    return *reinterpret_cast<uint32_t*>(&h);
}

// D += A(16x16) * B(16x8), fp16 inputs, fp32 accum
__device__ __forceinline__ void mma16(float* c, uint32_t a0, uint32_t a1,
                                      uint32_t a2, uint32_t a3,
                                      uint32_t b0, uint32_t b1) {
    asm volatile(
        "mma.sync.aligned.m16n8k16.row.col.f32.f16.f16.f32 "
        "{%0,%1,%2,%3}, {%4,%5,%6,%7}, {%8,%9}, {%0,%1,%2,%3};\n"
        : "+f"(c[0]), "+f"(c[1]), "+f"(c[2]), "+f"(c[3])
        : "r"(a0), "r"(a1), "r"(a2), "r"(a3), "r"(b0), "r"(b1));
}

__device__ __forceinline__ uint32_t smem_u32(const void* p) {
    uint32_t a;
    asm("{ .reg .u64 t; cvta.to.shared.u64 t, %1; cvt.u32.u64 %0, t; }"
        : "=r"(a) : "l"(p));
    return a;
}

__device__ __forceinline__ void cp16(uint32_t saddr, const void* gptr) {
    asm volatile("cp.async.cg.shared.global [%0], [%1], 16;"
                 :: "r"(saddr), "l"(gptr));
}
#define CP_COMMIT() asm volatile("cp.async.commit_group;" ::: "memory")
#define CP_WAIT(n)  asm volatile("cp.async.wait_group %0;" :: "n"(n) : "memory")

// ---------------------------------------------------------------------------
// weight permute to fp16 B-frag pairs (4 planes). grid (16, 8, 4)
// block tile: 64 n-rows (8 jn) x 128 k (8 jk16)
// ---------------------------------------------------------------------------
__global__ __launch_bounds__(256) void round_w_k(const float* __restrict__ wq,
                                                 const float* __restrict__ wk,
                                                 const float* __restrict__ wv,
                                                 const float* __restrict__ wo)
{
    __shared__ float SW[64][132];
    const int jnT = blockIdx.x;
    const int jkT = blockIdx.y;
    const int z   = blockIdx.z;
    const float* src = (z == 0) ? wq : (z == 1) ? wk : (z == 2) ? wv : wo;
    uint2* dst = (uint2*)(g_rw + (size_t)z * DD * DD);
    const int t = threadIdx.x;
#pragma unroll
    for (int i = 0; i < 8; i++) {
        int f = i * 256 + t;
        int r = f >> 5, c4 = f & 31;
        float4 vv = *(const float4*)(src + (size_t)(jnT * 64 + r) * DD
                                         + jkT * 128 + c4 * 4);
        *(float4*)&SW[r][c4 * 4] = vv;
    }
    __syncthreads();
#pragma unroll
    for (int i = 0; i < 8; i++) {
        int f = i * 256 + t;            // 2048 uint2
        int ln = f & 31, q = f >> 5;    // q 0..63
        int jk_l = q & 7, jn_l = q >> 3;
        int g2 = ln >> 2, t2 = ln & 3;
        int r = jn_l * 8 + g2, c = jk_l * 16 + 2 * t2;
        uint2 o;
        o.x = f2h2(SW[r][c],     SW[r][c + 1]);
        o.y = f2h2(SW[r][c + 8], SW[r][c + 9]);
        size_t idx = ((size_t)(jnT * 8 + jn_l) * 64 + jkT * 8 + jk_l) * 32 + ln;
        dst[idx] = o;
    }
}

// ---------------------------------------------------------------------------
// input permute to fp16 A-frag quads (q,k,v planes). grid (512, 2, 3)
// ---------------------------------------------------------------------------
__global__ __launch_bounds__(256) void permute_in_k(const float* __restrict__ q,
                                                    const float* __restrict__ k,
                                                    const float* __restrict__ v)
{
    __shared__ float SP[16][516];
    const int jm = blockIdx.x;
    const int ch = blockIdx.y;
    const int z  = blockIdx.z;
    const float* src = (z == 0) ? q : (z == 1) ? k : v;
    uint4* dst = (uint4*)(g_pA + (size_t)z * MM * DD);
    const int t = threadIdx.x;
#pragma unroll
    for (int i = 0; i < 8; i++) {
        int f = i * 256 + t;
        int r = f >> 7, c4 = f & 127;
        float4 vv = *(const float4*)(src + (size_t)(jm * 16 + r) * DD
                                         + ch * 512 + c4 * 4);
        *(float4*)&SP[r][c4 * 4] = vv;
    }
    __syncthreads();
#pragma unroll
    for (int i = 0; i < 4; i++) {
        int f = i * 256 + t;            // 1024 uint4
        int ln = f & 31, jk_l = f >> 5; // jk_l 0..31
        int g = ln >> 2, t2 = ln & 3;
        int c = jk_l * 16 + 2 * t2;
        uint4 o;
        o.x = f2h2(SP[g    ][c],     SP[g    ][c + 1]);
        o.y = f2h2(SP[g + 8][c],     SP[g + 8][c + 1]);
        o.z = f2h2(SP[g    ][c + 8], SP[g    ][c + 9]);
        o.w = f2h2(SP[g + 8][c + 8], SP[g + 8][c + 9]);
        size_t idx = ((size_t)jm * 64 + ch * 32 + jk_l) * 32 + ln;
        dst[idx] = o;
    }
}

// ---------------------------------------------------------------------------
// FP16 GEMM on fragment-major operands, BK=32 (2 k16), 3-stage cp.async.
// Block tile 128x128, 256 thr = 8 warps (4M x 2N), warp = 32x64.
// smem: 3 stages x (A 8KB + B 8KB) = 48KB; epilogue staging 67.5KB (fp32).
// MODE: 0 flat fp32; 1 Q frags (*0.125); 2 K (fp32 out + K-frags);
//       3 V (fp32 out + V-frags).
// ---------------------------------------------------------------------------
#define GEMM_SMEM 67584

template<int MODE>
__device__ __forceinline__ void gemm_body(const __half* __restrict__ A2h,
                                          const __half* __restrict__ W2h,
                                          float* __restrict__ out_full)
{
    extern __shared__ float dsm[];
    const uint32_t sA = smem_u32(dsm);            // 3 x 8KB A stages
    const uint32_t sB = sA + 3 * 8192;            // 3 x 8KB B stages

    const int tid  = threadIdx.x;
    const int lane = tid & 31;
    const int w    = tid >> 5;
    const int g    = lane >> 2;
    const int tg   = lane & 3;
    const int wm   = w & 3;
    const int wn   = w >> 2;

    const int m0  = blockIdx.y << 7;
    const int n0  = blockIdx.x << 7;
    const int jm0 = blockIdx.y * 8;
    const int jn0 = blockIdx.x * 16;

    // loaders: A: 8 groups of 32 (one jm each); B: flat 512x16B per chunk
    const int ajm = tid >> 5, ati = tid & 31;
    const uint4* Ag = (const uint4*)A2h + (size_t)(jm0 + ajm) * 2048;
    const __half* Bg = W2h;   // indexed per f below

#pragma unroll
    for (int c = 0; c < 3; c++) {
#pragma unroll
        for (int i = 0; i < 2; i++) {
            int q = ati + i * 32;
            cp16(sA + (uint32_t)(c * 8192 + (ajm * 64 + q) * 16), Ag + c * 64 + q);
            int f = tid + i * 256;
            int jn_l = f >> 5, rem = f & 31;
            cp16(sB + (uint32_t)(c * 8192 + f * 16),
                 Bg + ((size_t)(jn0 + jn_l) * 2048 + c * 64 + rem * 2) * 4);
        }
        CP_COMMIT();
    }

    float acc[2][8][4];
#pragma unroll
    for (int mf = 0; mf < 2; mf++)
#pragma unroll
        for (int nf = 0; nf < 8; nf++)
#pragma unroll
            for (int r = 0; r < 4; r++) acc[mf][nf][r] = 0.0f;

    int s_cur = 0;
    for (int t = 0; t < 32; t++) {
        if (t < 31) { CP_WAIT(1); } else { CP_WAIT(0); }
        __syncthreads();
        if (t >= 1 && t + 2 < 32) {
            int st = (t + 2) % 3;
#pragma unroll
            for (int i = 0; i < 2; i++) {
                int q = ati + i * 32;
                cp16(sA + (uint32_t)(st * 8192 + (ajm * 64 + q) * 16),
                     Ag + (t + 2) * 64 + q);
                int f = tid + i * 256;
                int jn_l = f >> 5, rem = f & 31;
                cp16(sB + (uint32_t)(st * 8192 + f * 16),
                     Bg + ((size_t)(jn0 + jn_l) * 2048 + (t + 2) * 64 + rem * 2) * 4);
            }
            CP_COMMIT();
        }
        const uint4* as4 = (const uint4*)((const char*)dsm + s_cur * 8192);
        const uint2* bs2 = (const uint2*)((const char*)dsm + 3 * 8192 + s_cur * 8192);
#pragma unroll
        for (int ks = 0; ks < 2; ks++) {
            uint4 a0 = as4[(wm * 2 + 0) * 64 + ks * 32 + lane];
            uint4 a1 = as4[(wm * 2 + 1) * 64 + ks * 32 + lane];
#pragma unroll
            for (int nf = 0; nf < 8; nf++) {
                uint2 b = bs2[(wn * 8 + nf) * 64 + ks * 32 + lane];
                mma16(acc[0][nf], a0.x, a0.y, a0.z, a0.w, b.x, b.y);
                mma16(acc[1][nf], a1.x, a1.y, a1.z, a1.w, b.x, b.y);
            }
        }
        s_cur = (s_cur == 2) ? 0 : s_cur + 1;
    }

    if (MODE == 0) {
#pragma unroll
        for (int mf = 0; mf < 2; mf++) {
#pragma unroll
            for (int half = 0; half < 2; half++) {
                int m = m0 + (wm << 5) + (mf << 4) + g + half * 8;
#pragma unroll
                for (int nf = 0; nf < 8; nf++) {
                    int e = n0 + (wn << 6) + (nf << 3) + (tg << 1);
                    float2 val;
                    val.x = acc[mf][nf][half * 2 + 0];
                    val.y = acc[mf][nf][half * 2 + 1];
                    *(float2*)&out_full[(size_t)m * DD + e] = val;
                }
            }
        }
        return;
    }

    // staged epilogue: C tile -> smem fp32 [128][132]
    __syncthreads();
    float* stage = dsm;
#pragma unroll
    for (int mf = 0; mf < 2; mf++) {
#pragma unroll
        for (int half = 0; half < 2; half++) {
            int r = (wm << 5) + (mf << 4) + (half << 3) + g;
#pragma unroll
            for (int nf = 0; nf < 8; nf++) {
                int c = (wn << 6) + (nf << 3) + (tg << 1);
                float2 val;
                val.x = acc[mf][nf][half * 2 + 0];
                val.y = acc[mf][nf][half * 2 + 1];
                *(float2*)&stage[r * 132 + c] = val;
            }
        }
    }
    __syncthreads();

    const int bq = m0 >> 11;
    const int h0 = n0 >> 6;

    if (MODE == 2 || MODE == 3) {
        // full-fp32 head-layout output (reference outputs), coalesced
#pragma unroll
        for (int i = 0; i < 16; i++) {
            int f = i * 256 + tid;
            int row = f >> 5, c4 = f & 31;
            float4 v = *(const float4*)&stage[row * 132 + c4 * 4];
            int m = m0 + row;
            int s = m & 2047;
            int e = n0 + c4 * 4;
            int h = e >> 6, dk = e & 63;
            *(float4*)&out_full[((((size_t)bq * HH + h) << 11) + s) * DKK + dk] = v;
        }
    }

    if (MODE == 1) {
        const int jmb = (m0 & 2047) >> 4;
        uint4* dst = (uint4*)g_Qh;
#pragma unroll
        for (int i = 0; i < 8; i++) {
            int f = i * 256 + tid;          // 2048 quads
            int ln = f & 31, q = f >> 5;    // q 0..63
            int jk = q & 3, jm_l = (q >> 2) & 7, hs = (q >> 5) & 1;
            int g2 = ln >> 2, t2 = ln & 3;
            int r = jm_l * 16 + g2, c = hs * 64 + jk * 16 + 2 * t2;
            uint4 o;
            o.x = f2h2(stage[r * 132 + c] * 0.125f,       stage[r * 132 + c + 1] * 0.125f);
            o.y = f2h2(stage[(r + 8) * 132 + c] * 0.125f, stage[(r + 8) * 132 + c + 1] * 0.125f);
            o.z = f2h2(stage[r * 132 + c + 8] * 0.125f,   stage[r * 132 + c + 9] * 0.125f);
            o.w = f2h2(stage[(r + 8) * 132 + c + 8] * 0.125f,
                       stage[(r + 8) * 132 + c + 9] * 0.125f);
            size_t idx = (((size_t)(bq * HH + h0 + hs) * 128 + jmb + jm_l) * 4 + jk) * 32 + ln;
            dst[idx] = o;
        }
    } else if (MODE == 2) {
        const int kt0 = (m0 & 2047) >> 6;
        uint2* dst = (uint2*)g_rKh;
#pragma unroll
        for (int i = 0; i < 16; i++) {
            int f = i * 256 + tid;          // 4096 uint2
            int ln = f & 31, q = f >> 5;    // q 0..127
            int jk = q & 3, jn = (q >> 2) & 7, ktl = (q >> 5) & 1, hs = q >> 6;
            int g2 = ln >> 2, t2 = ln & 3;
            int r = ktl * 64 + jn * 8 + g2;
            int c = hs * 64 + jk * 16 + 2 * t2;
            uint2 o;
            o.x = f2h2(stage[r * 132 + c],     stage[r * 132 + c + 1]);
            o.y = f2h2(stage[r * 132 + c + 8], stage[r * 132 + c + 9]);
            size_t idx = ((size_t)(bq * HH + h0 + hs) * 32 + kt0 + ktl) * 1024
                       + (jn * 4 + jk) * 32 + ln;
            dst[idx] = o;
        }
    } else if (MODE == 3) {
        const int kt0 = (m0 & 2047) >> 6;
        uint2* dst = (uint2*)g_rVh;
#pragma unroll
        for (int i = 0; i < 16; i++) {
            int f = i * 256 + tid;
            int ln = f & 31, q = f >> 5;
            int jk = q & 3, jn = (q >> 2) & 7, ktl = (q >> 5) & 1, hs = q >> 6;
            int g2 = ln >> 2, t2 = ln & 3;
            int r = ktl * 64 + jk * 16 + 2 * t2;
            int c = hs * 64 + jn * 8 + g2;
            uint2 o;
            o.x = f2h2(stage[r * 132 + c],       stage[(r + 1) * 132 + c]);
            o.y = f2h2(stage[(r + 8) * 132 + c], stage[(r + 9) * 132 + c]);
            size_t idx = ((size_t)(bq * HH + h0 + hs) * 32 + kt0 + ktl) * 1024
                       + (jn * 4 + jk) * 32 + ln;
            dst[idx] = o;
        }
    }
}

__global__ __launch_bounds__(256, 2) void gemm_qkv(
    float* __restrict__ keyh, float* __restrict__ valh)
{
    const int z = blockIdx.z;
    const __half* A2 = g_pA + (size_t)z * MM * DD;
    const __half* W2 = g_rw + (size_t)z * DD * DD;
    if (z == 0)      gemm_body<1>(A2, W2, nullptr);
    else if (z == 1) gemm_body<2>(A2, W2, keyh);
    else             gemm_body<3>(A2, W2, valh);
}

__global__ __launch_bounds__(256, 2) void gemm_out_k(float* __restrict__ O)
{
    gemm_body<0>(g_ctx, g_rw + (size_t)3 * DD * DD, O);
}

// ---------------------------------------------------------------------------
// FP16 causal flash attention. Grid: (S/128, B*H). Block: 128 thr (4 warps).
// Warp owns 32 query rows (2 m-frags). P and ctx conversions are
// register-local (c-frag == a-frag layout for f16 k16). smem: K/V double
// buffers only, 4 x 8KB = 32KB.
// ---------------------------------------------------------------------------
#define ATT_SMEM (4 * 8192)

__global__ __launch_bounds__(128, 2) void attn_tc()
{
    extern __shared__ float sm[];
    const uint32_t uKb = smem_u32(sm);          // 2 x 8KB K
    const uint32_t uVb = uKb + 2 * 8192;        // 2 x 8KB V

    const int tid  = threadIdx.x;
    const int lane = tid & 31;
    const int w    = tid >> 5;          // 0..3
    const int g    = lane >> 2;
    const int tg   = lane & 3;
    const int wrow = w << 5;
    const int bxr  = gridDim.x - 1 - blockIdx.x;   // heavy blocks first
    const int bh   = blockIdx.y;

    const int qwarp = bxr * 128 + wrow;

    const __half* Ktiles = g_rKh + (size_t)bh * 32 * 4096;
    const __half* Vtiles = g_rVh + (size_t)bh * 32 * 4096;

    // prefetch tile 0 into buffer 0 (512 x 16B each)
#pragma unroll
    for (int u = 0; u < 4; u++) {
        int f = u * 128 + tid;
        cp16(uKb + (uint32_t)f * 16, Ktiles + f * 8);
        cp16(uVb + (uint32_t)f * 16, Vtiles + f * 8);
    }
    CP_COMMIT();

    // Q a-fragments straight from global (pre-scaled, fp16)
    uint4 aQ[2][4];
#pragma unroll
    for (int mf = 0; mf < 2; mf++) {
        const uint4* Qf = (const uint4*)g_Qh
                        + ((size_t)bh * 128 + bxr * 8 + w * 2 + mf) * 128;
#pragma unroll
        for (int jk = 0; jk < 4; jk++)
            aQ[mf][jk] = Qf[jk * 32 + lane];
    }

    float accO[2][8][4];
#pragma unroll
    for (int mf = 0; mf < 2; mf++)
#pragma unroll
        for (int nf = 0; nf < 8; nf++)
#pragma unroll
            for (int r = 0; r < 4; r++) accO[mf][nf][r] = 0.0f;
    float m_[2][2] = {{-1e30f, -1e30f}, {-1e30f, -1e30f}};
    float l_[2][2] = {{0.0f, 0.0f}, {0.0f, 0.0f}};

    const int ktmax = 2 * bxr + 1;
    for (int kt = 0; kt <= ktmax; kt++) {
        __syncthreads();

        if (kt + 1 <= ktmax) {
            const int bsel = (kt + 1) & 1;
            const __half* Kn = Ktiles + (size_t)(kt + 1) * 4096;
            const __half* Vn = Vtiles + (size_t)(kt + 1) * 4096;
#pragma unroll
            for (int u = 0; u < 4; u++) {
                int f = u * 128 + tid;
                cp16(uKb + (uint32_t)(bsel * 8192 + f * 16), Kn + f * 8);
                cp16(uVb + (uint32_t)(bsel * 8192 + f * 16), Vn + f * 8);
            }
            CP_COMMIT();
            CP_WAIT(1);
        } else {
            CP_WAIT(0);
        }
        __syncthreads();

        const uint2* Kc = (const uint2*)((const char*)sm + (kt & 1) * 8192);
        const uint2* Vc = (const uint2*)((const char*)sm + 2 * 8192 + (kt & 1) * 8192);

        const bool skip = (kt * 64) > (qwarp + 31);

        if (!skip) {
            float sacc[2][8][4];
#pragma unroll
            for (int mf = 0; mf < 2; mf++)
#pragma unroll
                for (int nf = 0; nf < 8; nf++)
#pragma unroll
                    for (int r = 0; r < 4; r++) sacc[mf][nf][r] = 0.0f;

            // GEMM1: S = Q @ K^T
#pragma unroll
            for (int jk = 0; jk < 4; jk++) {
#pragma unroll
                for (int nf = 0; nf < 8; nf++) {
                    uint2 b = Kc[(nf * 4 + jk) * 32 + lane];
                    mma16(sacc[0][nf], aQ[0][jk].x, aQ[0][jk].y, aQ[0][jk].z,
                          aQ[0][jk].w, b.x, b.y);
                    mma16(sacc[1][nf], aQ[1][jk].x, aQ[1][jk].y, aQ[1][jk].z,
                          aQ[1][jk].w, b.x, b.y);
                }
            }

            // causal mask (absolute indices)
            if (kt * 64 + 63 > qwarp) {
                int koff = kt * 64;
#pragma unroll
                for (int mf = 0; mf < 2; mf++) {
                    int r0 = qwarp + (mf << 4) + g, r1 = r0 + 8;
#pragma unroll
                    for (int nf = 0; nf < 8; nf++) {
                        int c0 = koff + nf * 8 + tg * 2, c1 = c0 + 1;
                        if (c0 > r0) sacc[mf][nf][0] = -1e30f;
                        if (c1 > r0) sacc[mf][nf][1] = -1e30f;
                        if (c0 > r1) sacc[mf][nf][2] = -1e30f;
                        if (c1 > r1) sacc[mf][nf][3] = -1e30f;
                    }
                }
            }

            // online softmax per (mf, row-half)
#pragma unroll
            for (int mf = 0; mf < 2; mf++) {
                float rm0 = -1e30f, rm1 = -1e30f;
#pragma unroll
                for (int nf = 0; nf < 8; nf++) {
                    rm0 = fmaxf(rm0, fmaxf(sacc[mf][nf][0], sacc[mf][nf][1]));
                    rm1 = fmaxf(rm1, fmaxf(sacc[mf][nf][2], sacc[mf][nf][3]));
                }
                rm0 = fmaxf(rm0, __shfl_xor_sync(0xFFFFFFFFu, rm0, 1));
                rm0 = fmaxf(rm0, __shfl_xor_sync(0xFFFFFFFFu, rm0, 2));
                rm1 = fmaxf(rm1, __shfl_xor_sync(0xFFFFFFFFu, rm1, 1));
                rm1 = fmaxf(rm1, __shfl_xor_sync(0xFFFFFFFFu, rm1, 2));
                float mn0 = fmaxf(m_[mf][0], rm0), mn1 = fmaxf(m_[mf][1], rm1);
                float al0 = __expf(m_[mf][0] - mn0), al1 = __expf(m_[mf][1] - mn1);
                float rs0 = 0.0f, rs1 = 0.0f;
#pragma unroll
                for (int nf = 0; nf < 8; nf++) {
                    sacc[mf][nf][0] = __expf(sacc[mf][nf][0] - mn0);
                    sacc[mf][nf][1] = __expf(sacc[mf][nf][1] - mn0);
                    sacc[mf][nf][2] = __expf(sacc[mf][nf][2] - mn1);
                    sacc[mf][nf][3] = __expf(sacc[mf][nf][3] - mn1);
                    rs0 += sacc[mf][nf][0] + sacc[mf][nf][1];
                    rs1 += sacc[mf][nf][2] + sacc[mf][nf][3];
                }
                rs0 += __shfl_xor_sync(0xFFFFFFFFu, rs0, 1);
                rs0 += __shfl_xor_sync(0xFFFFFFFFu, rs0, 2);
                rs1 += __shfl_xor_sync(0xFFFFFFFFu, rs1, 1);
                rs1 += __shfl_xor_sync(0xFFFFFFFFu, rs1, 2);
                l_[mf][0] = l_[mf][0] * al0 + rs0;
                l_[mf][1] = l_[mf][1] * al1 + rs1;
                m_[mf][0] = mn0; m_[mf][1] = mn1;
#pragma unroll
                for (int nf = 0; nf < 8; nf++) {
                    accO[mf][nf][0] *= al0; accO[mf][nf][1] *= al0;
                    accO[mf][nf][2] *= al1; accO[mf][nf][3] *= al1;
                }
            }

            // GEMM2: O += P @ V. P a-frags are register-local repacks of sacc.
#pragma unroll
            for (int jk = 0; jk < 4; jk++) {
                uint32_t pa[2][4];
#pragma unroll
                for (int mf = 0; mf < 2; mf++) {
                    pa[mf][0] = f2h2(sacc[mf][2*jk  ][0], sacc[mf][2*jk  ][1]);
                    pa[mf][1] = f2h2(sacc[mf][2*jk  ][2], sacc[mf][2*jk  ][3]);
                    pa[mf][2] = f2h2(sacc[mf][2*jk+1][0], sacc[mf][2*jk+1][1]);
                    pa[mf][3] = f2h2(sacc[mf][2*jk+1][2], sacc[mf][2*jk+1][3]);
                }
#pragma unroll
                for (int nf = 0; nf < 8; nf++) {
                    uint2 b = Vc[(nf * 4 + jk) * 32 + lane];
                    mma16(accO[0][nf], pa[0][0], pa[0][1], pa[0][2], pa[0][3],
                          b.x, b.y);
                    mma16(accO[1][nf], pa[1][0], pa[1][1], pa[1][2], pa[1][3],
                          b.x, b.y);
                }
            }
        }
    }

    // epilogue: normalize, register-local repack to A-frag quads, direct STG
    {
        const int b = bh >> 4;
        const int h = bh & 15;
        uint4* ctx4 = (uint4*)g_ctx;
#pragma unroll
        for (int mf = 0; mf < 2; mf++) {
            float inv0 = 1.0f / l_[mf][0], inv1 = 1.0f / l_[mf][1];
            size_t jm = (size_t)b * 128 + bxr * 8 + w * 2 + mf;
#pragma unroll
            for (int jk = 0; jk < 4; jk++) {
                uint4 o;
                o.x = f2h2(accO[mf][2*jk  ][0] * inv0, accO[mf][2*jk  ][1] * inv0);
                o.y = f2h2(accO[mf][2*jk  ][2] * inv1, accO[mf][2*jk  ][3] * inv1);
                o.z = f2h2(accO[mf][2*jk+1][0] * inv0, accO[mf][2*jk+1][1] * inv0);
                o.w = f2h2(accO[mf][2*jk+1][2] * inv1, accO[mf][2*jk+1][3] * inv1);
                ctx4[(jm * 64 + h * 4 + jk) * 32 + lane] = o;
            }
        }
    }
}

// ---------------------------------------------------------------------------
extern "C" void kernel_launch(void* const* d_in, const int* in_sizes, int n_in,
                              void* d_out, int out_size)
{
    const float* q   = (const float*)d_in[0];
    const float* k   = (const float*)d_in[1];
    const float* v   = (const float*)d_in[2];
    // d_in[3] = mask (causal tril) — computed analytically in-kernel
    const float* w_q = (const float*)d_in[4];
    const float* w_k = (const float*)d_in[5];
    const float* w_v = (const float*)d_in[6];
    const float* w_o = (const float*)d_in[7];

    float* out  = (float*)d_out;
    float* keyh = out + OUT_PLANE;
    float* valh = out + 2 * (size_t)OUT_PLANE;

    static bool configured = false;
    if (!configured) {
        cudaFuncSetAttribute(gemm_qkv, cudaFuncAttributeMaxDynamicSharedMemorySize,
                             GEMM_SMEM);
        cudaFuncSetAttribute(gemm_out_k, cudaFuncAttributeMaxDynamicSharedMemorySize,
                             GEMM_SMEM);
        cudaFuncSetAttribute(attn_tc, cudaFuncAttributeMaxDynamicSharedMemorySize,
                             ATT_SMEM);
        configured = true;
    }

    dim3 wgrid(16, 8, 4);
    round_w_k<<<wgrid, 256>>>(w_q, w_k, w_v, w_o);

    dim3 pgrid(MM / 16, 2, 3);             // (512, 2, 3)
    permute_in_k<<<pgrid, 256>>>(q, k, v);

    dim3 qkvgrid(DD / 128, MM / 128, 3);   // (8, 64, 3)
    gemm_qkv<<<qkvgrid, 256, GEMM_SMEM>>>(keyh, valh);

    dim3 agrid(SS / 128, BB * HH);         // (16, 64)
    attn_tc<<<agrid, 128, ATT_SMEM>>>();

    dim3 ogrid(DD / 128, MM / 128, 1);     // (8, 64)
    gemm_out_k<<<ogrid, 256, GEMM_SMEM>>>(out);
}

// round 13
// speedup vs baseline: 3.8179x; 1.0376x over previous
#include <cuda_runtime.h>
#include <cuda_fp16.h>
#include <cstdint>

// Problem constants
#define BB 4
#define SS 2048
#define DD 1024
#define HH 16
#define DKK 64
#define MM (BB*SS)            // 8192
#define OUT_PLANE (BB*SS*DD)  // 8388608
#define HPLANE (BB*HH*SS*DKK) // 8388608

// Q pre-scale: (1/sqrt(64)) * log2(e)  -> softmax runs in exp2 domain
#define QSCALE 0.18033688011112042f

// Scratch (allocation-free rule: __device__ globals), all fp16 fragment layouts
__device__ __half g_Qh[HPLANE];        // Q proj, A-frag quads, *QSCALE
__device__ __half g_rKh[HPLANE];       // K proj, B-frag pairs (GEMM1)
__device__ __half g_rVh[HPLANE];       // V proj, B-frag pairs (GEMM2)
__device__ __half g_ctx[BB*SS*DD];     // attention context, A-frag quads
__device__ __half g_rw[4*DD*DD];       // weights, B-frag pairs
__device__ __half g_pA[3*(size_t)MM*DD]; // q,k,v inputs, A-frag quads

// fp16 m16n8k16 fragment layouts, g=lane>>2, t=lane&3:
//  A quad (jm=m/16, jk16=k/16, lane): uint4 {a0,a1,a2,a3}:
//    a0={A[16jm+g][16jk16+2t],[+1]}, a1=row+8, a2=cols+8,+9, a3=row+8 cols+8,+9
//  B pair (jn=n/8, jk16, lane): uint2 {b0,b1} per layout comments in emitters.

// ---------------------------------------------------------------------------
// helpers
// ---------------------------------------------------------------------------
__device__ __forceinline__ uint32_t f2h2(float lo, float hi) {
    __half2 h = __floats2half2_rn(lo, hi);
    return *reinterpret_cast<uint32_t*>(&h);
}

__device__ __forceinline__ float ex2(float x) {
    float r;
    asm("ex2.approx.f32 %0, %1;" : "=f"(r) : "f"(x));
    return r;
}

// D += A(16x16) * B(16x8), fp16 inputs, fp32 accum
__device__ __forceinline__ void mma16(float* c, uint32_t a0, uint32_t a1,
                                      uint32_t a2, uint32_t a3,
                                      uint32_t b0, uint32_t b1) {
    asm volatile(
        "mma.sync.aligned.m16n8k16.row.col.f32.f16.f16.f32 "
        "{%0,%1,%2,%3}, {%4,%5,%6,%7}, {%8,%9}, {%0,%1,%2,%3};\n"
        : "+f"(c[0]), "+f"(c[1]), "+f"(c[2]), "+f"(c[3])
        : "r"(a0), "r"(a1), "r"(a2), "r"(a3), "r"(b0), "r"(b1));
}

__device__ __forceinline__ uint32_t smem_u32(const void* p) {
    uint32_t a;
    asm("{ .reg .u64 t; cvta.to.shared.u64 t, %1; cvt.u32.u64 %0, t; }"
        : "=r"(a) : "l"(p));
    return a;
}

__device__ __forceinline__ void cp16(uint32_t saddr, const void* gptr) {
    asm volatile("cp.async.cg.shared.global [%0], [%1], 16;"
                 :: "r"(saddr), "l"(gptr));
}
#define CP_COMMIT() asm volatile("cp.async.commit_group;" ::: "memory")
#define CP_WAIT(n)  asm volatile("cp.async.wait_group %0;" :: "n"(n) : "memory")

// ---------------------------------------------------------------------------
// fused prologue: weight permute (blocks 0..511) + input permute (512..3583)
// 1-D grid of 3584 blocks x 256 threads.
// ---------------------------------------------------------------------------
__global__ __launch_bounds__(256) void prep_k(const float* __restrict__ q,
                                              const float* __restrict__ k,
                                              const float* __restrict__ v,
                                              const float* __restrict__ wq,
                                              const float* __restrict__ wk,
                                              const float* __restrict__ wv,
                                              const float* __restrict__ wo)
{
    __shared__ float S[64 * 132];   // weight view [64][132]; input view [16][516]
    const int b = blockIdx.x;
    const int t = threadIdx.x;

    if (b < 512) {
        // ---- weight permute to fp16 B-frag pairs ----
        const int jnT = b & 15;
        const int jkT = (b >> 4) & 7;
        const int z   = b >> 7;
        const float* src = (z == 0) ? wq : (z == 1) ? wk : (z == 2) ? wv : wo;
        uint2* dst = (uint2*)(g_rw + (size_t)z * DD * DD);
#pragma unroll
        for (int i = 0; i < 8; i++) {
            int f = i * 256 + t;
            int r = f >> 5, c4 = f & 31;
            float4 vv = *(const float4*)(src + (size_t)(jnT * 64 + r) * DD
                                             + jkT * 128 + c4 * 4);
            *(float4*)&S[r * 132 + c4 * 4] = vv;
        }
        __syncthreads();
#pragma unroll
        for (int i = 0; i < 8; i++) {
            int f = i * 256 + t;
            int ln = f & 31, qq = f >> 5;
            int jk_l = qq & 7, jn_l = qq >> 3;
            int g2 = ln >> 2, t2 = ln & 3;
            int r = jn_l * 8 + g2, c = jk_l * 16 + 2 * t2;
            uint2 o;
            o.x = f2h2(S[r * 132 + c],     S[r * 132 + c + 1]);
            o.y = f2h2(S[r * 132 + c + 8], S[r * 132 + c + 9]);
            size_t idx = ((size_t)(jnT * 8 + jn_l) * 64 + jkT * 8 + jk_l) * 32 + ln;
            dst[idx] = o;
        }
    } else {
        // ---- input permute to fp16 A-frag quads ----
        const int idx0 = b - 512;
        const int jm = idx0 & 511;
        const int ch = (idx0 >> 9) & 1;
        const int z  = idx0 >> 10;
        const float* src = (z == 0) ? q : (z == 1) ? k : v;
        uint4* dst = (uint4*)(g_pA + (size_t)z * MM * DD);
#pragma unroll
        for (int i = 0; i < 8; i++) {
            int f = i * 256 + t;
            int r = f >> 7, c4 = f & 127;
            float4 vv = *(const float4*)(src + (size_t)(jm * 16 + r) * DD
                                             + ch * 512 + c4 * 4);
            *(float4*)&S[r * 516 + c4 * 4] = vv;
        }
        __syncthreads();
#pragma unroll
        for (int i = 0; i < 4; i++) {
            int f = i * 256 + t;
            int ln = f & 31, jk_l = f >> 5;
            int g = ln >> 2, t2 = ln & 3;
            int c = jk_l * 16 + 2 * t2;
            uint4 o;
            o.x = f2h2(S[g * 516 + c],           S[g * 516 + c + 1]);
            o.y = f2h2(S[(g + 8) * 516 + c],     S[(g + 8) * 516 + c + 1]);
            o.z = f2h2(S[g * 516 + c + 8],       S[g * 516 + c + 9]);
            o.w = f2h2(S[(g + 8) * 516 + c + 8], S[(g + 8) * 516 + c + 9]);
            size_t di = ((size_t)jm * 64 + ch * 32 + jk_l) * 32 + ln;
            dst[di] = o;
        }
    }
}

// ---------------------------------------------------------------------------
// FP16 GEMM on fragment-major operands, BK=32 (2 k16), 3-stage cp.async.
// Block tile 128x128, 256 thr = 8 warps (4M x 2N), warp = 32x64.
// MODE: 0 flat fp32; 1 Q frags (*QSCALE); 2 K (fp32 out + K-frags);
//       3 V (fp32 out + V-frags).
// ---------------------------------------------------------------------------
#define GEMM_SMEM 67584

template<int MODE>
__device__ __forceinline__ void gemm_body(const __half* __restrict__ A2h,
                                          const __half* __restrict__ W2h,
                                          float* __restrict__ out_full)
{
    extern __shared__ float dsm[];
    const uint32_t sA = smem_u32(dsm);            // 3 x 8KB A stages
    const uint32_t sB = sA + 3 * 8192;            // 3 x 8KB B stages

    const int tid  = threadIdx.x;
    const int lane = tid & 31;
    const int w    = tid >> 5;
    const int g    = lane >> 2;
    const int tg   = lane & 3;
    const int wm   = w & 3;
    const int wn   = w >> 2;

    const int m0  = blockIdx.y << 7;
    const int n0  = blockIdx.x << 7;
    const int jm0 = blockIdx.y * 8;
    const int jn0 = blockIdx.x * 16;

    const int ajm = tid >> 5, ati = tid & 31;
    const uint4* Ag = (const uint4*)A2h + (size_t)(jm0 + ajm) * 2048;
    const __half* Bg = W2h;

#pragma unroll
    for (int c = 0; c < 3; c++) {
#pragma unroll
        for (int i = 0; i < 2; i++) {
            int qq = ati + i * 32;
            cp16(sA + (uint32_t)(c * 8192 + (ajm * 64 + qq) * 16), Ag + c * 64 + qq);
            int f = tid + i * 256;
            int jn_l = f >> 5, rem = f & 31;
            cp16(sB + (uint32_t)(c * 8192 + f * 16),
                 Bg + ((size_t)(jn0 + jn_l) * 2048 + c * 64 + rem * 2) * 4);
        }
        CP_COMMIT();
    }

    float acc[2][8][4];
#pragma unroll
    for (int mf = 0; mf < 2; mf++)
#pragma unroll
        for (int nf = 0; nf < 8; nf++)
#pragma unroll
            for (int r = 0; r < 4; r++) acc[mf][nf][r] = 0.0f;

    int s_cur = 0;
    for (int t = 0; t < 32; t++) {
        if (t < 31) { CP_WAIT(1); } else { CP_WAIT(0); }
        __syncthreads();
        if (t >= 1 && t + 2 < 32) {
            int st = (t + 2) % 3;
#pragma unroll
            for (int i = 0; i < 2; i++) {
                int qq = ati + i * 32;
                cp16(sA + (uint32_t)(st * 8192 + (ajm * 64 + qq) * 16),
                     Ag + (t + 2) * 64 + qq);
                int f = tid + i * 256;
                int jn_l = f >> 5, rem = f & 31;
                cp16(sB + (uint32_t)(st * 8192 + f * 16),
                     Bg + ((size_t)(jn0 + jn_l) * 2048 + (t + 2) * 64 + rem * 2) * 4);
            }
            CP_COMMIT();
        }
        const uint4* as4 = (const uint4*)((const char*)dsm + s_cur * 8192);
        const uint2* bs2 = (const uint2*)((const char*)dsm + 3 * 8192 + s_cur * 8192);
#pragma unroll
        for (int ks = 0; ks < 2; ks++) {
            uint4 a0 = as4[(wm * 2 + 0) * 64 + ks * 32 + lane];
            uint4 a1 = as4[(wm * 2 + 1) * 64 + ks * 32 + lane];
#pragma unroll
            for (int nf = 0; nf < 8; nf++) {
                uint2 b = bs2[(wn * 8 + nf) * 64 + ks * 32 + lane];
                mma16(acc[0][nf], a0.x, a0.y, a0.z, a0.w, b.x, b.y);
                mma16(acc[1][nf], a1.x, a1.y, a1.z, a1.w, b.x, b.y);
            }
        }
        s_cur = (s_cur == 2) ? 0 : s_cur + 1;
    }

    if (MODE == 0) {
#pragma unroll
        for (int mf = 0; mf < 2; mf++) {
#pragma unroll
            for (int half = 0; half < 2; half++) {
                int m = m0 + (wm << 5) + (mf << 4) + g + half * 8;
#pragma unroll
                for (int nf = 0; nf < 8; nf++) {
                    int e = n0 + (wn << 6) + (nf << 3) + (tg << 1);
                    float2 val;
                    val.x = acc[mf][nf][half * 2 + 0];
                    val.y = acc[mf][nf][half * 2 + 1];
                    *(float2*)&out_full[(size_t)m * DD + e] = val;
                }
            }
        }
        return;
    }

    // staged epilogue: C tile -> smem fp32 [128][132]
    __syncthreads();
    float* stage = dsm;
#pragma unroll
    for (int mf = 0; mf < 2; mf++) {
#pragma unroll
        for (int half = 0; half < 2; half++) {
            int r = (wm << 5) + (mf << 4) + (half << 3) + g;
#pragma unroll
            for (int nf = 0; nf < 8; nf++) {
                int c = (wn << 6) + (nf << 3) + (tg << 1);
                float2 val;
                val.x = acc[mf][nf][half * 2 + 0];
                val.y = acc[mf][nf][half * 2 + 1];
                *(float2*)&stage[r * 132 + c] = val;
            }
        }
    }
    __syncthreads();

    const int bq = m0 >> 11;
    const int h0 = n0 >> 6;

    if (MODE == 2 || MODE == 3) {
#pragma unroll
        for (int i = 0; i < 16; i++) {
            int f = i * 256 + tid;
            int row = f >> 5, c4 = f & 31;
            float4 v = *(const float4*)&stage[row * 132 + c4 * 4];
            int m = m0 + row;
            int s = m & 2047;
            int e = n0 + c4 * 4;
            int h = e >> 6, dk = e & 63;
            *(float4*)&out_full[((((size_t)bq * HH + h) << 11) + s) * DKK + dk] = v;
        }
    }

    if (MODE == 1) {
        const int jmb = (m0 & 2047) >> 4;
        uint4* dst = (uint4*)g_Qh;
#pragma unroll
        for (int i = 0; i < 8; i++) {
            int f = i * 256 + tid;
            int ln = f & 31, qq = f >> 5;
            int jk = qq & 3, jm_l = (qq >> 2) & 7, hs = (qq >> 5) & 1;
            int g2 = ln >> 2, t2 = ln & 3;
            int r = jm_l * 16 + g2, c = hs * 64 + jk * 16 + 2 * t2;
            uint4 o;
            o.x = f2h2(stage[r * 132 + c] * QSCALE,       stage[r * 132 + c + 1] * QSCALE);
            o.y = f2h2(stage[(r + 8) * 132 + c] * QSCALE, stage[(r + 8) * 132 + c + 1] * QSCALE);
            o.z = f2h2(stage[r * 132 + c + 8] * QSCALE,   stage[r * 132 + c + 9] * QSCALE);
            o.w = f2h2(stage[(r + 8) * 132 + c + 8] * QSCALE,
                       stage[(r + 8) * 132 + c + 9] * QSCALE);
            size_t idx = (((size_t)(bq * HH + h0 + hs) * 128 + jmb + jm_l) * 4 + jk) * 32 + ln;
            dst[idx] = o;
        }
    } else if (MODE == 2) {
        const int kt0 = (m0 & 2047) >> 6;
        uint2* dst = (uint2*)g_rKh;
#pragma unroll
        for (int i = 0; i < 16; i++) {
            int f = i * 256 + tid;
            int ln = f & 31, qq = f >> 5;
            int jk = qq & 3, jn = (qq >> 2) & 7, ktl = (qq >> 5) & 1, hs = qq >> 6;
            int g2 = ln >> 2, t2 = ln & 3;
            int r = ktl * 64 + jn * 8 + g2;
            int c = hs * 64 + jk * 16 + 2 * t2;
            uint2 o;
            o.x = f2h2(stage[r * 132 + c],     stage[r * 132 + c + 1]);
            o.y = f2h2(stage[r * 132 + c + 8], stage[r * 132 + c + 9]);
            size_t idx = ((size_t)(bq * HH + h0 + hs) * 32 + kt0 + ktl) * 1024
                       + (jn * 4 + jk) * 32 + ln;
            dst[idx] = o;
        }
    } else if (MODE == 3) {
        const int kt0 = (m0 & 2047) >> 6;
        uint2* dst = (uint2*)g_rVh;
#pragma unroll
        for (int i = 0; i < 16; i++) {
            int f = i * 256 + tid;
            int ln = f & 31, qq = f >> 5;
            int jk = qq & 3, jn = (qq >> 2) & 7, ktl = (qq >> 5) & 1, hs = qq >> 6;
            int g2 = ln >> 2, t2 = ln & 3;
            int r = ktl * 64 + jk * 16 + 2 * t2;
            int c = hs * 64 + jn * 8 + g2;
            uint2 o;
            o.x = f2h2(stage[r * 132 + c],       stage[(r + 1) * 132 + c]);
            o.y = f2h2(stage[(r + 8) * 132 + c], stage[(r + 9) * 132 + c]);
            size_t idx = ((size_t)(bq * HH + h0 + hs) * 32 + kt0 + ktl) * 1024
                       + (jn * 4 + jk) * 32 + ln;
            dst[idx] = o;
        }
    }
}

__global__ __launch_bounds__(256, 2) void gemm_qkv(
    float* __restrict__ keyh, float* __restrict__ valh)
{
    const int z = blockIdx.z;
    const __half* A2 = g_pA + (size_t)z * MM * DD;
    const __half* W2 = g_rw + (size_t)z * DD * DD;
    if (z == 0)      gemm_body<1>(A2, W2, nullptr);
    else if (z == 1) gemm_body<2>(A2, W2, keyh);
    else             gemm_body<3>(A2, W2, valh);
}

__global__ __launch_bounds__(256, 2) void gemm_out_k(float* __restrict__ O)
{
    gemm_body<0>(g_ctx, g_rw + (size_t)3 * DD * DD, O);
}

// ---------------------------------------------------------------------------
// FP16 causal flash attention, exp2-domain softmax, 4-stage K/V ring
// (one __syncthreads per tile). Grid: (S/128, B*H). Block: 128 thr (4 warps).
// Warp owns 32 query rows (2 m-frags). smem: 4x8KB K + 4x8KB V = 64KB.
// ---------------------------------------------------------------------------
#define ATT_SMEM (8 * 8192)

__global__ __launch_bounds__(128, 2) void attn_tc()
{
    extern __shared__ float sm[];
    const uint32_t uKb = smem_u32(sm);          // 4 x 8KB K
    const uint32_t uVb = uKb + 4 * 8192;        // 4 x 8KB V

    const int tid  = threadIdx.x;
    const int lane = tid & 31;
    const int w    = tid >> 5;          // 0..3
    const int g    = lane >> 2;
    const int tg   = lane & 3;
    const int wrow = w << 5;
    const int bxr  = gridDim.x - 1 - blockIdx.x;   // heavy blocks first
    const int bh   = blockIdx.y;

    const int qwarp = bxr * 128 + wrow;

    const __half* Ktiles = g_rKh + (size_t)bh * 32 * 4096;
    const __half* Vtiles = g_rVh + (size_t)bh * 32 * 4096;
    const int ktmax = 2 * bxr + 1;   // >= 1 always

    // prologue: prefetch tiles 0 and 1 into ring slots 0 and 1
#pragma unroll
    for (int c = 0; c < 2; c++) {
#pragma unroll
        for (int u = 0; u < 4; u++) {
            int f = u * 128 + tid;
            cp16(uKb + (uint32_t)(c * 8192 + f * 16), Ktiles + (size_t)c * 4096 + f * 8);
            cp16(uVb + (uint32_t)(c * 8192 + f * 16), Vtiles + (size_t)c * 4096 + f * 8);
        }
        CP_COMMIT();
    }

    // Q a-fragments straight from global (pre-scaled by QSCALE, fp16)
    uint4 aQ[2][4];
#pragma unroll
    for (int mf = 0; mf < 2; mf++) {
        const uint4* Qf = (const uint4*)g_Qh
                        + ((size_t)bh * 128 + bxr * 8 + w * 2 + mf) * 128;
#pragma unroll
        for (int jk = 0; jk < 4; jk++)
            aQ[mf][jk] = Qf[jk * 32 + lane];
    }

    float accO[2][8][4];
#pragma unroll
    for (int mf = 0; mf < 2; mf++)
#pragma unroll
        for (int nf = 0; nf < 8; nf++)
#pragma unroll
            for (int r = 0; r < 4; r++) accO[mf][nf][r] = 0.0f;
    float m_[2][2] = {{-1e30f, -1e30f}, {-1e30f, -1e30f}};
    float l_[2][2] = {{0.0f, 0.0f}, {0.0f, 0.0f}};

    for (int kt = 0; kt <= ktmax; kt++) {
        // ring slot (kt+2)&3 was consumed at kt-2 (all warps passed kt-1's
        // barrier since) -> safe to overwrite without a leading barrier.
        if (kt + 2 <= ktmax) {
            const int bsel = (kt + 2) & 3;
            const __half* Kn = Ktiles + (size_t)(kt + 2) * 4096;
            const __half* Vn = Vtiles + (size_t)(kt + 2) * 4096;
#pragma unroll
            for (int u = 0; u < 4; u++) {
                int f = u * 128 + tid;
                cp16(uKb + (uint32_t)(bsel * 8192 + f * 16), Kn + f * 8);
                cp16(uVb + (uint32_t)(bsel * 8192 + f * 16), Vn + f * 8);
            }
            CP_COMMIT();
            CP_WAIT(2);
        } else if (kt + 1 <= ktmax) {
            CP_WAIT(1);
        } else {
            CP_WAIT(0);
        }
        __syncthreads();   // tile kt visible block-wide

        const uint2* Kc = (const uint2*)((const char*)sm + (kt & 3) * 8192);
        const uint2* Vc = (const uint2*)((const char*)sm + 4 * 8192 + (kt & 3) * 8192);

        const bool skip = (kt * 64) > (qwarp + 31);

        if (!skip) {
            float sacc[2][8][4];
#pragma unroll
            for (int mf = 0; mf < 2; mf++)
#pragma unroll
                for (int nf = 0; nf < 8; nf++)
#pragma unroll
                    for (int r = 0; r < 4; r++) sacc[mf][nf][r] = 0.0f;

            // GEMM1: S2 = (Q*log2e/8) @ K^T  (scores in exp2 domain)
#pragma unroll
            for (int jk = 0; jk < 4; jk++) {
#pragma unroll
                for (int nf = 0; nf < 8; nf++) {
                    uint2 b = Kc[(nf * 4 + jk) * 32 + lane];
                    mma16(sacc[0][nf], aQ[0][jk].x, aQ[0][jk].y, aQ[0][jk].z,
                          aQ[0][jk].w, b.x, b.y);
                    mma16(sacc[1][nf], aQ[1][jk].x, aQ[1][jk].y, aQ[1][jk].z,
                          aQ[1][jk].w, b.x, b.y);
                }
            }

            // causal mask (absolute indices)
            if (kt * 64 + 63 > qwarp) {
                int koff = kt * 64;
#pragma unroll
                for (int mf = 0; mf < 2; mf++) {
                    int r0 = qwarp + (mf << 4) + g, r1 = r0 + 8;
#pragma unroll
                    for (int nf = 0; nf < 8; nf++) {
                        int c0 = koff + nf * 8 + tg * 2, c1 = c0 + 1;
                        if (c0 > r0) sacc[mf][nf][0] = -1e30f;
                        if (c1 > r0) sacc[mf][nf][1] = -1e30f;
                        if (c0 > r1) sacc[mf][nf][2] = -1e30f;
                        if (c1 > r1) sacc[mf][nf][3] = -1e30f;
                    }
                }
            }

            // online softmax in exp2 domain per (mf, row-half)
#pragma unroll
            for (int mf = 0; mf < 2; mf++) {
                float rm0 = -1e30f, rm1 = -1e30f;
#pragma unroll
                for (int nf = 0; nf < 8; nf++) {
                    rm0 = fmaxf(rm0, fmaxf(sacc[mf][nf][0], sacc[mf][nf][1]));
                    rm1 = fmaxf(rm1, fmaxf(sacc[mf][nf][2], sacc[mf][nf][3]));
                }
                rm0 = fmaxf(rm0, __shfl_xor_sync(0xFFFFFFFFu, rm0, 1));
                rm0 = fmaxf(rm0, __shfl_xor_sync(0xFFFFFFFFu, rm0, 2));
                rm1 = fmaxf(rm1, __shfl_xor_sync(0xFFFFFFFFu, rm1, 1));
                rm1 = fmaxf(rm1, __shfl_xor_sync(0xFFFFFFFFu, rm1, 2));
                float mn0 = fmaxf(m_[mf][0], rm0), mn1 = fmaxf(m_[mf][1], rm1);
                float al0 = ex2(m_[mf][0] - mn0), al1 = ex2(m_[mf][1] - mn1);
                float rs0 = 0.0f, rs1 = 0.0f;
#pragma unroll
                for (int nf = 0; nf < 8; nf++) {
                    sacc[mf][nf][0] = ex2(sacc[mf][nf][0] - mn0);
                    sacc[mf][nf][1] = ex2(sacc[mf][nf][1] - mn0);
                    sacc[mf][nf][2] = ex2(sacc[mf][nf][2] - mn1);
                    sacc[mf][nf][3] = ex2(sacc[mf][nf][3] - mn1);
                    rs0 += sacc[mf][nf][0] + sacc[mf][nf][1];
                    rs1 += sacc[mf][nf][2] + sacc[mf][nf][3];
                }
                rs0 += __shfl_xor_sync(0xFFFFFFFFu, rs0, 1);
                rs0 += __shfl_xor_sync(0xFFFFFFFFu, rs0, 2);
                rs1 += __shfl_xor_sync(0xFFFFFFFFu, rs1, 1);
                rs1 += __shfl_xor_sync(0xFFFFFFFFu, rs1, 2);
                l_[mf][0] = l_[mf][0] * al0 + rs0;
                l_[mf][1] = l_[mf][1] * al1 + rs1;
                m_[mf][0] = mn0; m_[mf][1] = mn1;
#pragma unroll
                for (int nf = 0; nf < 8; nf++) {
                    accO[mf][nf][0] *= al0; accO[mf][nf][1] *= al0;
                    accO[mf][nf][2] *= al1; accO[mf][nf][3] *= al1;
                }
            }

            // GEMM2: O += P @ V. P a-frags are register-local repacks of sacc.
#pragma unroll
            for (int jk = 0; jk < 4; jk++) {
                uint32_t pa[2][4];
#pragma unroll
                for (int mf = 0; mf < 2; mf++) {
                    pa[mf][0] = f2h2(sacc[mf][2*jk  ][0], sacc[mf][2*jk  ][1]);
                    pa[mf][1] = f2h2(sacc[mf][2*jk  ][2], sacc[mf][2*jk  ][3]);
                    pa[mf][2] = f2h2(sacc[mf][2*jk+1][0], sacc[mf][2*jk+1][1]);
                    pa[mf][3] = f2h2(sacc[mf][2*jk+1][2], sacc[mf][2*jk+1][3]);
                }
#pragma unroll
                for (int nf = 0; nf < 8; nf++) {
                    uint2 b = Vc[(nf * 4 + jk) * 32 + lane];
                    mma16(accO[0][nf], pa[0][0], pa[0][1], pa[0][2], pa[0][3],
                          b.x, b.y);
                    mma16(accO[1][nf], pa[1][0], pa[1][1], pa[1][2], pa[1][3],
                          b.x, b.y);
                }
            }
        }
    }

    // epilogue: normalize, register-local repack to A-frag quads, direct STG
    {
        const int b = bh >> 4;
        const int h = bh & 15;
        uint4* ctx4 = (uint4*)g_ctx;
#pragma unroll
        for (int mf = 0; mf < 2; mf++) {
            float inv0 = 1.0f / l_[mf][0], inv1 = 1.0f / l_[mf][1];
            size_t jm = (size_t)b * 128 + bxr * 8 + w * 2 + mf;
#pragma unroll
            for (int jk = 0; jk < 4; jk++) {
                uint4 o;
                o.x = f2h2(accO[mf][2*jk  ][0] * inv0, accO[mf][2*jk  ][1] * inv0);
                o.y = f2h2(accO[mf][2*jk  ][2] * inv1, accO[mf][2*jk  ][3] * inv1);
                o.z = f2h2(accO[mf][2*jk+1][0] * inv0, accO[mf][2*jk+1][1] * inv0);
                o.w = f2h2(accO[mf][2*jk+1][2] * inv1, accO[mf][2*jk+1][3] * inv1);
                ctx4[(jm * 64 + h * 4 + jk) * 32 + lane] = o;
            }
        }
    }
}

// ---------------------------------------------------------------------------
extern "C" void kernel_launch(void* const* d_in, const int* in_sizes, int n_in,
                              void* d_out, int out_size)
{
    const float* q   = (const float*)d_in[0];
    const float* k   = (const float*)d_in[1];
    const float* v   = (const float*)d_in[2];
    // d_in[3] = mask (causal tril) — computed analytically in-kernel
    const float* w_q = (const float*)d_in[4];
    const float* w_k = (const float*)d_in[5];
    const float* w_v = (const float*)d_in[6];
    const float* w_o = (const float*)d_in[7];

    float* out  = (float*)d_out;
    float* keyh = out + OUT_PLANE;
    float* valh = out + 2 * (size_t)OUT_PLANE;

    static bool configured = false;
    if (!configured) {
        cudaFuncSetAttribute(gemm_qkv, cudaFuncAttributeMaxDynamicSharedMemorySize,
                             GEMM_SMEM);
        cudaFuncSetAttribute(gemm_out_k, cudaFuncAttributeMaxDynamicSharedMemorySize,
                             GEMM_SMEM);
        cudaFuncSetAttribute(attn_tc, cudaFuncAttributeMaxDynamicSharedMemorySize,
                             ATT_SMEM);
        configured = true;
    }

    prep_k<<<3584, 256>>>(q, k, v, w_q, w_k, w_v, w_o);

    dim3 qkvgrid(DD / 128, MM / 128, 3);   // (8, 64, 3)
    gemm_qkv<<<qkvgrid, 256, GEMM_SMEM>>>(keyh, valh);

    dim3 agrid(SS / 128, BB * HH);         // (16, 64)
    attn_tc<<<agrid, 128, ATT_SMEM>>>();

    dim3 ogrid(DD / 128, MM / 128, 1);     // (8, 64)
    gemm_out_k<<<ogrid, 256, GEMM_SMEM>>>(out);
}

// round 14
// speedup vs baseline: 3.8601x; 1.0110x over previous
#include <cuda_runtime.h>
#include <cuda_fp16.h>
#include <cstdint>

// Problem constants
#define BB 4
#define SS 2048
#define DD 1024
#define HH 16
#define DKK 64
#define MM (BB*SS)            // 8192
#define OUT_PLANE (BB*SS*DD)  // 8388608
#define HPLANE (BB*HH*SS*DKK) // 8388608

// Q pre-scale: (1/sqrt(64)) * log2(e)  -> softmax runs in exp2 domain
#define QSCALE 0.18033688011112042f

// Scratch (allocation-free rule: __device__ globals), all fp16 fragment layouts
__device__ __half g_Qh[HPLANE];        // Q proj, A-frag quads, *QSCALE
__device__ __half g_rKh[HPLANE];       // K proj, B-frag pairs (GEMM1)
__device__ __half g_rVh[HPLANE];       // V proj, B-frag pairs (GEMM2)
__device__ __half g_ctx[BB*SS*DD];     // attention context, A-frag quads
__device__ __half g_rw[4*DD*DD];       // weights, B-frag pairs
__device__ __half g_pA[3*(size_t)MM*DD]; // q,k,v inputs, A-frag quads

// fp16 m16n8k16 fragment layouts, g=lane>>2, t=lane&3:
//  A quad (jm=m/16, jk16=k/16, lane): uint4 {a0,a1,a2,a3}:
//    a0={A[16jm+g][16jk16+2t],[+1]}, a1=row+8, a2=cols+8,+9, a3=row+8 cols+8,+9
//  B pair (jn=n/8, jk16, lane): uint2 {b0,b1} per layout comments in emitters.

// ---------------------------------------------------------------------------
// helpers
// ---------------------------------------------------------------------------
__device__ __forceinline__ uint32_t f2h2(float lo, float hi) {
    __half2 h = __floats2half2_rn(lo, hi);
    return *reinterpret_cast<uint32_t*>(&h);
}

__device__ __forceinline__ float ex2(float x) {
    float r;
    asm("ex2.approx.f32 %0, %1;" : "=f"(r) : "f"(x));
    return r;
}

// D += A(16x16) * B(16x8), fp16 inputs, fp32 accum
__device__ __forceinline__ void mma16(float* c, uint32_t a0, uint32_t a1,
                                      uint32_t a2, uint32_t a3,
                                      uint32_t b0, uint32_t b1) {
    asm volatile(
        "mma.sync.aligned.m16n8k16.row.col.f32.f16.f16.f32 "
        "{%0,%1,%2,%3}, {%4,%5,%6,%7}, {%8,%9}, {%0,%1,%2,%3};\n"
        : "+f"(c[0]), "+f"(c[1]), "+f"(c[2]), "+f"(c[3])
        : "r"(a0), "r"(a1), "r"(a2), "r"(a3), "r"(b0), "r"(b1));
}

__device__ __forceinline__ uint32_t smem_u32(const void* p) {
    uint32_t a;
    asm("{ .reg .u64 t; cvta.to.shared.u64 t, %1; cvt.u32.u64 %0, t; }"
        : "=r"(a) : "l"(p));
    return a;
}

__device__ __forceinline__ void cp16(uint32_t saddr, const void* gptr) {
    asm volatile("cp.async.cg.shared.global [%0], [%1], 16;"
                 :: "r"(saddr), "l"(gptr));
}
#define CP_COMMIT() asm volatile("cp.async.commit_group;" ::: "memory")
#define CP_WAIT(n)  asm volatile("cp.async.wait_group %0;" :: "n"(n) : "memory")

// ---------------------------------------------------------------------------
// fused prologue: weight permute (blocks 0..511) + input permute (512..3583)
// ---------------------------------------------------------------------------
__global__ __launch_bounds__(256) void prep_k(const float* __restrict__ q,
                                              const float* __restrict__ k,
                                              const float* __restrict__ v,
                                              const float* __restrict__ wq,
                                              const float* __restrict__ wk,
                                              const float* __restrict__ wv,
                                              const float* __restrict__ wo)
{
    __shared__ float S[64 * 132];
    const int b = blockIdx.x;
    const int t = threadIdx.x;

    if (b < 512) {
        const int jnT = b & 15;
        const int jkT = (b >> 4) & 7;
        const int z   = b >> 7;
        const float* src = (z == 0) ? wq : (z == 1) ? wk : (z == 2) ? wv : wo;
        uint2* dst = (uint2*)(g_rw + (size_t)z * DD * DD);
#pragma unroll
        for (int i = 0; i < 8; i++) {
            int f = i * 256 + t;
            int r = f >> 5, c4 = f & 31;
            float4 vv = *(const float4*)(src + (size_t)(jnT * 64 + r) * DD
                                             + jkT * 128 + c4 * 4);
            *(float4*)&S[r * 132 + c4 * 4] = vv;
        }
        __syncthreads();
#pragma unroll
        for (int i = 0; i < 8; i++) {
            int f = i * 256 + t;
            int ln = f & 31, qq = f >> 5;
            int jk_l = qq & 7, jn_l = qq >> 3;
            int g2 = ln >> 2, t2 = ln & 3;
            int r = jn_l * 8 + g2, c = jk_l * 16 + 2 * t2;
            uint2 o;
            o.x = f2h2(S[r * 132 + c],     S[r * 132 + c + 1]);
            o.y = f2h2(S[r * 132 + c + 8], S[r * 132 + c + 9]);
            size_t idx = ((size_t)(jnT * 8 + jn_l) * 64 + jkT * 8 + jk_l) * 32 + ln;
            dst[idx] = o;
        }
    } else {
        const int idx0 = b - 512;
        const int jm = idx0 & 511;
        const int ch = (idx0 >> 9) & 1;
        const int z  = idx0 >> 10;
        const float* src = (z == 0) ? q : (z == 1) ? k : v;
        uint4* dst = (uint4*)(g_pA + (size_t)z * MM * DD);
#pragma unroll
        for (int i = 0; i < 8; i++) {
            int f = i * 256 + t;
            int r = f >> 7, c4 = f & 127;
            float4 vv = *(const float4*)(src + (size_t)(jm * 16 + r) * DD
                                             + ch * 512 + c4 * 4);
            *(float4*)&S[r * 516 + c4 * 4] = vv;
        }
        __syncthreads();
#pragma unroll
        for (int i = 0; i < 4; i++) {
            int f = i * 256 + t;
            int ln = f & 31, jk_l = f >> 5;
            int g = ln >> 2, t2 = ln & 3;
            int c = jk_l * 16 + 2 * t2;
            uint4 o;
            o.x = f2h2(S[g * 516 + c],           S[g * 516 + c + 1]);
            o.y = f2h2(S[(g + 8) * 516 + c],     S[(g + 8) * 516 + c + 1]);
            o.z = f2h2(S[g * 516 + c + 8],       S[g * 516 + c + 9]);
            o.w = f2h2(S[(g + 8) * 516 + c + 8], S[(g + 8) * 516 + c + 9]);
            size_t di = ((size_t)jm * 64 + ch * 32 + jk_l) * 32 + ln;
            dst[di] = o;
        }
    }
}

// ---------------------------------------------------------------------------
// FP16 GEMM on fragment-major operands, BK=32 (2 k16), 4-stage cp.async ring.
// Block tile 128x128, 256 thr = 8 warps (4M x 2N), warp = 32x64.
// smem: 4 x 8KB A + 4 x 8KB B = 64KB ring; epilogue staging 67.5KB (fp32).
// MODE: 0 flat fp32; 1 Q frags (*QSCALE); 2 K (fp32 out + K-frags);
//       3 V (fp32 out + V-frags).
// ---------------------------------------------------------------------------
#define GEMM_SMEM 67584

template<int MODE>
__device__ __forceinline__ void gemm_body(const __half* __restrict__ A2h,
                                          const __half* __restrict__ W2h,
                                          float* __restrict__ out_full)
{
    extern __shared__ float dsm[];
    const uint32_t sA = smem_u32(dsm);            // 4 x 8KB A stages
    const uint32_t sB = sA + 4 * 8192;            // 4 x 8KB B stages

    const int tid  = threadIdx.x;
    const int lane = tid & 31;
    const int w    = tid >> 5;
    const int g    = lane >> 2;
    const int tg   = lane & 3;
    const int wm   = w & 3;
    const int wn   = w >> 2;

    const int m0  = blockIdx.y << 7;
    const int n0  = blockIdx.x << 7;
    const int jm0 = blockIdx.y * 8;
    const int jn0 = blockIdx.x * 16;

    const int ajm = tid >> 5, ati = tid & 31;
    const uint4* Ag = (const uint4*)A2h + (size_t)(jm0 + ajm) * 2048;
    const __half* Bg = W2h;

    // prologue: chunks 0,1,2 -> slots 0,1,2
#pragma unroll
    for (int c = 0; c < 3; c++) {
#pragma unroll
        for (int i = 0; i < 2; i++) {
            int qq = ati + i * 32;
            cp16(sA + (uint32_t)(c * 8192 + (ajm * 64 + qq) * 16), Ag + c * 64 + qq);
            int f = tid + i * 256;
            int jn_l = f >> 5, rem = f & 31;
            cp16(sB + (uint32_t)(c * 8192 + f * 16),
                 Bg + ((size_t)(jn0 + jn_l) * 2048 + c * 64 + rem * 2) * 4);
        }
        CP_COMMIT();
    }

    float acc[2][8][4];
#pragma unroll
    for (int mf = 0; mf < 2; mf++)
#pragma unroll
        for (int nf = 0; nf < 8; nf++)
#pragma unroll
            for (int r = 0; r < 4; r++) acc[mf][nf][r] = 0.0f;

    for (int t = 0; t < 32; t++) {
        // groups issued after chunk t's group: min(31, t+2) - t
        if (t < 30)      { CP_WAIT(2); }
        else if (t == 30){ CP_WAIT(1); }
        else             { CP_WAIT(0); }
        __syncthreads();   // chunk t visible; slot (t+3)&3 = (t-1)&3 consumed
        if (t + 3 < 32) {
            int st = (t + 3) & 3;
#pragma unroll
            for (int i = 0; i < 2; i++) {
                int qq = ati + i * 32;
                cp16(sA + (uint32_t)(st * 8192 + (ajm * 64 + qq) * 16),
                     Ag + (t + 3) * 64 + qq);
                int f = tid + i * 256;
                int jn_l = f >> 5, rem = f & 31;
                cp16(sB + (uint32_t)(st * 8192 + f * 16),
                     Bg + ((size_t)(jn0 + jn_l) * 2048 + (t + 3) * 64 + rem * 2) * 4);
            }
            CP_COMMIT();
        }
        const uint4* as4 = (const uint4*)((const char*)dsm + (t & 3) * 8192);
        const uint2* bs2 = (const uint2*)((const char*)dsm + 4 * 8192 + (t & 3) * 8192);
#pragma unroll
        for (int ks = 0; ks < 2; ks++) {
            uint4 a0 = as4[(wm * 2 + 0) * 64 + ks * 32 + lane];
            uint4 a1 = as4[(wm * 2 + 1) * 64 + ks * 32 + lane];
#pragma unroll
            for (int nf = 0; nf < 8; nf++) {
                uint2 b = bs2[(wn * 8 + nf) * 64 + ks * 32 + lane];
                mma16(acc[0][nf], a0.x, a0.y, a0.z, a0.w, b.x, b.y);
                mma16(acc[1][nf], a1.x, a1.y, a1.z, a1.w, b.x, b.y);
            }
        }
    }

    if (MODE == 0) {
#pragma unroll
        for (int mf = 0; mf < 2; mf++) {
#pragma unroll
            for (int half = 0; half < 2; half++) {
                int m = m0 + (wm << 5) + (mf << 4) + g + half * 8;
#pragma unroll
                for (int nf = 0; nf < 8; nf++) {
                    int e = n0 + (wn << 6) + (nf << 3) + (tg << 1);
                    float2 val;
                    val.x = acc[mf][nf][half * 2 + 0];
                    val.y = acc[mf][nf][half * 2 + 1];
                    *(float2*)&out_full[(size_t)m * DD + e] = val;
                }
            }
        }
        return;
    }

    // staged epilogue: C tile -> smem fp32 [128][132]
    __syncthreads();
    float* stage = dsm;
#pragma unroll
    for (int mf = 0; mf < 2; mf++) {
#pragma unroll
        for (int half = 0; half < 2; half++) {
            int r = (wm << 5) + (mf << 4) + (half << 3) + g;
#pragma unroll
            for (int nf = 0; nf < 8; nf++) {
                int c = (wn << 6) + (nf << 3) + (tg << 1);
                float2 val;
                val.x = acc[mf][nf][half * 2 + 0];
                val.y = acc[mf][nf][half * 2 + 1];
                *(float2*)&stage[r * 132 + c] = val;
            }
        }
    }
    __syncthreads();

    const int bq = m0 >> 11;
    const int h0 = n0 >> 6;

    if (MODE == 2 || MODE == 3) {
#pragma unroll
        for (int i = 0; i < 16; i++) {
            int f = i * 256 + tid;
            int row = f >> 5, c4 = f & 31;
            float4 v = *(const float4*)&stage[row * 132 + c4 * 4];
            int m = m0 + row;
            int s = m & 2047;
            int e = n0 + c4 * 4;
            int h = e >> 6, dk = e & 63;
            *(float4*)&out_full[((((size_t)bq * HH + h) << 11) + s) * DKK + dk] = v;
        }
    }

    if (MODE == 1) {
        const int jmb = (m0 & 2047) >> 4;
        uint4* dst = (uint4*)g_Qh;
#pragma unroll
        for (int i = 0; i < 8; i++) {
            int f = i * 256 + tid;
            int ln = f & 31, qq = f >> 5;
            int jk = qq & 3, jm_l = (qq >> 2) & 7, hs = (qq >> 5) & 1;
            int g2 = ln >> 2, t2 = ln & 3;
            int r = jm_l * 16 + g2, c = hs * 64 + jk * 16 + 2 * t2;
            uint4 o;
            o.x = f2h2(stage[r * 132 + c] * QSCALE,       stage[r * 132 + c + 1] * QSCALE);
            o.y = f2h2(stage[(r + 8) * 132 + c] * QSCALE, stage[(r + 8) * 132 + c + 1] * QSCALE);
            o.z = f2h2(stage[r * 132 + c + 8] * QSCALE,   stage[r * 132 + c + 9] * QSCALE);
            o.w = f2h2(stage[(r + 8) * 132 + c + 8] * QSCALE,
                       stage[(r + 8) * 132 + c + 9] * QSCALE);
            size_t idx = (((size_t)(bq * HH + h0 + hs) * 128 + jmb + jm_l) * 4 + jk) * 32 + ln;
            dst[idx] = o;
        }
    } else if (MODE == 2) {
        const int kt0 = (m0 & 2047) >> 6;
        uint2* dst = (uint2*)g_rKh;
#pragma unroll
        for (int i = 0; i < 16; i++) {
            int f = i * 256 + tid;
            int ln = f & 31, qq = f >> 5;
            int jk = qq & 3, jn = (qq >> 2) & 7, ktl = (qq >> 5) & 1, hs = qq >> 6;
            int g2 = ln >> 2, t2 = ln & 3;
            int r = ktl * 64 + jn * 8 + g2;
            int c = hs * 64 + jk * 16 + 2 * t2;
            uint2 o;
            o.x = f2h2(stage[r * 132 + c],     stage[r * 132 + c + 1]);
            o.y = f2h2(stage[r * 132 + c + 8], stage[r * 132 + c + 9]);
            size_t idx = ((size_t)(bq * HH + h0 + hs) * 32 + kt0 + ktl) * 1024
                       + (jn * 4 + jk) * 32 + ln;
            dst[idx] = o;
        }
    } else if (MODE == 3) {
        const int kt0 = (m0 & 2047) >> 6;
        uint2* dst = (uint2*)g_rVh;
#pragma unroll
        for (int i = 0; i < 16; i++) {
            int f = i * 256 + tid;
            int ln = f & 31, qq = f >> 5;
            int jk = qq & 3, jn = (qq >> 2) & 7, ktl = (qq >> 5) & 1, hs = qq >> 6;
            int g2 = ln >> 2, t2 = ln & 3;
            int r = ktl * 64 + jk * 16 + 2 * t2;
            int c = hs * 64 + jn * 8 + g2;
            uint2 o;
            o.x = f2h2(stage[r * 132 + c],       stage[(r + 1) * 132 + c]);
            o.y = f2h2(stage[(r + 8) * 132 + c], stage[(r + 9) * 132 + c]);
            size_t idx = ((size_t)(bq * HH + h0 + hs) * 32 + kt0 + ktl) * 1024
                       + (jn * 4 + jk) * 32 + ln;
            dst[idx] = o;
        }
    }
}

__global__ __launch_bounds__(256, 2) void gemm_qkv(
    float* __restrict__ keyh, float* __restrict__ valh)
{
    const int z = blockIdx.z;
    const __half* A2 = g_pA + (size_t)z * MM * DD;
    const __half* W2 = g_rw + (size_t)z * DD * DD;
    if (z == 0)      gemm_body<1>(A2, W2, nullptr);
    else if (z == 1) gemm_body<2>(A2, W2, keyh);
    else             gemm_body<3>(A2, W2, valh);
}

__global__ __launch_bounds__(256, 2) void gemm_out_k(float* __restrict__ O)
{
    gemm_body<0>(g_ctx, g_rw + (size_t)3 * DD * DD, O);
}

// ---------------------------------------------------------------------------
// FP16 causal flash attention, exp2-domain softmax, 4-stage K/V ring
// (one __syncthreads per tile). Grid: (S/128, B*H). Block: 128 thr (4 warps).
// ---------------------------------------------------------------------------
#define ATT_SMEM (8 * 8192)

__global__ __launch_bounds__(128, 2) void attn_tc()
{
    extern __shared__ float sm[];
    const uint32_t uKb = smem_u32(sm);          // 4 x 8KB K
    const uint32_t uVb = uKb + 4 * 8192;        // 4 x 8KB V

    const int tid  = threadIdx.x;
    const int lane = tid & 31;
    const int w    = tid >> 5;
    const int g    = lane >> 2;
    const int tg   = lane & 3;
    const int wrow = w << 5;
    const int bxr  = gridDim.x - 1 - blockIdx.x;   // heavy blocks first
    const int bh   = blockIdx.y;

    const int qwarp = bxr * 128 + wrow;

    const __half* Ktiles = g_rKh + (size_t)bh * 32 * 4096;
    const __half* Vtiles = g_rVh + (size_t)bh * 32 * 4096;
    const int ktmax = 2 * bxr + 1;

    // prologue: prefetch tiles 0 and 1 into ring slots 0 and 1
#pragma unroll
    for (int c = 0; c < 2; c++) {
#pragma unroll
        for (int u = 0; u < 4; u++) {
            int f = u * 128 + tid;
            cp16(uKb + (uint32_t)(c * 8192 + f * 16), Ktiles + (size_t)c * 4096 + f * 8);
            cp16(uVb + (uint32_t)(c * 8192 + f * 16), Vtiles + (size_t)c * 4096 + f * 8);
        }
        CP_COMMIT();
    }

    // Q a-fragments straight from global (pre-scaled by QSCALE, fp16)
    uint4 aQ[2][4];
#pragma unroll
    for (int mf = 0; mf < 2; mf++) {
        const uint4* Qf = (const uint4*)g_Qh
                        + ((size_t)bh * 128 + bxr * 8 + w * 2 + mf) * 128;
#pragma unroll
        for (int jk = 0; jk < 4; jk++)
            aQ[mf][jk] = Qf[jk * 32 + lane];
    }

    float accO[2][8][4];
#pragma unroll
    for (int mf = 0; mf < 2; mf++)
#pragma unroll
        for (int nf = 0; nf < 8; nf++)
#pragma unroll
            for (int r = 0; r < 4; r++) accO[mf][nf][r] = 0.0f;
    float m_[2][2] = {{-1e30f, -1e30f}, {-1e30f, -1e30f}};
    float l_[2][2] = {{0.0f, 0.0f}, {0.0f, 0.0f}};

    for (int kt = 0; kt <= ktmax; kt++) {
        if (kt + 2 <= ktmax) {
            const int bsel = (kt + 2) & 3;
            const __half* Kn = Ktiles + (size_t)(kt + 2) * 4096;
            const __half* Vn = Vtiles + (size_t)(kt + 2) * 4096;
#pragma unroll
            for (int u = 0; u < 4; u++) {
                int f = u * 128 + tid;
                cp16(uKb + (uint32_t)(bsel * 8192 + f * 16), Kn + f * 8);
                cp16(uVb + (uint32_t)(bsel * 8192 + f * 16), Vn + f * 8);
            }
            CP_COMMIT();
            CP_WAIT(2);
        } else if (kt + 1 <= ktmax) {
            CP_WAIT(1);
        } else {
            CP_WAIT(0);
        }
        __syncthreads();

        const uint2* Kc = (const uint2*)((const char*)sm + (kt & 3) * 8192);
        const uint2* Vc = (const uint2*)((const char*)sm + 4 * 8192 + (kt & 3) * 8192);

        const bool skip = (kt * 64) > (qwarp + 31);

        if (!skip) {
            float sacc[2][8][4];
#pragma unroll
            for (int mf = 0; mf < 2; mf++)
#pragma unroll
                for (int nf = 0; nf < 8; nf++)
#pragma unroll
                    for (int r = 0; r < 4; r++) sacc[mf][nf][r] = 0.0f;

#pragma unroll
            for (int jk = 0; jk < 4; jk++) {
#pragma unroll
                for (int nf = 0; nf < 8; nf++) {
                    uint2 b = Kc[(nf * 4 + jk) * 32 + lane];
                    mma16(sacc[0][nf], aQ[0][jk].x, aQ[0][jk].y, aQ[0][jk].z,
                          aQ[0][jk].w, b.x, b.y);
                    mma16(sacc[1][nf], aQ[1][jk].x, aQ[1][jk].y, aQ[1][jk].z,
                          aQ[1][jk].w, b.x, b.y);
                }
            }

            if (kt * 64 + 63 > qwarp) {
                int koff = kt * 64;
#pragma unroll
                for (int mf = 0; mf < 2; mf++) {
                    int r0 = qwarp + (mf << 4) + g, r1 = r0 + 8;
#pragma unroll
                    for (int nf = 0; nf < 8; nf++) {
                        int c0 = koff + nf * 8 + tg * 2, c1 = c0 + 1;
                        if (c0 > r0) sacc[mf][nf][0] = -1e30f;
                        if (c1 > r0) sacc[mf][nf][1] = -1e30f;
                        if (c0 > r1) sacc[mf][nf][2] = -1e30f;
                        if (c1 > r1) sacc[mf][nf][3] = -1e30f;
                    }
                }
            }

#pragma unroll
            for (int mf = 0; mf < 2; mf++) {
                float rm0 = -1e30f, rm1 = -1e30f;
#pragma unroll
                for (int nf = 0; nf < 8; nf++) {
                    rm0 = fmaxf(rm0, fmaxf(sacc[mf][nf][0], sacc[mf][nf][1]));
                    rm1 = fmaxf(rm1, fmaxf(sacc[mf][nf][2], sacc[mf][nf][3]));
                }
                rm0 = fmaxf(rm0, __shfl_xor_sync(0xFFFFFFFFu, rm0, 1));
                rm0 = fmaxf(rm0, __shfl_xor_sync(0xFFFFFFFFu, rm0, 2));
                rm1 = fmaxf(rm1, __shfl_xor_sync(0xFFFFFFFFu, rm1, 1));
                rm1 = fmaxf(rm1, __shfl_xor_sync(0xFFFFFFFFu, rm1, 2));
                float mn0 = fmaxf(m_[mf][0], rm0), mn1 = fmaxf(m_[mf][1], rm1);
                float al0 = ex2(m_[mf][0] - mn0), al1 = ex2(m_[mf][1] - mn1);
                float rs0 = 0.0f, rs1 = 0.0f;
#pragma unroll
                for (int nf = 0; nf < 8; nf++) {
                    sacc[mf][nf][0] = ex2(sacc[mf][nf][0] - mn0);
                    sacc[mf][nf][1] = ex2(sacc[mf][nf][1] - mn0);
                    sacc[mf][nf][2] = ex2(sacc[mf][nf][2] - mn1);
                    sacc[mf][nf][3] = ex2(sacc[mf][nf][3] - mn1);
                    rs0 += sacc[mf][nf][0] + sacc[mf][nf][1];
                    rs1 += sacc[mf][nf][2] + sacc[mf][nf][3];
                }
                rs0 += __shfl_xor_sync(0xFFFFFFFFu, rs0, 1);
                rs0 += __shfl_xor_sync(0xFFFFFFFFu, rs0, 2);
                rs1 += __shfl_xor_sync(0xFFFFFFFFu, rs1, 1);
                rs1 += __shfl_xor_sync(0xFFFFFFFFu, rs1, 2);
                l_[mf][0] = l_[mf][0] * al0 + rs0;
                l_[mf][1] = l_[mf][1] * al1 + rs1;
                m_[mf][0] = mn0; m_[mf][1] = mn1;
#pragma unroll
                for (int nf = 0; nf < 8; nf++) {
                    accO[mf][nf][0] *= al0; accO[mf][nf][1] *= al0;
                    accO[mf][nf][2] *= al1; accO[mf][nf][3] *= al1;
                }
            }

#pragma unroll
            for (int jk = 0; jk < 4; jk++) {
                uint32_t pa[2][4];
#pragma unroll
                for (int mf = 0; mf < 2; mf++) {
                    pa[mf][0] = f2h2(sacc[mf][2*jk  ][0], sacc[mf][2*jk  ][1]);
                    pa[mf][1] = f2h2(sacc[mf][2*jk  ][2], sacc[mf][2*jk  ][3]);
                    pa[mf][2] = f2h2(sacc[mf][2*jk+1][0], sacc[mf][2*jk+1][1]);
                    pa[mf][3] = f2h2(sacc[mf][2*jk+1][2], sacc[mf][2*jk+1][3]);
                }
#pragma unroll
                for (int nf = 0; nf < 8; nf++) {
                    uint2 b = Vc[(nf * 4 + jk) * 32 + lane];
                    mma16(accO[0][nf], pa[0][0], pa[0][1], pa[0][2], pa[0][3],
                          b.x, b.y);
                    mma16(accO[1][nf], pa[1][0], pa[1][1], pa[1][2], pa[1][3],
                          b.x, b.y);
                }
            }
        }
    }

    // epilogue: normalize, register-local repack to A-frag quads, direct STG
    {
        const int b = bh >> 4;
        const int h = bh & 15;
        uint4* ctx4 = (uint4*)g_ctx;
#pragma unroll
        for (int mf = 0; mf < 2; mf++) {
            float inv0 = 1.0f / l_[mf][0], inv1 = 1.0f / l_[mf][1];
            size_t jm = (size_t)b * 128 + bxr * 8 + w * 2 + mf;
#pragma unroll
            for (int jk = 0; jk < 4; jk++) {
                uint4 o;
                o.x = f2h2(accO[mf][2*jk  ][0] * inv0, accO[mf][2*jk  ][1] * inv0);
                o.y = f2h2(accO[mf][2*jk  ][2] * inv1, accO[mf][2*jk  ][3] * inv1);
                o.z = f2h2(accO[mf][2*jk+1][0] * inv0, accO[mf][2*jk+1][1] * inv0);
                o.w = f2h2(accO[mf][2*jk+1][2] * inv1, accO[mf][2*jk+1][3] * inv1);
                ctx4[(jm * 64 + h * 4 + jk) * 32 + lane] = o;
            }
        }
    }
}

// ---------------------------------------------------------------------------
extern "C" void kernel_launch(void* const* d_in, const int* in_sizes, int n_in,
                              void* d_out, int out_size)
{
    const float* q   = (const float*)d_in[0];
    const float* k   = (const float*)d_in[1];
    const float* v   = (const float*)d_in[2];
    // d_in[3] = mask (causal tril) — computed analytically in-kernel
    const float* w_q = (const float*)d_in[4];
    const float* w_k = (const float*)d_in[5];
    const float* w_v = (const float*)d_in[6];
    const float* w_o = (const float*)d_in[7];

    float* out  = (float*)d_out;
    float* keyh = out + OUT_PLANE;
    float* valh = out + 2 * (size_t)OUT_PLANE;

    static bool configured = false;
    if (!configured) {
        cudaFuncSetAttribute(gemm_qkv, cudaFuncAttributeMaxDynamicSharedMemorySize,
                             GEMM_SMEM);
        cudaFuncSetAttribute(gemm_out_k, cudaFuncAttributeMaxDynamicSharedMemorySize,
                             GEMM_SMEM);
        cudaFuncSetAttribute(attn_tc, cudaFuncAttributeMaxDynamicSharedMemorySize,
                             ATT_SMEM);
        configured = true;
    }

    prep_k<<<3584, 256>>>(q, k, v, w_q, w_k, w_v, w_o);

    dim3 qkvgrid(DD / 128, MM / 128, 3);   // (8, 64, 3)
    gemm_qkv<<<qkvgrid, 256, GEMM_SMEM>>>(keyh, valh);

    dim3 agrid(SS / 128, BB * HH);         // (16, 64)
    attn_tc<<<agrid, 128, ATT_SMEM>>>();

    dim3 ogrid(DD / 128, MM / 128, 1);     // (8, 64)
    gemm_out_k<<<ogrid, 256, GEMM_SMEM>>>(out);
}

// round 15
// speedup vs baseline: 4.0142x; 1.0399x over previous
#include <cuda_runtime.h>
#include <cuda_fp16.h>
#include <cstdint>

// Problem constants
#define BB 4
#define SS 2048
#define DD 1024
#define HH 16
#define DKK 64
#define MM (BB*SS)            // 8192
#define OUT_PLANE (BB*SS*DD)  // 8388608
#define HPLANE (BB*HH*SS*DKK) // 8388608

// Q pre-scale: (1/sqrt(64)) * log2(e)  -> softmax runs in exp2 domain
#define QSCALE 0.18033688011112042f

// Scratch (allocation-free rule: __device__ globals), all fp16 fragment layouts
__device__ __half g_Qh[HPLANE];        // Q proj, A-frag quads, *QSCALE
__device__ __half g_rKh[HPLANE];       // K proj, B-frag pairs (GEMM1)
__device__ __half g_rVh[HPLANE];       // V proj, B-frag pairs (GEMM2)
__device__ __half g_ctx[BB*SS*DD];     // attention context, A-frag quads
__device__ __half g_rw[4*DD*DD];       // weights, B-frag pairs
__device__ __half g_pA[3*(size_t)MM*DD]; // q,k,v inputs, A-frag quads

// fp16 m16n8k16 fragment layouts, g=lane>>2, t=lane&3:
//  A quad (jm=m/16, jk16=k/16, lane): uint4 idx = (jm*NJK16 + jk16)*32 + lane
//  B pair (jn=n/8, jk16, lane): uint2 idx = (jn*NJK16 + jk16)*32 + lane

// ---------------------------------------------------------------------------
// helpers
// ---------------------------------------------------------------------------
__device__ __forceinline__ uint32_t f2h2(float lo, float hi) {
    __half2 h = __floats2half2_rn(lo, hi);
    return *reinterpret_cast<uint32_t*>(&h);
}

__device__ __forceinline__ float ex2(float x) {
    float r;
    asm("ex2.approx.f32 %0, %1;" : "=f"(r) : "f"(x));
    return r;
}

// D += A(16x16) * B(16x8), fp16 inputs, fp32 accum
__device__ __forceinline__ void mma16(float* c, uint32_t a0, uint32_t a1,
                                      uint32_t a2, uint32_t a3,
                                      uint32_t b0, uint32_t b1) {
    asm volatile(
        "mma.sync.aligned.m16n8k16.row.col.f32.f16.f16.f32 "
        "{%0,%1,%2,%3}, {%4,%5,%6,%7}, {%8,%9}, {%0,%1,%2,%3};\n"
        : "+f"(c[0]), "+f"(c[1]), "+f"(c[2]), "+f"(c[3])
        : "r"(a0), "r"(a1), "r"(a2), "r"(a3), "r"(b0), "r"(b1));
}

__device__ __forceinline__ uint32_t smem_u32(const void* p) {
    uint32_t a;
    asm("{ .reg .u64 t; cvta.to.shared.u64 t, %1; cvt.u32.u64 %0, t; }"
        : "=r"(a) : "l"(p));
    return a;
}

__device__ __forceinline__ void cp16(uint32_t saddr, const void* gptr) {
    asm volatile("cp.async.cg.shared.global [%0], [%1], 16;"
                 :: "r"(saddr), "l"(gptr));
}
#define CP_COMMIT() asm volatile("cp.async.commit_group;" ::: "memory")
#define CP_WAIT(n)  asm volatile("cp.async.wait_group %0;" :: "n"(n) : "memory")

// ---------------------------------------------------------------------------
// fused prologue: weight permute (blocks 0..511) + input permute (512..3583)
// ---------------------------------------------------------------------------
__global__ __launch_bounds__(256) void prep_k(const float* __restrict__ q,
                                              const float* __restrict__ k,
                                              const float* __restrict__ v,
                                              const float* __restrict__ wq,
                                              const float* __restrict__ wk,
                                              const float* __restrict__ wv,
                                              const float* __restrict__ wo)
{
    __shared__ float S[64 * 132];
    const int b = blockIdx.x;
    const int t = threadIdx.x;

    if (b < 512) {
        const int jnT = b & 15;
        const int jkT = (b >> 4) & 7;
        const int z   = b >> 7;
        const float* src = (z == 0) ? wq : (z == 1) ? wk : (z == 2) ? wv : wo;
        uint2* dst = (uint2*)(g_rw + (size_t)z * DD * DD);
#pragma unroll
        for (int i = 0; i < 8; i++) {
            int f = i * 256 + t;
            int r = f >> 5, c4 = f & 31;
            float4 vv = *(const float4*)(src + (size_t)(jnT * 64 + r) * DD
                                             + jkT * 128 + c4 * 4);
            *(float4*)&S[r * 132 + c4 * 4] = vv;
        }
        __syncthreads();
#pragma unroll
        for (int i = 0; i < 8; i++) {
            int f = i * 256 + t;
            int ln = f & 31, qq = f >> 5;
            int jk_l = qq & 7, jn_l = qq >> 3;
            int g2 = ln >> 2, t2 = ln & 3;
            int r = jn_l * 8 + g2, c = jk_l * 16 + 2 * t2;
            uint2 o;
            o.x = f2h2(S[r * 132 + c],     S[r * 132 + c + 1]);
            o.y = f2h2(S[r * 132 + c + 8], S[r * 132 + c + 9]);
            size_t idx = ((size_t)(jnT * 8 + jn_l) * 64 + jkT * 8 + jk_l) * 32 + ln;
            dst[idx] = o;
        }
    } else {
        const int idx0 = b - 512;
        const int jm = idx0 & 511;
        const int ch = (idx0 >> 9) & 1;
        const int z  = idx0 >> 10;
        const float* src = (z == 0) ? q : (z == 1) ? k : v;
        uint4* dst = (uint4*)(g_pA + (size_t)z * MM * DD);
#pragma unroll
        for (int i = 0; i < 8; i++) {
            int f = i * 256 + t;
            int r = f >> 7, c4 = f & 127;
            float4 vv = *(const float4*)(src + (size_t)(jm * 16 + r) * DD
                                             + ch * 512 + c4 * 4);
            *(float4*)&S[r * 516 + c4 * 4] = vv;
        }
        __syncthreads();
#pragma unroll
        for (int i = 0; i < 4; i++) {
            int f = i * 256 + t;
            int ln = f & 31, jk_l = f >> 5;
            int g = ln >> 2, t2 = ln & 3;
            int c = jk_l * 16 + 2 * t2;
            uint4 o;
            o.x = f2h2(S[g * 516 + c],           S[g * 516 + c + 1]);
            o.y = f2h2(S[(g + 8) * 516 + c],     S[(g + 8) * 516 + c + 1]);
            o.z = f2h2(S[g * 516 + c + 8],       S[g * 516 + c + 9]);
            o.w = f2h2(S[(g + 8) * 516 + c + 8], S[(g + 8) * 516 + c + 9]);
            size_t di = ((size_t)jm * 64 + ch * 32 + jk_l) * 32 + ln;
            dst[di] = o;
        }
    }
}

// ---------------------------------------------------------------------------
// FP16 GEMM, BK=64 (4 k16), 3-stage cp.async ring (32KB stages).
// Block tile 128x128, 256 thr = 8 warps (4M x 2N), warp = 32x64. 16 chunks.
// smem: 3 x 16KB A + 3 x 16KB B = 96KB; epilogue staging 67.5KB (reuses).
// MODE: 0 flat fp32; 1 Q frags (*QSCALE); 2 K (fp32 out + K-frags);
//       3 V (fp32 out + V-frags).
// ---------------------------------------------------------------------------
#define GEMM_SMEM 98304

template<int MODE>
__device__ __forceinline__ void gemm_body(const __half* __restrict__ A2h,
                                          const __half* __restrict__ W2h,
                                          float* __restrict__ out_full)
{
    extern __shared__ float dsm[];
    const uint32_t sA = smem_u32(dsm);            // 3 x 16KB A stages
    const uint32_t sB = sA + 3 * 16384;           // 3 x 16KB B stages

    const int tid  = threadIdx.x;
    const int lane = tid & 31;
    const int w    = tid >> 5;
    const int g    = lane >> 2;
    const int tg   = lane & 3;
    const int wm   = w & 3;
    const int wn   = w >> 2;

    const int m0  = blockIdx.y << 7;
    const int n0  = blockIdx.x << 7;
    const int jm0 = blockIdx.y * 8;
    const int jn0 = blockIdx.x * 16;

    const int ajm = tid >> 5, ati = tid & 31;
    const uint4* Ag = (const uint4*)A2h + (size_t)(jm0 + ajm) * 2048;
    const uint2* Bg2 = (const uint2*)W2h;

    // loader B mapping: f in [0,1024): jn_l=f>>6, jkl=(f&63)>>4, lp=f&15
    // prologue: chunks 0,1,2 -> stages 0,1,2
#pragma unroll
    for (int c = 0; c < 3; c++) {
#pragma unroll
        for (int i = 0; i < 4; i++) {
            cp16(sA + (uint32_t)(c * 16384 + ((ajm * 4 + i) * 32 + ati) * 16),
                 Ag + (c * 4 + i) * 32 + ati);
            int f = tid + i * 256;
            int jn_l = f >> 6, rem = f & 63;
            int jkl = rem >> 4, lp = rem & 15;
            cp16(sB + (uint32_t)(c * 16384 + ((jn_l * 4 + jkl) * 32 + lp * 2) * 8),
                 Bg2 + (size_t)(jn0 + jn_l) * 2048 + (c * 4 + jkl) * 32 + lp * 2);
        }
        CP_COMMIT();
    }

    float acc[2][8][4];
#pragma unroll
    for (int mf = 0; mf < 2; mf++)
#pragma unroll
        for (int nf = 0; nf < 8; nf++)
#pragma unroll
            for (int r = 0; r < 4; r++) acc[mf][nf][r] = 0.0f;

    for (int t = 0; t < 16; t++) {
        if (t < 15) { CP_WAIT(1); } else { CP_WAIT(0); }
        __syncthreads();   // chunk t visible; stage (t+2)%3 = (t-1)%3 consumed
        if (t + 2 < 16) {
            int st = (t + 2) % 3;
#pragma unroll
            for (int i = 0; i < 4; i++) {
                cp16(sA + (uint32_t)(st * 16384 + ((ajm * 4 + i) * 32 + ati) * 16),
                     Ag + ((t + 2) * 4 + i) * 32 + ati);
                int f = tid + i * 256;
                int jn_l = f >> 6, rem = f & 63;
                int jkl = rem >> 4, lp = rem & 15;
                cp16(sB + (uint32_t)(st * 16384 + ((jn_l * 4 + jkl) * 32 + lp * 2) * 8),
                     Bg2 + (size_t)(jn0 + jn_l) * 2048 + ((t + 2) * 4 + jkl) * 32 + lp * 2);
            }
            CP_COMMIT();
        }
        const int st = t % 3;
        const uint4* as4 = (const uint4*)((const char*)dsm + st * 16384);
        const uint2* bs2 = (const uint2*)((const char*)dsm + 3 * 16384 + st * 16384);
#pragma unroll
        for (int ks = 0; ks < 4; ks++) {
            uint4 a0 = as4[((wm * 2 + 0) * 4 + ks) * 32 + lane];
            uint4 a1 = as4[((wm * 2 + 1) * 4 + ks) * 32 + lane];
#pragma unroll
            for (int nf = 0; nf < 8; nf++) {
                uint2 b = bs2[((wn * 8 + nf) * 4 + ks) * 32 + lane];
                mma16(acc[0][nf], a0.x, a0.y, a0.z, a0.w, b.x, b.y);
                mma16(acc[1][nf], a1.x, a1.y, a1.z, a1.w, b.x, b.y);
            }
        }
    }

    if (MODE == 0) {
#pragma unroll
        for (int mf = 0; mf < 2; mf++) {
#pragma unroll
            for (int half = 0; half < 2; half++) {
                int m = m0 + (wm << 5) + (mf << 4) + g + half * 8;
#pragma unroll
                for (int nf = 0; nf < 8; nf++) {
                    int e = n0 + (wn << 6) + (nf << 3) + (tg << 1);
                    float2 val;
                    val.x = acc[mf][nf][half * 2 + 0];
                    val.y = acc[mf][nf][half * 2 + 1];
                    *(float2*)&out_full[(size_t)m * DD + e] = val;
                }
            }
        }
        return;
    }

    // staged epilogue: C tile -> smem fp32 [128][132]
    __syncthreads();
    float* stage = dsm;
#pragma unroll
    for (int mf = 0; mf < 2; mf++) {
#pragma unroll
        for (int half = 0; half < 2; half++) {
            int r = (wm << 5) + (mf << 4) + (half << 3) + g;
#pragma unroll
            for (int nf = 0; nf < 8; nf++) {
                int c = (wn << 6) + (nf << 3) + (tg << 1);
                float2 val;
                val.x = acc[mf][nf][half * 2 + 0];
                val.y = acc[mf][nf][half * 2 + 1];
                *(float2*)&stage[r * 132 + c] = val;
            }
        }
    }
    __syncthreads();

    const int bq = m0 >> 11;
    const int h0 = n0 >> 6;

    if (MODE == 2 || MODE == 3) {
#pragma unroll
        for (int i = 0; i < 16; i++) {
            int f = i * 256 + tid;
            int row = f >> 5, c4 = f & 31;
            float4 v = *(const float4*)&stage[row * 132 + c4 * 4];
            int m = m0 + row;
            int s = m & 2047;
            int e = n0 + c4 * 4;
            int h = e >> 6, dk = e & 63;
            *(float4*)&out_full[((((size_t)bq * HH + h) << 11) + s) * DKK + dk] = v;
        }
    }

    if (MODE == 1) {
        const int jmb = (m0 & 2047) >> 4;
        uint4* dst = (uint4*)g_Qh;
#pragma unroll
        for (int i = 0; i < 8; i++) {
            int f = i * 256 + tid;
            int ln = f & 31, qq = f >> 5;
            int jk = qq & 3, jm_l = (qq >> 2) & 7, hs = (qq >> 5) & 1;
            int g2 = ln >> 2, t2 = ln & 3;
            int r = jm_l * 16 + g2, c = hs * 64 + jk * 16 + 2 * t2;
            uint4 o;
            o.x = f2h2(stage[r * 132 + c] * QSCALE,       stage[r * 132 + c + 1] * QSCALE);
            o.y = f2h2(stage[(r + 8) * 132 + c] * QSCALE, stage[(r + 8) * 132 + c + 1] * QSCALE);
            o.z = f2h2(stage[r * 132 + c + 8] * QSCALE,   stage[r * 132 + c + 9] * QSCALE);
            o.w = f2h2(stage[(r + 8) * 132 + c + 8] * QSCALE,
                       stage[(r + 8) * 132 + c + 9] * QSCALE);
            size_t idx = (((size_t)(bq * HH + h0 + hs) * 128 + jmb + jm_l) * 4 + jk) * 32 + ln;
            dst[idx] = o;
        }
    } else if (MODE == 2) {
        const int kt0 = (m0 & 2047) >> 6;
        uint2* dst = (uint2*)g_rKh;
#pragma unroll
        for (int i = 0; i < 16; i++) {
            int f = i * 256 + tid;
            int ln = f & 31, qq = f >> 5;
            int jk = qq & 3, jn = (qq >> 2) & 7, ktl = (qq >> 5) & 1, hs = qq >> 6;
            int g2 = ln >> 2, t2 = ln & 3;
            int r = ktl * 64 + jn * 8 + g2;
            int c = hs * 64 + jk * 16 + 2 * t2;
            uint2 o;
            o.x = f2h2(stage[r * 132 + c],     stage[r * 132 + c + 1]);
            o.y = f2h2(stage[r * 132 + c + 8], stage[r * 132 + c + 9]);
            size_t idx = ((size_t)(bq * HH + h0 + hs) * 32 + kt0 + ktl) * 1024
                       + (jn * 4 + jk) * 32 + ln;
            dst[idx] = o;
        }
    } else if (MODE == 3) {
        const int kt0 = (m0 & 2047) >> 6;
        uint2* dst = (uint2*)g_rVh;
#pragma unroll
        for (int i = 0; i < 16; i++) {
            int f = i * 256 + tid;
            int ln = f & 31, qq = f >> 5;
            int jk = qq & 3, jn = (qq >> 2) & 7, ktl = (qq >> 5) & 1, hs = qq >> 6;
            int g2 = ln >> 2, t2 = ln & 3;
            int r = ktl * 64 + jk * 16 + 2 * t2;
            int c = hs * 64 + jn * 8 + g2;
            uint2 o;
            o.x = f2h2(stage[r * 132 + c],       stage[(r + 1) * 132 + c]);
            o.y = f2h2(stage[(r + 8) * 132 + c], stage[(r + 9) * 132 + c]);
            size_t idx = ((size_t)(bq * HH + h0 + hs) * 32 + kt0 + ktl) * 1024
                       + (jn * 4 + jk) * 32 + ln;
            dst[idx] = o;
        }
    }
}

__global__ __launch_bounds__(256, 2) void gemm_qkv(
    float* __restrict__ keyh, float* __restrict__ valh)
{
    const int z = blockIdx.z;
    const __half* A2 = g_pA + (size_t)z * MM * DD;
    const __half* W2 = g_rw + (size_t)z * DD * DD;
    if (z == 0)      gemm_body<1>(A2, W2, nullptr);
    else if (z == 1) gemm_body<2>(A2, W2, keyh);
    else             gemm_body<3>(A2, W2, valh);
}

__global__ __launch_bounds__(256, 2) void gemm_out_k(float* __restrict__ O)
{
    gemm_body<0>(g_ctx, g_rw + (size_t)3 * DD * DD, O);
}

// ---------------------------------------------------------------------------
// FP16 causal flash attention, exp2-domain softmax, 4-slot K/V ring,
// TWO 64-key tiles per loop iteration (one barrier per pair).
// Grid: (S/128, B*H). Block: 128 thr (4 warps); warp owns 32 query rows.
// ---------------------------------------------------------------------------
#define ATT_SMEM (8 * 8192)

__global__ __launch_bounds__(128, 2) void attn_tc()
{
    extern __shared__ float sm[];
    const uint32_t uKb = smem_u32(sm);          // 4 x 8KB K
    const uint32_t uVb = uKb + 4 * 8192;        // 4 x 8KB V

    const int tid  = threadIdx.x;
    const int lane = tid & 31;
    const int w    = tid >> 5;
    const int g    = lane >> 2;
    const int tg   = lane & 3;
    const int wrow = w << 5;
    const int bxr  = gridDim.x - 1 - blockIdx.x;   // heavy blocks first
    const int bh   = blockIdx.y;

    const int qwarp = bxr * 128 + wrow;

    const __half* Ktiles = g_rKh + (size_t)bh * 32 * 4096;
    const __half* Vtiles = g_rVh + (size_t)bh * 32 * 4096;
    const int ktmax = 2 * bxr + 1;   // odd -> tiles form exact pairs

    // prologue: prefetch tiles 0 and 1 into ring slots 0 and 1
#pragma unroll
    for (int c = 0; c < 2; c++) {
#pragma unroll
        for (int u = 0; u < 4; u++) {
            int f = u * 128 + tid;
            cp16(uKb + (uint32_t)(c * 8192 + f * 16), Ktiles + (size_t)c * 4096 + f * 8);
            cp16(uVb + (uint32_t)(c * 8192 + f * 16), Vtiles + (size_t)c * 4096 + f * 8);
        }
        CP_COMMIT();
    }

    // Q a-fragments straight from global (pre-scaled by QSCALE, fp16)
    uint4 aQ[2][4];
#pragma unroll
    for (int mf = 0; mf < 2; mf++) {
        const uint4* Qf = (const uint4*)g_Qh
                        + ((size_t)bh * 128 + bxr * 8 + w * 2 + mf) * 128;
#pragma unroll
        for (int jk = 0; jk < 4; jk++)
            aQ[mf][jk] = Qf[jk * 32 + lane];
    }

    float accO[2][8][4];
#pragma unroll
    for (int mf = 0; mf < 2; mf++)
#pragma unroll
        for (int nf = 0; nf < 8; nf++)
#pragma unroll
            for (int r = 0; r < 4; r++) accO[mf][nf][r] = 0.0f;
    float m_[2][2] = {{-1e30f, -1e30f}, {-1e30f, -1e30f}};
    float l_[2][2] = {{0.0f, 0.0f}, {0.0f, 0.0f}};

    for (int ktt = 0; ktt <= ktmax; ktt += 2) {
        CP_WAIT(0);        // tiles ktt, ktt+1 resident
        __syncthreads();   // ... and every warp done with slots of ktt-2,ktt-1

        // prefetch next pair into slots (ktt+2)&3, (ktt+3)&3 (consumed pre-barrier)
#pragma unroll
        for (int d = 2; d < 4; d++) {
            int tt = ktt + d;
            if (tt <= ktmax) {
                const int bsel = tt & 3;
                const __half* Kn = Ktiles + (size_t)tt * 4096;
                const __half* Vn = Vtiles + (size_t)tt * 4096;
#pragma unroll
                for (int u = 0; u < 4; u++) {
                    int f = u * 128 + tid;
                    cp16(uKb + (uint32_t)(bsel * 8192 + f * 16), Kn + f * 8);
                    cp16(uVb + (uint32_t)(bsel * 8192 + f * 16), Vn + f * 8);
                }
                CP_COMMIT();
            }
        }

#pragma unroll
        for (int sub = 0; sub < 2; sub++) {
            const int kt = ktt + sub;
            const uint2* Kc = (const uint2*)((const char*)sm + (kt & 3) * 8192);
            const uint2* Vc = (const uint2*)((const char*)sm + 4 * 8192 + (kt & 3) * 8192);

            const bool skip = (kt * 64) > (qwarp + 31);
            if (skip) continue;

            float sacc[2][8][4];
#pragma unroll
            for (int mf = 0; mf < 2; mf++)
#pragma unroll
                for (int nf = 0; nf < 8; nf++)
#pragma unroll
                    for (int r = 0; r < 4; r++) sacc[mf][nf][r] = 0.0f;

            // GEMM1: S2 = (Q*log2e/8) @ K^T
#pragma unroll
            for (int jk = 0; jk < 4; jk++) {
#pragma unroll
                for (int nf = 0; nf < 8; nf++) {
                    uint2 b = Kc[(nf * 4 + jk) * 32 + lane];
                    mma16(sacc[0][nf], aQ[0][jk].x, aQ[0][jk].y, aQ[0][jk].z,
                          aQ[0][jk].w, b.x, b.y);
                    mma16(sacc[1][nf], aQ[1][jk].x, aQ[1][jk].y, aQ[1][jk].z,
                          aQ[1][jk].w, b.x, b.y);
                }
            }

            // causal mask (absolute indices)
            if (kt * 64 + 63 > qwarp) {
                int koff = kt * 64;
#pragma unroll
                for (int mf = 0; mf < 2; mf++) {
                    int r0 = qwarp + (mf << 4) + g, r1 = r0 + 8;
#pragma unroll
                    for (int nf = 0; nf < 8; nf++) {
                        int c0 = koff + nf * 8 + tg * 2, c1 = c0 + 1;
                        if (c0 > r0) sacc[mf][nf][0] = -1e30f;
                        if (c1 > r0) sacc[mf][nf][1] = -1e30f;
                        if (c0 > r1) sacc[mf][nf][2] = -1e30f;
                        if (c1 > r1) sacc[mf][nf][3] = -1e30f;
                    }
                }
            }

            // online softmax in exp2 domain per (mf, row-half)
#pragma unroll
            for (int mf = 0; mf < 2; mf++) {
                float rm0 = -1e30f, rm1 = -1e30f;
#pragma unroll
                for (int nf = 0; nf < 8; nf++) {
                    rm0 = fmaxf(rm0, fmaxf(sacc[mf][nf][0], sacc[mf][nf][1]));
                    rm1 = fmaxf(rm1, fmaxf(sacc[mf][nf][2], sacc[mf][nf][3]));
                }
                rm0 = fmaxf(rm0, __shfl_xor_sync(0xFFFFFFFFu, rm0, 1));
                rm0 = fmaxf(rm0, __shfl_xor_sync(0xFFFFFFFFu, rm0, 2));
                rm1 = fmaxf(rm1, __shfl_xor_sync(0xFFFFFFFFu, rm1, 1));
                rm1 = fmaxf(rm1, __shfl_xor_sync(0xFFFFFFFFu, rm1, 2));
                float mn0 = fmaxf(m_[mf][0], rm0), mn1 = fmaxf(m_[mf][1], rm1);
                float al0 = ex2(m_[mf][0] - mn0), al1 = ex2(m_[mf][1] - mn1);
                float rs0 = 0.0f, rs1 = 0.0f;
#pragma unroll
                for (int nf = 0; nf < 8; nf++) {
                    sacc[mf][nf][0] = ex2(sacc[mf][nf][0] - mn0);
                    sacc[mf][nf][1] = ex2(sacc[mf][nf][1] - mn0);
                    sacc[mf][nf][2] = ex2(sacc[mf][nf][2] - mn1);
                    sacc[mf][nf][3] = ex2(sacc[mf][nf][3] - mn1);
                    rs0 += sacc[mf][nf][0] + sacc[mf][nf][1];
                    rs1 += sacc[mf][nf][2] + sacc[mf][nf][3];
                }
                rs0 += __shfl_xor_sync(0xFFFFFFFFu, rs0, 1);
                rs0 += __shfl_xor_sync(0xFFFFFFFFu, rs0, 2);
                rs1 += __shfl_xor_sync(0xFFFFFFFFu, rs1, 1);
                rs1 += __shfl_xor_sync(0xFFFFFFFFu, rs1, 2);
                l_[mf][0] = l_[mf][0] * al0 + rs0;
                l_[mf][1] = l_[mf][1] * al1 + rs1;
                m_[mf][0] = mn0; m_[mf][1] = mn1;
#pragma unroll
                for (int nf = 0; nf < 8; nf++) {
                    accO[mf][nf][0] *= al0; accO[mf][nf][1] *= al0;
                    accO[mf][nf][2] *= al1; accO[mf][nf][3] *= al1;
                }
            }

            // GEMM2: O += P @ V (register-local P repack)
#pragma unroll
            for (int jk = 0; jk < 4; jk++) {
                uint32_t pa[2][4];
#pragma unroll
                for (int mf = 0; mf < 2; mf++) {
                    pa[mf][0] = f2h2(sacc[mf][2*jk  ][0], sacc[mf][2*jk  ][1]);
                    pa[mf][1] = f2h2(sacc[mf][2*jk  ][2], sacc[mf][2*jk  ][3]);
                    pa[mf][2] = f2h2(sacc[mf][2*jk+1][0], sacc[mf][2*jk+1][1]);
                    pa[mf][3] = f2h2(sacc[mf][2*jk+1][2], sacc[mf][2*jk+1][3]);
                }
#pragma unroll
                for (int nf = 0; nf < 8; nf++) {
                    uint2 b = Vc[(nf * 4 + jk) * 32 + lane];
                    mma16(accO[0][nf], pa[0][0], pa[0][1], pa[0][2], pa[0][3],
                          b.x, b.y);
                    mma16(accO[1][nf], pa[1][0], pa[1][1], pa[1][2], pa[1][3],
                          b.x, b.y);
                }
            }
        }
    }

    // epilogue: normalize, register-local repack to A-frag quads, direct STG
    {
        const int b = bh >> 4;
        const int h = bh & 15;
        uint4* ctx4 = (uint4*)g_ctx;
#pragma unroll
        for (int mf = 0; mf < 2; mf++) {
            float inv0 = 1.0f / l_[mf][0], inv1 = 1.0f / l_[mf][1];
            size_t jm = (size_t)b * 128 + bxr * 8 + w * 2 + mf;
#pragma unroll
            for (int jk = 0; jk < 4; jk++) {
                uint4 o;
                o.x = f2h2(accO[mf][2*jk  ][0] * inv0, accO[mf][2*jk  ][1] * inv0);
                o.y = f2h2(accO[mf][2*jk  ][2] * inv1, accO[mf][2*jk  ][3] * inv1);
                o.z = f2h2(accO[mf][2*jk+1][0] * inv0, accO[mf][2*jk+1][1] * inv0);
                o.w = f2h2(accO[mf][2*jk+1][2] * inv1, accO[mf][2*jk+1][3] * inv1);
                ctx4[(jm * 64 + h * 4 + jk) * 32 + lane] = o;
            }
        }
    }
}

// ---------------------------------------------------------------------------
extern "C" void kernel_launch(void* const* d_in, const int* in_sizes, int n_in,
                              void* d_out, int out_size)
{
    const float* q   = (const float*)d_in[0];
    const float* k   = (const float*)d_in[1];
    const float* v   = (const float*)d_in[2];
    // d_in[3] = mask (causal tril) — computed analytically in-kernel
    const float* w_q = (const float*)d_in[4];
    const float* w_k = (const float*)d_in[5];
    const float* w_v = (const float*)d_in[6];
    const float* w_o = (const float*)d_in[7];

    float* out  = (float*)d_out;
    float* keyh = out + OUT_PLANE;
    float* valh = out + 2 * (size_t)OUT_PLANE;

    static bool configured = false;
    if (!configured) {
        cudaFuncSetAttribute(gemm_qkv, cudaFuncAttributeMaxDynamicSharedMemorySize,
                             GEMM_SMEM);
        cudaFuncSetAttribute(gemm_out_k, cudaFuncAttributeMaxDynamicSharedMemorySize,
                             GEMM_SMEM);
        cudaFuncSetAttribute(attn_tc, cudaFuncAttributeMaxDynamicSharedMemorySize,
                             ATT_SMEM);
        configured = true;
    }

    prep_k<<<3584, 256>>>(q, k, v, w_q, w_k, w_v, w_o);

    dim3 qkvgrid(DD / 128, MM / 128, 3);   // (8, 64, 3)
    gemm_qkv<<<qkvgrid, 256, GEMM_SMEM>>>(keyh, valh);

    dim3 agrid(SS / 128, BB * HH);         // (16, 64)
    attn_tc<<<agrid, 128, ATT_SMEM>>>();

    dim3 ogrid(DD / 128, MM / 128, 1);     // (8, 64)
    gemm_out_k<<<ogrid, 256, GEMM_SMEM>>>(out);
}